// round 1
// baseline (speedup 1.0000x reference)
#include <cuda_runtime.h>
#include <math.h>

// Problem dims (fixed by the dataset)
#define BB  8
#define CIN 64
#define CO  128
#define HH  224
#define WW  224
#define HO  112
#define WO  112
#define LL  (HO*WO)     // 12544
#define HWD (HH*WW)     // 50176

// ---------------- static device scratch (no allocations allowed) ----------------
__device__ float sc_s[(size_t)BB*CIN*HWD];        // shuffled dw output      (98 MB)
__device__ float sc_y[(size_t)BB*CO*HWD];         // after csc 1x1           (196 MB)
__device__ float sc_a[(size_t)BB*CO*HWD];         // gelu(bn(y))             (196 MB)
__device__ float sc_g[(size_t)BB*CO*LL];          // guide tokens            (49 MB)
__device__ float sc_T[(size_t)BB*5*CO*LL];        // tokens [b][p][c][l]     (245 MB)
__device__ float sc_Km[(size_t)BB*5*CO*LL];       // k      [b][p][c][l]     (245 MB)
__device__ float sc_q0[(size_t)BB*CO*LL];         // q at p=0                (49 MB)
__device__ float sc_attn[BB*CO*5];
__device__ float sc_feff[BB*CO*640];
__device__ float sc_beff[CO];
__device__ float sc_bnscale[CO];
__device__ float sc_bnshift[CO];

// ---------------- per-head depthwise conv + channel shuffle ----------------
template<int KSZ>
__global__ void __launch_bounds__(256) dw_kernel(const float* __restrict__ x,
                                                 const float* __restrict__ w,
                                                 const float* __restrict__ bias,
                                                 int head) {
    int p = blockIdx.x * 256 + threadIdx.x;
    if (p >= HWD) return;
    int j = blockIdx.y;          // channel within head (0..15)
    int b = blockIdx.z;
    int h = p / WW, wc = p % WW;
    const int pad = KSZ / 2;
    const float* xin = x + ((size_t)(b*CIN + head*16 + j)) * HWD;
    float acc = bias[j];
    #pragma unroll
    for (int ky = 0; ky < KSZ; ky++) {
        int ih = h + ky - pad;
        if (ih < 0 || ih >= HH) continue;
        #pragma unroll
        for (int kx = 0; kx < KSZ; kx++) {
            int iw = wc + kx - pad;
            if (iw < 0 || iw >= WW) continue;
            acc += xin[ih*WW + iw] * w[(j*KSZ + ky)*KSZ + kx];
        }
    }
    // channel shuffle: out channel = j*NH + head
    sc_s[((size_t)(b*CIN + j*4 + head)) * HWD + p] = acc;
}

// ---------------- generic M=128 SGEMM: C = A(128xK) @ B(KxN) + bias ----------------
// K multiple of 16, N multiple of 128. Batched over blockIdx.z via strides.
__global__ void __launch_bounds__(256) sgemm_kernel(const float* __restrict__ A, size_t sA,
                                                    const float* __restrict__ Bm, size_t sB,
                                                    const float* __restrict__ bias,
                                                    float* __restrict__ C, size_t sC,
                                                    int K, int N) {
    __shared__ float As[16][128];
    __shared__ float Bs[16][128];
    int z = blockIdx.z;
    A  += (size_t)z * sA;
    Bm += (size_t)z * sB;
    C  += (size_t)z * sC;
    int n0  = blockIdx.x * 128;
    int tid = threadIdx.x;
    int tm = (tid >> 4) << 3;
    int tn = (tid & 15) << 3;
    float acc[8][8];
    #pragma unroll
    for (int i = 0; i < 8; i++)
        #pragma unroll
        for (int j = 0; j < 8; j++) acc[i][j] = 0.f;

    for (int k0 = 0; k0 < K; k0 += 16) {
        #pragma unroll
        for (int i = 0; i < 2; i++) {
            int id = tid + i*256;
            int r = id >> 2, c4 = (id & 3) << 2;
            float4 v = *reinterpret_cast<const float4*>(A + (size_t)r*K + k0 + c4);
            As[c4+0][r] = v.x; As[c4+1][r] = v.y; As[c4+2][r] = v.z; As[c4+3][r] = v.w;
        }
        #pragma unroll
        for (int i = 0; i < 2; i++) {
            int id = tid + i*256;
            int r = id >> 5, c4 = (id & 31) << 2;
            *reinterpret_cast<float4*>(&Bs[r][c4]) =
                *reinterpret_cast<const float4*>(Bm + (size_t)(k0 + r)*N + n0 + c4);
        }
        __syncthreads();
        #pragma unroll
        for (int kk = 0; kk < 16; kk++) {
            float a[8], bf[8];
            #pragma unroll
            for (int i = 0; i < 8; i++) a[i]  = As[kk][tm + i];
            #pragma unroll
            for (int i = 0; i < 8; i++) bf[i] = Bs[kk][tn + i];
            #pragma unroll
            for (int i = 0; i < 8; i++)
                #pragma unroll
                for (int j = 0; j < 8; j++) acc[i][j] += a[i] * bf[j];
        }
        __syncthreads();
    }
    #pragma unroll
    for (int i = 0; i < 8; i++) {
        float bv = bias[tm + i];
        #pragma unroll
        for (int j = 0; j < 8; j += 4) {
            float4 v;
            v.x = acc[i][j+0] + bv; v.y = acc[i][j+1] + bv;
            v.z = acc[i][j+2] + bv; v.w = acc[i][j+3] + bv;
            *reinterpret_cast<float4*>(C + (size_t)(tm + i)*N + n0 + tn + j) = v;
        }
    }
}

// ---------------- small precompute kernels ----------------
__global__ void precompute_kernel(const float* __restrict__ gamma, const float* __restrict__ beta,
                                  const float* __restrict__ mean,  const float* __restrict__ var,
                                  const float* __restrict__ proj_w, const float* __restrict__ qkv_b,
                                  const float* __restrict__ proj_b) {
    int c = threadIdx.x;   // 128 threads
    float sc = gamma[c] * rsqrtf(var[c] + 1e-5f);
    sc_bnscale[c] = sc;
    sc_bnshift[c] = beta[c] - mean[c] * sc;
    float acc = proj_b[c];
    for (int k = 0; k < CO; k++) acc += proj_w[c*CO + k] * qkv_b[256 + k];
    sc_beff[c] = acc;
}

// ---------------- a = gelu(bn(y)) ----------------
__global__ void __launch_bounds__(256) act_kernel() {
    int p = blockIdx.x * 256 + threadIdx.x;
    int c = blockIdx.y, b = blockIdx.z;
    size_t idx = ((size_t)(b*CO + c)) * HWD + p;
    float v = sc_y[idx] * sc_bnscale[c] + sc_bnshift[c];
    sc_a[idx] = 0.5f * v * (1.0f + erff(v * 0.7071067811865476f));
}

// ---------------- g = dwconv7 stride2 over a ----------------
__global__ void __launch_bounds__(256) ggm_kernel(const float* __restrict__ w,
                                                  const float* __restrict__ bias) {
    int l = blockIdx.x * 256 + threadIdx.x;
    int c = blockIdx.y, b = blockIdx.z;
    int ho = l / WO, wo = l % WO;
    const float* ain = sc_a + ((size_t)(b*CO + c)) * HWD;
    const float* wr  = w + c*49;
    float acc = bias[c];
    #pragma unroll
    for (int i = 0; i < 7; i++) {
        int ih = 2*ho + i - 3;
        if (ih < 0 || ih >= HH) continue;
        #pragma unroll
        for (int j = 0; j < 7; j++) {
            int iw = 2*wo + j - 3;
            if (iw < 0 || iw >= WW) continue;
            acc += ain[ih*WW + iw] * wr[i*7 + j];
        }
    }
    sc_g[((size_t)(b*CO + c)) * LL + l] = acc;
}

// ---------------- build token tensor T[b][p][c][l] ----------------
__global__ void __launch_bounds__(256) buildT_kernel() {
    int l = blockIdx.x * 256 + threadIdx.x;
    int c = blockIdx.y;
    int z = blockIdx.z;           // b*5 + p
    int b = z / 5, p = z % 5;
    float v;
    if (p == 0) {
        v = sc_g[((size_t)(b*CO + c)) * LL + l];
    } else {
        int dy = (p - 1) >> 1, dx = (p - 1) & 1;
        int ho = l / WO, wo = l % WO;
        v = sc_y[((size_t)(b*CO + c)) * HWD + (size_t)(2*ho + dy)*WW + 2*wo + dx];
    }
    sc_T[((size_t)z * CO + c) * LL + l] = v;
}

// ---------------- 5-way gram + softmax row 0 ----------------
__global__ void __launch_bounds__(256) gram_kernel() {
    int c = blockIdx.x, b = blockIdx.y;
    int tid = threadIdx.x;
    float S[5] = {0,0,0,0,0};
    const float* q = sc_q0 + ((size_t)(b*CO + c)) * LL;
    for (int l = tid; l < LL; l += 256) {
        float qv = q[l];
        #pragma unroll
        for (int t = 0; t < 5; t++)
            S[t] += qv * sc_Km[((size_t)(b*5 + t) * CO + c) * LL + l];
    }
    __shared__ float red[256];
    __shared__ float Sf[5];
    for (int t = 0; t < 5; t++) {
        red[tid] = S[t]; __syncthreads();
        for (int off = 128; off > 0; off >>= 1) {
            if (tid < off) red[tid] += red[tid + off];
            __syncthreads();
        }
        if (tid == 0) Sf[t] = red[0];
        __syncthreads();
    }
    if (tid == 0) {
        const float scale = 0.08838834764831845f;   // 1/sqrt(128)
        float m = -1e30f;
        #pragma unroll
        for (int t = 0; t < 5; t++) { Sf[t] *= scale; m = fmaxf(m, Sf[t]); }
        float e[5], sum = 0.f;
        #pragma unroll
        for (int t = 0; t < 5; t++) { e[t] = expf(Sf[t] - m); sum += e[t]; }
        float inv = 1.0f / sum;
        #pragma unroll
        for (int t = 0; t < 5; t++) sc_attn[(b*CO + c)*5 + t] = e[t] * inv;
    }
}

// ---------------- Feff[b][o][p*128+c'] = sum_c P[o,c]*attn0[b,c,p]*Wv[c,c'] ----------------
__global__ void __launch_bounds__(256) feff_kernel(const float* __restrict__ proj_w,
                                                   const float* __restrict__ qkv_w) {
    int idx = blockIdx.x * 256 + threadIdx.x;   // 8*128*640 = 655360 total
    int j  = idx % 640;
    int o  = (idx / 640) % CO;
    int b  = idx / (640 * CO);
    int p  = j >> 7, cp = j & 127;
    float acc = 0.f;
    for (int c = 0; c < CO; c++)
        acc += proj_w[o*CO + c] * sc_attn[(b*CO + c)*5 + p] * qkv_w[(256 + c)*CO + cp];
    sc_feff[idx] = acc;
}

// ---------------- launch ----------------
extern "C" void kernel_launch(void* const* d_in, const int* in_sizes, int n_in,
                              void* d_out, int out_size) {
    const float* x      = (const float*)d_in[0];
    const float* dww[4] = {(const float*)d_in[1], (const float*)d_in[3],
                           (const float*)d_in[5], (const float*)d_in[7]};
    const float* dwb[4] = {(const float*)d_in[2], (const float*)d_in[4],
                           (const float*)d_in[6], (const float*)d_in[8]};
    const float* csc_w  = (const float*)d_in[9];
    const float* csc_b  = (const float*)d_in[10];
    const float* bn_g   = (const float*)d_in[11];
    const float* bn_b   = (const float*)d_in[12];
    const float* bn_m   = (const float*)d_in[13];
    const float* bn_v   = (const float*)d_in[14];
    const float* ggm_w  = (const float*)d_in[15];
    const float* ggm_b  = (const float*)d_in[16];
    const float* qkv_w  = (const float*)d_in[17];
    const float* qkv_b  = (const float*)d_in[18];
    const float* proj_w = (const float*)d_in[19];
    const float* proj_b = (const float*)d_in[20];
    float* out = (float*)d_out;

    float *p_s, *p_y, *p_T, *p_Km, *p_q0, *p_feff, *p_beff;
    cudaGetSymbolAddress((void**)&p_s,    sc_s);
    cudaGetSymbolAddress((void**)&p_y,    sc_y);
    cudaGetSymbolAddress((void**)&p_T,    sc_T);
    cudaGetSymbolAddress((void**)&p_Km,   sc_Km);
    cudaGetSymbolAddress((void**)&p_q0,   sc_q0);
    cudaGetSymbolAddress((void**)&p_feff, sc_feff);
    cudaGetSymbolAddress((void**)&p_beff, sc_beff);

    // 0. small precompute (bn affine fold + effective output bias)
    precompute_kernel<<<1, 128>>>(bn_g, bn_b, bn_m, bn_v, proj_w, qkv_b, proj_b);

    // 1. depthwise convs + channel shuffle -> sc_s
    dim3 gdw((HWD + 255)/256, 16, BB);
    dw_kernel<3><<<gdw, 256>>>(x, dww[0], dwb[0], 0);
    dw_kernel<5><<<gdw, 256>>>(x, dww[1], dwb[1], 1);
    dw_kernel<7><<<gdw, 256>>>(x, dww[2], dwb[2], 2);
    dw_kernel<9><<<gdw, 256>>>(x, dww[3], dwb[3], 3);

    // 2. csc 1x1: y = csc_w @ s   (per batch)
    sgemm_kernel<<<dim3(HWD/128, 1, BB), 256>>>(csc_w, 0,
                                                p_s, (size_t)CIN*HWD, csc_b,
                                                p_y, (size_t)CO*HWD, CIN, HWD);

    // 3. a = gelu(bn(y))
    act_kernel<<<dim3(HWD/256, CO, BB), 256>>>();

    // 4. g = dwconv7 stride2 (a)
    ggm_kernel<<<dim3(LL/256, CO, BB), 256>>>(ggm_w, ggm_b);

    // 5. tokens T[b][p][c][l]
    buildT_kernel<<<dim3(LL/256, CO, BB*5), 256>>>();

    // 6. q0 = Wq @ T[:,0]  (per batch)
    sgemm_kernel<<<dim3(LL/128, 1, BB), 256>>>(qkv_w, 0,
                                               p_T, (size_t)5*CO*LL, qkv_b,
                                               p_q0, (size_t)CO*LL, CO, LL);

    // 7. k = Wk @ T[:,p]   (per batch*token)
    sgemm_kernel<<<dim3(LL/128, 1, BB*5), 256>>>(qkv_w + 128*128, 0,
                                                 p_T, (size_t)CO*LL, qkv_b + 128,
                                                 p_Km, (size_t)CO*LL, CO, LL);

    // 8. gram + softmax (row p=0 only)
    gram_kernel<<<dim3(CO, BB), 256>>>();

    // 9. effective folded weight (attn0 * Wv, then proj)
    feff_kernel<<<(BB*CO*640)/256, 256>>>(proj_w, qkv_w);

    // 10. final: out = Feff_b @ T_b + beff   (per batch) -> writes d_out directly
    sgemm_kernel<<<dim3(LL/128, 1, BB), 256>>>(p_feff, (size_t)CO*640,
                                               p_T, (size_t)5*CO*LL, p_beff,
                                               out, (size_t)CO*LL, 640, LL);
}

// round 3
// speedup vs baseline: 1.4150x; 1.4150x over previous
#include <cuda_runtime.h>
#include <cuda_bf16.h>
#include <stdint.h>
#include <math.h>

// Problem dims (fixed)
#define BB  8
#define CIN 64
#define CO  128
#define HH  224
#define WW  224
#define HO  112
#define WO  112
#define LL  (HO*WO)     // 12544
#define HWD (HH*WW)     // 50176
#define NT_S (HWD/128)  // 392
#define NT_L (LL/128)   // 98

// ---------------- static device scratch ----------------
__device__ __align__(16) float sc_s[(size_t)BB*CIN*HWD];     // dw output [b][c][hw]
__device__ __align__(16) float sc_y[(size_t)BB*CO*HWD];      // csc output [b][c][hw]
__device__ __align__(16) float sc_g[(size_t)BB*CO*LL];       // guide tokens [b][c][l]
__device__ __align__(16) float sc_q0[(size_t)BB*CO*LL];
__device__ __align__(16) float sc_Km[(size_t)BB*5*CO*LL];
__device__ float sc_attn[BB*CO*5];
__device__ float sc_beff[CO];
__device__ float sc_bnscale[CO];
__device__ float sc_bnshift[CO];
// bf16 hi/lo planes
__device__ __align__(16) __nv_bfloat16 sc_sBh[(size_t)BB*HWD*64];   // [b][hw][64]
__device__ __align__(16) __nv_bfloat16 sc_sBl[(size_t)BB*HWD*64];
__device__ __align__(16) __nv_bfloat16 sc_TBh[(size_t)BB*LL*640];   // [b][l][p*128+c]
__device__ __align__(16) __nv_bfloat16 sc_TBl[(size_t)BB*LL*640];
__device__ __align__(16) __nv_bfloat16 sc_cAh[128*64];
__device__ __align__(16) __nv_bfloat16 sc_cAl[128*64];
__device__ __align__(16) __nv_bfloat16 sc_qAh[128*128];
__device__ __align__(16) __nv_bfloat16 sc_qAl[128*128];
__device__ __align__(16) __nv_bfloat16 sc_kAh[128*128];
__device__ __align__(16) __nv_bfloat16 sc_kAl[128*128];
__device__ __align__(16) __nv_bfloat16 sc_fAh[(size_t)BB*128*640];
__device__ __align__(16) __nv_bfloat16 sc_fAl[(size_t)BB*128*640];

// ---------------- helpers ----------------
__device__ __forceinline__ uint32_t smem_u32(const void* p) {
    uint32_t a;
    asm("{ .reg .u64 t; cvta.to.shared.u64 t, %1; cvt.u32.u64 %0, t; }" : "=r"(a) : "l"(p));
    return a;
}
__device__ __forceinline__ void split_bf(float v, __nv_bfloat16& h, __nv_bfloat16& l) {
    h = __float2bfloat16(v);
    l = __float2bfloat16(v - __bfloat162float(h));
}

#define LDSM4(r, a)                                                           \
    asm volatile("ldmatrix.sync.aligned.m8n8.x4.shared.b16 {%0,%1,%2,%3}, [%4];" \
        : "=r"((r)[0]), "=r"((r)[1]), "=r"((r)[2]), "=r"((r)[3]) : "r"(a))

__device__ __forceinline__ void mma16816(float* c, const uint32_t* a, uint32_t b0, uint32_t b1) {
    asm volatile(
        "mma.sync.aligned.m16n8k16.row.col.f32.bf16.bf16.f32 "
        "{%0,%1,%2,%3}, {%4,%5,%6,%7}, {%8,%9}, {%0,%1,%2,%3};"
        : "+f"(c[0]), "+f"(c[1]), "+f"(c[2]), "+f"(c[3])
        : "r"(a[0]), "r"(a[1]), "r"(a[2]), "r"(a[3]), "r"(b0), "r"(b1));
}

// ---------------- depthwise conv + channel shuffle (4 outputs/thread) ----------------
template<int KSZ>
__global__ void __launch_bounds__(256) dw_kernel(const float* __restrict__ x,
                                                 const float* __restrict__ w,
                                                 const float* __restrict__ bias, int head) {
    const int pad = KSZ / 2;
    int q = blockIdx.x * 256 + threadIdx.x;      // quarter-row index
    int j = blockIdx.y, b = blockIdx.z;
    int h = q / (WW / 4);
    int w0 = (q % (WW / 4)) * 4;
    const float* xin = x + ((size_t)(b * CIN + head * 16 + j)) * HWD;
    float a0 = bias[j], a1 = a0, a2 = a0, a3 = a0;
    #pragma unroll
    for (int ky = 0; ky < KSZ; ky++) {
        int ih = h + ky - pad;
        if (ih < 0 || ih >= HH) continue;
        const float* row = xin + (size_t)ih * WW;
        float v[KSZ + 3];
        #pragma unroll
        for (int t = 0; t < KSZ + 3; t++) {
            int iw = w0 - pad + t;
            v[t] = (iw >= 0 && iw < WW) ? row[iw] : 0.f;
        }
        #pragma unroll
        for (int kx = 0; kx < KSZ; kx++) {
            float wv = __ldg(&w[(j * KSZ + ky) * KSZ + kx]);
            a0 += v[kx] * wv; a1 += v[kx + 1] * wv;
            a2 += v[kx + 2] * wv; a3 += v[kx + 3] * wv;
        }
    }
    float4 r; r.x = a0; r.y = a1; r.z = a2; r.w = a3;
    *reinterpret_cast<float4*>(sc_s + ((size_t)(b * CIN + j * 4 + head)) * HWD + (size_t)h * WW + w0) = r;
}

// ---------------- precompute ----------------
__global__ void precompute_kernel(const float* g, const float* be, const float* mn,
                                  const float* vr, const float* proj_w,
                                  const float* qkv_b, const float* proj_b) {
    int c = threadIdx.x;
    float sc = g[c] * rsqrtf(vr[c] + 1e-5f);
    sc_bnscale[c] = sc;
    sc_bnshift[c] = be[c] - mn[c] * sc;
    float acc = proj_b[c];
    for (int k = 0; k < CO; k++) acc += proj_w[c * CO + k] * qkv_b[256 + k];
    sc_beff[c] = acc;
}

// ---------------- pack weight matrix into hi/lo planes (row-major) ----------------
__global__ void packW_kernel(const float* __restrict__ W, int n,
                             __nv_bfloat16* __restrict__ Hd, __nv_bfloat16* __restrict__ Ld) {
    int i = blockIdx.x * 256 + threadIdx.x;
    if (i >= n) return;
    __nv_bfloat16 h, l; split_bf(W[i], h, l);
    Hd[i] = h; Ld[i] = l;
}

// ---------------- transpose dw output -> [hw][c] bf16 hi/lo ----------------
__global__ void __launch_bounds__(256) packS_kernel() {
    __shared__ __align__(16) __nv_bfloat16 smh[128][72];
    __shared__ __align__(16) __nv_bfloat16 sml[128][72];
    int t = blockIdx.x, b = blockIdx.y;
    int tid = threadIdx.x;
    int c = tid >> 2, lq = tid & 3;
    const float* src = sc_s + ((size_t)(b * CIN + c)) * HWD + (size_t)t * 128 + lq * 32;
    #pragma unroll 8
    for (int j = 0; j < 32; j++) {
        __nv_bfloat16 h, l; split_bf(src[j], h, l);
        smh[lq * 32 + j][c] = h;
        sml[lq * 32 + j][c] = l;
    }
    __syncthreads();
    int hw = tid >> 1, ch = tid & 1;
    size_t dst = ((size_t)b * HWD + (size_t)t * 128 + hw) * 64 + ch * 32;
    const int4* sh = (const int4*)&smh[hw][ch * 32];
    const int4* sl = (const int4*)&sml[hw][ch * 32];
    int4* dh = (int4*)(sc_sBh + dst);
    int4* dl = (int4*)(sc_sBl + dst);
    #pragma unroll
    for (int j = 0; j < 4; j++) { dh[j] = sh[j]; dl[j] = sl[j]; }
}

// ---------------- bf16 split-precision mma.sync GEMM: C[128 x 128-tile] ----------------
// A: [128 x K] row-major hi/lo. B: rows=spatial (ld=ldb), cols=K, hi/lo. C: [128 x N] row-major.
__global__ void __launch_bounds__(256) gemm_mma(
    const __nv_bfloat16* __restrict__ Ah, const __nv_bfloat16* __restrict__ Al, size_t sAz,
    const __nv_bfloat16* __restrict__ Bh, const __nv_bfloat16* __restrict__ Bl, size_t sBz,
    int bMod, int pOff, int ldb,
    const float* __restrict__ bias,
    float* __restrict__ C, size_t sCz, int ldc, int K)
{
    extern __shared__ __align__(16) char smem[];   // 64KB: Ah|Al|Bh|Bl 16KB each
    int tid = threadIdx.x, lane = tid & 31, w = tid >> 5;
    int nt = blockIdx.x, z = blockIdx.z;
    size_t Aoff = (size_t)z * sAz;
    size_t Boff = (size_t)(z / bMod) * sBz + (size_t)(z % bMod) * pOff + (size_t)(nt * 128) * ldb;
    const __nv_bfloat16* Ahg = Ah + Aoff;
    const __nv_bfloat16* Alg = Al + Aoff;
    const __nv_bfloat16* Bhg = Bh + Boff;
    const __nv_bfloat16* Blg = Bl + Boff;
    float* Cz = C + (size_t)z * sCz + (size_t)nt * 128;

    int mr0 = (w & 3) * 32;
    int n0  = (w >> 2) * 64;
    uint32_t sb = smem_u32(smem);

    float c[2][8][4];
    #pragma unroll
    for (int i = 0; i < 2; i++)
        #pragma unroll
        for (int j = 0; j < 8; j++)
            #pragma unroll
            for (int q = 0; q < 4; q++) c[i][j][q] = 0.f;

    int ar = lane & 15, ac = lane >> 4;                     // A ldmatrix lane mapping
    int br = (lane & 7) + ((lane >> 4) << 3), bc = (lane >> 3) & 1;  // B lane mapping

    int kchunks = K >> 6;
    for (int kc = 0; kc < kchunks; kc++) {
        int kb = kc * 64;
        for (int i = tid; i < 1024; i += 256) {
            int r = i >> 3, cc = i & 7;
            uint32_t d = (uint32_t)(r * 128 + (((cc ^ (r & 7))) << 4));
            size_t sa = (size_t)r * K + kb + cc * 8;
            size_t sbo = (size_t)r * ldb + kb + cc * 8;
            *(int4*)(smem + d)          = *(const int4*)(Ahg + sa);
            *(int4*)(smem + 16384 + d)  = *(const int4*)(Alg + sa);
            *(int4*)(smem + 32768 + d)  = *(const int4*)(Bhg + sbo);
            *(int4*)(smem + 49152 + d)  = *(const int4*)(Blg + sbo);
        }
        __syncthreads();
        #pragma unroll
        for (int kk = 0; kk < 4; kk++) {
            uint32_t aH[2][4], aL[2][4], bH[4][4], bL[4][4];
            #pragma unroll
            for (int mi = 0; mi < 2; mi++) {
                int r = mr0 + mi * 16 + ar;
                uint32_t addr = sb + r * 128 + ((((kk * 2 + ac)) ^ (r & 7)) << 4);
                LDSM4(aH[mi], addr);
                LDSM4(aL[mi], addr + 16384);
            }
            #pragma unroll
            for (int np = 0; np < 4; np++) {
                int r = n0 + np * 16 + br;
                uint32_t addr = sb + 32768 + r * 128 + ((((kk * 2 + bc)) ^ (r & 7)) << 4);
                LDSM4(bH[np], addr);
                LDSM4(bL[np], addr + 16384);
            }
            #pragma unroll
            for (int mi = 0; mi < 2; mi++)
                #pragma unroll
                for (int np = 0; np < 4; np++) {
                    mma16816(c[mi][np*2],     aH[mi], bH[np][0], bH[np][1]);
                    mma16816(c[mi][np*2],     aH[mi], bL[np][0], bL[np][1]);
                    mma16816(c[mi][np*2],     aL[mi], bH[np][0], bH[np][1]);
                    mma16816(c[mi][np*2 + 1], aH[mi], bH[np][2], bH[np][3]);
                    mma16816(c[mi][np*2 + 1], aH[mi], bL[np][2], bL[np][3]);
                    mma16816(c[mi][np*2 + 1], aL[mi], bH[np][2], bH[np][3]);
                }
        }
        __syncthreads();
    }
    int g = lane >> 2, tg = lane & 3;
    #pragma unroll
    for (int mi = 0; mi < 2; mi++) {
        int row0 = mr0 + mi * 16 + g;
        float bv0 = bias[row0], bv1 = bias[row0 + 8];
        #pragma unroll
        for (int ni = 0; ni < 8; ni++) {
            int col = n0 + ni * 8 + tg * 2;
            float2 v0 = make_float2(c[mi][ni][0] + bv0, c[mi][ni][1] + bv0);
            float2 v1 = make_float2(c[mi][ni][2] + bv1, c[mi][ni][3] + bv1);
            *(float2*)(Cz + (size_t)row0 * ldc + col) = v0;
            *(float2*)(Cz + (size_t)(row0 + 8) * ldc + col) = v1;
        }
    }
}

// ---------------- fused BN + GELU + dwconv7 stride2 ----------------
__global__ void __launch_bounds__(256) actggm_kernel(const float* __restrict__ w,
                                                     const float* __restrict__ bias) {
    __shared__ float a[38 * 38];
    __shared__ float wk[49];
    int t = blockIdx.x, c = blockIdx.y, b = blockIdx.z;
    int ty = t / 7, tx = t % 7;
    int ho0 = ty * 16, wo0 = tx * 16;
    if (threadIdx.x < 49) wk[threadIdx.x] = w[c * 49 + threadIdx.x];
    const float* y = sc_y + ((size_t)(b * CO + c)) * HWD;
    float bs = sc_bnscale[c], bh = sc_bnshift[c];
    for (int ii = threadIdx.x; ii < 38 * 38; ii += 256) {
        int r = ii / 38, col = ii % 38;
        int ih = 2 * ho0 - 3 + r, iw = 2 * wo0 - 3 + col;
        float v = 0.f;
        if (ih >= 0 && ih < HH && iw >= 0 && iw < WW) {
            v = y[(size_t)ih * WW + iw] * bs + bh;
            v = 0.5f * v * (1.f + erff(v * 0.7071067811865476f));
        }
        a[ii] = v;
    }
    __syncthreads();
    int oy = threadIdx.x / 16, ox = threadIdx.x % 16;
    float acc = bias[c];
    #pragma unroll
    for (int i = 0; i < 7; i++)
        #pragma unroll
        for (int j = 0; j < 7; j++)
            acc += a[(2 * oy + i) * 38 + (2 * ox + j)] * wk[i * 7 + j];
    sc_g[((size_t)(b * CO + c)) * LL + (size_t)(ho0 + oy) * WO + wo0 + ox] = acc;
}

// ---------------- build token planes [b][l][p*128+c] hi/lo ----------------
__global__ void __launch_bounds__(256) buildT_kernel() {
    __shared__ __align__(16) __nv_bfloat16 smh[64][136];
    __shared__ __align__(16) __nv_bfloat16 sml[64][136];
    int lt = blockIdx.x, p = blockIdx.y, b = blockIdx.z;   // lt: 64-l blocks
    int tid = threadIdx.x;
    int c = tid >> 1, lh = tid & 1;
    int dy = (p - 1) >> 1, dx = (p - 1) & 1;
    const float* gsrc = sc_g + ((size_t)(b * CO + c)) * LL;
    const float* ysrc = sc_y + ((size_t)(b * CO + c)) * HWD;
    #pragma unroll 4
    for (int j = 0; j < 32; j++) {
        int li = lh * 32 + j;
        int l = lt * 64 + li;
        float v;
        if (p == 0) v = gsrc[l];
        else {
            int ho = l / WO, wo = l % WO;
            v = ysrc[(size_t)(2 * ho + dy) * WW + 2 * wo + dx];
        }
        __nv_bfloat16 h, lo; split_bf(v, h, lo);
        smh[li][c] = h; sml[li][c] = lo;
    }
    __syncthreads();
    int li = tid >> 2, cq = tid & 3;
    size_t dst = ((size_t)b * LL + (size_t)lt * 64 + li) * 640 + p * 128 + cq * 32;
    const int4* sh = (const int4*)&smh[li][cq * 32];
    const int4* sl = (const int4*)&sml[li][cq * 32];
    int4* dh = (int4*)(sc_TBh + dst);
    int4* dl = (int4*)(sc_TBl + dst);
    #pragma unroll
    for (int j = 0; j < 4; j++) { dh[j] = sh[j]; dl[j] = sl[j]; }
}

// ---------------- 5-way gram + softmax row 0 ----------------
__global__ void __launch_bounds__(256) gram_kernel() {
    int c = blockIdx.x, b = blockIdx.y;
    int tid = threadIdx.x;
    float S[5] = {0, 0, 0, 0, 0};
    const float* q = sc_q0 + ((size_t)(b * CO + c)) * LL;
    for (int l = tid; l < LL; l += 256) {
        float qv = q[l];
        #pragma unroll
        for (int t = 0; t < 5; t++)
            S[t] += qv * sc_Km[((size_t)(b * 5 + t) * CO + c) * LL + l];
    }
    __shared__ float red[256];
    __shared__ float Sf[5];
    for (int t = 0; t < 5; t++) {
        red[tid] = S[t]; __syncthreads();
        for (int off = 128; off > 0; off >>= 1) {
            if (tid < off) red[tid] += red[tid + off];
            __syncthreads();
        }
        if (tid == 0) Sf[t] = red[0];
        __syncthreads();
    }
    if (tid == 0) {
        const float scale = 0.08838834764831845f;
        float m = -1e30f;
        #pragma unroll
        for (int t = 0; t < 5; t++) { Sf[t] *= scale; m = fmaxf(m, Sf[t]); }
        float e[5], sum = 0.f;
        #pragma unroll
        for (int t = 0; t < 5; t++) { e[t] = expf(Sf[t] - m); sum += e[t]; }
        float inv = 1.0f / sum;
        #pragma unroll
        for (int t = 0; t < 5; t++) sc_attn[(b * CO + c) * 5 + t] = e[t] * inv;
    }
}

// ---------------- effective folded weight [b][o][p*128+c'] hi/lo ----------------
__global__ void feff_kernel(const float* __restrict__ proj_w, const float* __restrict__ qkv_w) {
    int idx = blockIdx.x * 256 + threadIdx.x;   // 8*128*640
    int j = idx % 640;
    int o = (idx / 640) % CO;
    int b = idx / (640 * CO);
    int pp = j >> 7, cpx = j & 127;
    float acc = 0.f;
    for (int c = 0; c < CO; c++)
        acc += proj_w[o * CO + c] * sc_attn[(b * CO + c) * 5 + pp] * qkv_w[(256 + c) * CO + cpx];
    __nv_bfloat16 h, l; split_bf(acc, h, l);
    sc_fAh[idx] = h; sc_fAl[idx] = l;
}

// ---------------- launch ----------------
extern "C" void kernel_launch(void* const* d_in, const int* in_sizes, int n_in,
                              void* d_out, int out_size) {
    const float* x      = (const float*)d_in[0];
    const float* dww[4] = {(const float*)d_in[1], (const float*)d_in[3],
                           (const float*)d_in[5], (const float*)d_in[7]};
    const float* dwb[4] = {(const float*)d_in[2], (const float*)d_in[4],
                           (const float*)d_in[6], (const float*)d_in[8]};
    const float* csc_w  = (const float*)d_in[9];
    const float* csc_b  = (const float*)d_in[10];
    const float* bn_g   = (const float*)d_in[11];
    const float* bn_b   = (const float*)d_in[12];
    const float* bn_m   = (const float*)d_in[13];
    const float* bn_v   = (const float*)d_in[14];
    const float* ggm_w  = (const float*)d_in[15];
    const float* ggm_b  = (const float*)d_in[16];
    const float* qkv_w  = (const float*)d_in[17];
    const float* qkv_b  = (const float*)d_in[18];
    const float* proj_w = (const float*)d_in[19];
    const float* proj_b = (const float*)d_in[20];
    float* out = (float*)d_out;

    float *p_y, *p_q0, *p_Km, *p_beff;
    __nv_bfloat16 *p_sBh, *p_sBl, *p_TBh, *p_TBl;
    __nv_bfloat16 *p_cAh, *p_cAl, *p_qAh, *p_qAl, *p_kAh, *p_kAl, *p_fAh, *p_fAl;
    cudaGetSymbolAddress((void**)&p_y,    sc_y);
    cudaGetSymbolAddress((void**)&p_q0,   sc_q0);
    cudaGetSymbolAddress((void**)&p_Km,   sc_Km);
    cudaGetSymbolAddress((void**)&p_beff, sc_beff);
    cudaGetSymbolAddress((void**)&p_sBh,  sc_sBh);
    cudaGetSymbolAddress((void**)&p_sBl,  sc_sBl);
    cudaGetSymbolAddress((void**)&p_TBh,  sc_TBh);
    cudaGetSymbolAddress((void**)&p_TBl,  sc_TBl);
    cudaGetSymbolAddress((void**)&p_cAh,  sc_cAh);
    cudaGetSymbolAddress((void**)&p_cAl,  sc_cAl);
    cudaGetSymbolAddress((void**)&p_qAh,  sc_qAh);
    cudaGetSymbolAddress((void**)&p_qAl,  sc_qAl);
    cudaGetSymbolAddress((void**)&p_kAh,  sc_kAh);
    cudaGetSymbolAddress((void**)&p_kAl,  sc_kAl);
    cudaGetSymbolAddress((void**)&p_fAh,  sc_fAh);
    cudaGetSymbolAddress((void**)&p_fAl,  sc_fAl);

    const int GSM = 65536;
    cudaFuncSetAttribute(gemm_mma, cudaFuncAttributeMaxDynamicSharedMemorySize, GSM);

    precompute_kernel<<<1, 128>>>(bn_g, bn_b, bn_m, bn_v, proj_w, qkv_b, proj_b);

    dim3 gdw(HWD / 4 / 256, 16, BB);
    dw_kernel<3><<<gdw, 256>>>(x, dww[0], dwb[0], 0);
    dw_kernel<5><<<gdw, 256>>>(x, dww[1], dwb[1], 1);
    dw_kernel<7><<<gdw, 256>>>(x, dww[2], dwb[2], 2);
    dw_kernel<9><<<gdw, 256>>>(x, dww[3], dwb[3], 3);

    packW_kernel<<<(128*64 + 255)/256, 256>>>(csc_w, 128*64, p_cAh, p_cAl);
    packW_kernel<<<(128*128 + 255)/256, 256>>>(qkv_w, 128*128, p_qAh, p_qAl);
    packW_kernel<<<(128*128 + 255)/256, 256>>>(qkv_w + 128*128, 128*128, p_kAh, p_kAl);

    packS_kernel<<<dim3(NT_S, BB), 256>>>();

    // csc: y[b][c][hw] = csc_w @ s
    gemm_mma<<<dim3(NT_S, 1, BB), 256, GSM>>>(
        p_cAh, p_cAl, 0,
        p_sBh, p_sBl, (size_t)HWD * 64, 1, 0, 64,
        csc_b, p_y, (size_t)CO * HWD, HWD, 64);

    actggm_kernel<<<dim3(49, CO, BB), 256>>>(ggm_w, ggm_b);

    buildT_kernel<<<dim3(LL / 64, 5, BB), 256>>>();

    // q0
    gemm_mma<<<dim3(NT_L, 1, BB), 256, GSM>>>(
        p_qAh, p_qAl, 0,
        p_TBh, p_TBl, (size_t)LL * 640, 1, 0, 640,
        qkv_b, p_q0, (size_t)CO * LL, LL, 128);

    // k over all 5 tokens: z = b*5+p
    gemm_mma<<<dim3(NT_L, 1, BB * 5), 256, GSM>>>(
        p_kAh, p_kAl, 0,
        p_TBh, p_TBl, (size_t)LL * 640, 5, 128, 640,
        qkv_b + 128, p_Km, (size_t)CO * LL, LL, 128);

    gram_kernel<<<dim3(CO, BB), 256>>>();

    feff_kernel<<<(BB * CO * 640) / 256, 256>>>(proj_w, qkv_w);

    // final: out = Feff_b @ T_b
    gemm_mma<<<dim3(NT_L, 1, BB), 256, GSM>>>(
        p_fAh, p_fAl, (size_t)128 * 640,
        p_TBh, p_TBl, (size_t)LL * 640, 1, 0, 640,
        p_beff, out, (size_t)CO * LL, LL, 640);
}

// round 4
// speedup vs baseline: 1.6472x; 1.1641x over previous
#include <cuda_runtime.h>
#include <cuda_bf16.h>
#include <stdint.h>
#include <math.h>

#define BB  8
#define CIN 64
#define CO  128
#define HH  224
#define WW  224
#define HO  112
#define WO  112
#define LL  (HO*WO)     // 12544
#define HWD (HH*WW)     // 50176
#define NT_S (HWD/128)  // 392
#define NT_L (LL/128)   // 98

// ---------------- static device scratch ----------------
__device__ __align__(16) float sc_s[(size_t)BB*CIN*HWD];     // dw output [b][c][hw]
__device__ __align__(16) float sc_y[(size_t)BB*CO*HWD];      // csc output [b][c][hw]
__device__ __align__(16) float sc_g[(size_t)BB*CO*LL];       // guide tokens [b][c][l]
__device__ __align__(16) float sc_Spart[BB*5*NT_L*128];      // score partials
__device__ float sc_attn[BB*5*128];
__device__ float sc_beff[CO], sc_bnscale[CO], sc_bnshift[CO];
// token planes [b][p][l][128c], bf16 hi/lo
__device__ __align__(16) __nv_bfloat16 sc_TBh[(size_t)BB*5*LL*128];
__device__ __align__(16) __nv_bfloat16 sc_TBl[(size_t)BB*5*LL*128];
__device__ __align__(16) __nv_bfloat16 sc_cAh[128*64],  sc_cAl[128*64];
__device__ __align__(16) __nv_bfloat16 sc_qAh[128*128], sc_qAl[128*128];
__device__ __align__(16) __nv_bfloat16 sc_kAh[128*128], sc_kAl[128*128];
__device__ __align__(16) __nv_bfloat16 sc_fAh[(size_t)BB*128*640], sc_fAl[(size_t)BB*128*640];

// ---------------- helpers ----------------
__device__ __forceinline__ uint32_t smem_u32(const void* p) {
    uint32_t a;
    asm("{ .reg .u64 t; cvta.to.shared.u64 t, %1; cvt.u32.u64 %0, t; }" : "=r"(a) : "l"(p));
    return a;
}
__device__ __forceinline__ void split_bf(float v, __nv_bfloat16& h, __nv_bfloat16& l) {
    h = __float2bfloat16(v);
    l = __float2bfloat16(v - __bfloat162float(h));
}

#define LDSM4(r, a)                                                           \
    asm volatile("ldmatrix.sync.aligned.m8n8.x4.shared.b16 {%0,%1,%2,%3}, [%4];" \
        : "=r"((r)[0]), "=r"((r)[1]), "=r"((r)[2]), "=r"((r)[3]) : "r"(a))

__device__ __forceinline__ void mma16816(float* c, const uint32_t* a, uint32_t b0, uint32_t b1) {
    asm volatile(
        "mma.sync.aligned.m16n8k16.row.col.f32.bf16.bf16.f32 "
        "{%0,%1,%2,%3}, {%4,%5,%6,%7}, {%8,%9}, {%0,%1,%2,%3};"
        : "+f"(c[0]), "+f"(c[1]), "+f"(c[2]), "+f"(c[3])
        : "r"(a[0]), "r"(a[1]), "r"(a[2]), "r"(a[3]), "r"(b0), "r"(b1));
}

// copy one 64-k chunk (hi at off, lo at off+16384) into swizzled smem
__device__ __forceinline__ void copy_chunk(char* smem, uint32_t off,
                                           const __nv_bfloat16* gh, const __nv_bfloat16* gl,
                                           int ld, int tid) {
    for (int i = tid; i < 1024; i += 256) {
        int r = i >> 3, cc = i & 7;
        uint32_t d = (uint32_t)(r * 128 + ((cc ^ (r & 7)) << 4));
        *(int4*)(smem + off + d)         = *(const int4*)(gh + r * ld + cc * 8);
        *(int4*)(smem + off + 16384 + d) = *(const int4*)(gl + r * ld + cc * 8);
    }
}

// 128x128 tile gemm over nch 64-k chunks; A chunks at aOff+ch*32768 (hi/lo), B at bOff+ch*32768
__device__ __forceinline__ void mma_tile(uint32_t sb, uint32_t aOff, uint32_t bOff, int nch,
                                         int mr0, int n0, int lane, float c[2][8][4]) {
    int ar = lane & 15, ac = lane >> 4;
    int br = (lane & 7) + ((lane >> 4) << 3), bc = (lane >> 3) & 1;
    for (int ch = 0; ch < nch; ch++) {
        #pragma unroll
        for (int kk = 0; kk < 4; kk++) {
            uint32_t aH[2][4], aL[2][4], bH[4][4], bL[4][4];
            #pragma unroll
            for (int mi = 0; mi < 2; mi++) {
                int r = mr0 + mi * 16 + ar;
                uint32_t addr = sb + aOff + ch * 32768 + r * 128 + (((kk * 2 + ac) ^ (r & 7)) << 4);
                LDSM4(aH[mi], addr);
                LDSM4(aL[mi], addr + 16384);
            }
            #pragma unroll
            for (int np = 0; np < 4; np++) {
                int r = n0 + np * 16 + br;
                uint32_t addr = sb + bOff + ch * 32768 + r * 128 + (((kk * 2 + bc) ^ (r & 7)) << 4);
                LDSM4(bH[np], addr);
                LDSM4(bL[np], addr + 16384);
            }
            #pragma unroll
            for (int mi = 0; mi < 2; mi++)
                #pragma unroll
                for (int np = 0; np < 4; np++) {
                    mma16816(c[mi][np*2],     aH[mi], bH[np][0], bH[np][1]);
                    mma16816(c[mi][np*2],     aH[mi], bL[np][0], bL[np][1]);
                    mma16816(c[mi][np*2],     aL[mi], bH[np][0], bH[np][1]);
                    mma16816(c[mi][np*2 + 1], aH[mi], bH[np][2], bH[np][3]);
                    mma16816(c[mi][np*2 + 1], aH[mi], bL[np][2], bL[np][3]);
                    mma16816(c[mi][np*2 + 1], aL[mi], bH[np][2], bH[np][3]);
                }
        }
    }
}

// ---------------- depthwise conv + channel shuffle ----------------
template<int KSZ>
__global__ void __launch_bounds__(256) dw_kernel(const float* __restrict__ x,
                                                 const float* __restrict__ w,
                                                 const float* __restrict__ bias, int head) {
    const int pad = KSZ / 2;
    int q = blockIdx.x * 256 + threadIdx.x;
    int j = blockIdx.y, b = blockIdx.z;
    int h = q / (WW / 4);
    int w0 = (q % (WW / 4)) * 4;
    const float* xin = x + (unsigned)(b * CIN + head * 16 + j) * HWD;
    const float* wp = w + j * KSZ * KSZ;
    float a0 = bias[j], a1 = a0, a2 = a0, a3 = a0;
    if (h >= pad && h < HH - pad && w0 >= pad && w0 + 3 + pad < WW) {
        #pragma unroll
        for (int ky = 0; ky < KSZ; ky++) {
            const float* row = xin + (unsigned)(h + ky - pad) * WW + w0 - pad;
            float v[KSZ + 3];
            #pragma unroll
            for (int t = 0; t < KSZ + 3; t++) v[t] = row[t];
            #pragma unroll
            for (int kx = 0; kx < KSZ; kx++) {
                float wv = __ldg(&wp[ky * KSZ + kx]);
                a0 += v[kx] * wv; a1 += v[kx + 1] * wv;
                a2 += v[kx + 2] * wv; a3 += v[kx + 3] * wv;
            }
        }
    } else {
        #pragma unroll
        for (int ky = 0; ky < KSZ; ky++) {
            int ih = h + ky - pad;
            if (ih < 0 || ih >= HH) continue;
            const float* row = xin + (unsigned)ih * WW;
            float v[KSZ + 3];
            #pragma unroll
            for (int t = 0; t < KSZ + 3; t++) {
                int iw = w0 - pad + t;
                v[t] = (iw >= 0 && iw < WW) ? row[iw] : 0.f;
            }
            #pragma unroll
            for (int kx = 0; kx < KSZ; kx++) {
                float wv = __ldg(&wp[ky * KSZ + kx]);
                a0 += v[kx] * wv; a1 += v[kx + 1] * wv;
                a2 += v[kx + 2] * wv; a3 += v[kx + 3] * wv;
            }
        }
    }
    float4 r; r.x = a0; r.y = a1; r.z = a2; r.w = a3;
    *reinterpret_cast<float4*>(sc_s + (unsigned)(b * CIN + j * 4 + head) * HWD + (unsigned)h * WW + w0) = r;
}

// ---------------- precompute ----------------
__global__ void precompute_kernel(const float* g, const float* be, const float* mn,
                                  const float* vr, const float* proj_w,
                                  const float* qkv_b, const float* proj_b) {
    int c = threadIdx.x;
    float sc = g[c] * rsqrtf(vr[c] + 1e-5f);
    sc_bnscale[c] = sc;
    sc_bnshift[c] = be[c] - mn[c] * sc;
    float acc = proj_b[c];
    for (int k = 0; k < CO; k++) acc += proj_w[c * CO + k] * qkv_b[256 + k];
    sc_beff[c] = acc;
}

// ---------------- pack weight matrix into hi/lo planes ----------------
__global__ void packW_kernel(const float* __restrict__ W, int n,
                             __nv_bfloat16* __restrict__ Hd, __nv_bfloat16* __restrict__ Ld) {
    int i = blockIdx.x * 256 + threadIdx.x;
    if (i >= n) return;
    __nv_bfloat16 h, l; split_bf(W[i], h, l);
    Hd[i] = h; Ld[i] = l;
}

// ---------------- csc GEMM with fused B transpose-split and TB epilogue ----------------
// grid (NT_S, 1, BB). smem 67584: mainloop [A hi|A lo|B hi|B lo] 16KB each; stage reuses all.
__global__ void __launch_bounds__(256) gemm_csc(const float* __restrict__ bias,
                                                const float* __restrict__ qdummy) {
    extern __shared__ __align__(16) char smem[];
    int tid = threadIdx.x, lane = tid & 31, w = tid >> 5;
    int nt = blockIdx.x, b = blockIdx.z;
    int hw0 = nt * 128;
    uint32_t sb = smem_u32(smem);
    int mr0 = (w & 3) * 32, n0 = (w >> 2) * 64;

    // A: csc weights (single chunk K=64)
    copy_chunk(smem, 0, sc_cAh, sc_cAl, 64, tid);
    // B: transpose-split sc_s fp32 [c][hw] -> smem [hw][64c] swizzled
    {
        int r = tid >> 2, seg = tid & 3;    // r = channel 0..63
        const float* src = sc_s + (unsigned)(b * CIN + r) * HWD + hw0 + seg * 32;
        int cc = r >> 3, cb = (r & 7) * 2;
        #pragma unroll
        for (int jj = 0; jj < 8; jj++) {
            float4 v = *reinterpret_cast<const float4*>(src + jj * 4);
            float vv[4] = {v.x, v.y, v.z, v.w};
            #pragma unroll
            for (int e = 0; e < 4; e++) {
                int hwl = seg * 32 + jj * 4 + e;
                __nv_bfloat16 hb, lb; split_bf(vv[e], hb, lb);
                uint32_t ob = (uint32_t)(hwl * 128 + ((cc ^ (hwl & 7)) << 4) + cb);
                *(uint16_t*)(smem + 32768 + ob) = __bfloat16_as_ushort(hb);
                *(uint16_t*)(smem + 49152 + ob) = __bfloat16_as_ushort(lb);
            }
        }
    }
    __syncthreads();

    float c[2][8][4];
    #pragma unroll
    for (int i = 0; i < 2; i++)
        #pragma unroll
        for (int j = 0; j < 8; j++)
            { c[i][j][0]=0.f; c[i][j][1]=0.f; c[i][j][2]=0.f; c[i][j][3]=0.f; }
    mma_tile(sb, 0, 32768, 1, mr0, n0, lane, c);

    // epilogue (a): y fp32
    int g = lane >> 2, tg = lane & 3;
    #pragma unroll
    for (int mi = 0; mi < 2; mi++) {
        int r0 = mr0 + mi * 16 + g;
        float bv0 = bias[r0], bv1 = bias[r0 + 8];
        #pragma unroll
        for (int ni = 0; ni < 8; ni++) {
            int col = n0 + ni * 8 + tg * 2;
            float2 v0 = make_float2(c[mi][ni][0] + bv0, c[mi][ni][1] + bv0);
            float2 v1 = make_float2(c[mi][ni][2] + bv1, c[mi][ni][3] + bv1);
            *(float2*)(sc_y + (unsigned)(b * CO + r0) * HWD + hw0 + col) = v0;
            *(float2*)(sc_y + (unsigned)(b * CO + r0 + 8) * HWD + hw0 + col) = v1;
        }
    }
    __syncthreads();
    // epilogue (b): stage bf16 hi/lo transposed [hw][hi 128 | lo 128], row stride 264 elems
    {
        uint16_t* sh = (uint16_t*)smem;
        #pragma unroll
        for (int mi = 0; mi < 2; mi++) {
            int r0 = mr0 + mi * 16 + g;
            float bv0 = bias[r0], bv1 = bias[r0 + 8];
            #pragma unroll
            for (int ni = 0; ni < 8; ni++) {
                int col = n0 + ni * 8 + tg * 2;
                float vals[4] = {c[mi][ni][0] + bv0, c[mi][ni][1] + bv0,
                                 c[mi][ni][2] + bv1, c[mi][ni][3] + bv1};
                int rows[4] = {r0, r0, r0 + 8, r0 + 8};
                int cols[4] = {col, col + 1, col, col + 1};
                #pragma unroll
                for (int e = 0; e < 4; e++) {
                    __nv_bfloat16 hb, lb; split_bf(vals[e], hb, lb);
                    sh[cols[e] * 264 + rows[e]]       = __bfloat16_as_ushort(hb);
                    sh[cols[e] * 264 + 128 + rows[e]] = __bfloat16_as_ushort(lb);
                }
            }
        }
    }
    __syncthreads();
    // write out to TB planes 1..4
    {
        int qq = tid & 3, hb = tid >> 2;
        #pragma unroll
        for (int rep = 0; rep < 2; rep++) {
            int hwl = hb + rep * 64;
            int hw = hw0 + hwl;
            int h = hw / WW, wv = hw % WW;
            int p = 1 + ((h & 1) << 1) + (wv & 1);
            int l = (h >> 1) * WO + (wv >> 1);
            __nv_bfloat16* dstp = (qq >> 1) ? sc_TBl : sc_TBh;
            int4* dst = (int4*)(dstp + (unsigned)((b * 5 + p) * LL + l) * 128 + (qq & 1) * 64);
            const int4* src = (const int4*)((char*)smem + hwl * 528 + (qq >> 1) * 256 + (qq & 1) * 128);
            #pragma unroll
            for (int jj = 0; jj < 8; jj++) dst[jj] = src[jj];
        }
    }
}

// ---------------- fused BN + GELU + dwconv7 stride2 ----------------
__global__ void __launch_bounds__(256) actggm_kernel(const float* __restrict__ w,
                                                     const float* __restrict__ bias) {
    __shared__ float a[38 * 38];
    __shared__ float wk[49];
    int t = blockIdx.x, c = blockIdx.y, b = blockIdx.z;
    int ty = t / 7, tx = t % 7;
    int ho0 = ty * 16, wo0 = tx * 16;
    if (threadIdx.x < 49) wk[threadIdx.x] = w[c * 49 + threadIdx.x];
    const float* y = sc_y + (unsigned)(b * CO + c) * HWD;
    float bs = sc_bnscale[c], bh = sc_bnshift[c];
    for (int ii = threadIdx.x; ii < 38 * 38; ii += 256) {
        int r = ii / 38, col = ii % 38;
        int ih = 2 * ho0 - 3 + r, iw = 2 * wo0 - 3 + col;
        float v = 0.f;
        if (ih >= 0 && ih < HH && iw >= 0 && iw < WW) {
            v = y[(unsigned)ih * WW + iw] * bs + bh;
            v = 0.5f * v * (1.f + erff(v * 0.7071067811865476f));
        }
        a[ii] = v;
    }
    __syncthreads();
    int oy = threadIdx.x / 16, ox = threadIdx.x % 16;
    float acc = bias[c];
    #pragma unroll
    for (int i = 0; i < 7; i++)
        #pragma unroll
        for (int j = 0; j < 7; j++)
            acc += a[(2 * oy + i) * 38 + (2 * ox + j)] * wk[i * 7 + j];
    sc_g[(unsigned)(b * CO + c) * LL + (unsigned)(ho0 + oy) * WO + wo0 + ox] = acc;
}

// ---------------- g -> TB plane 0 (transpose + split) ----------------
__global__ void __launch_bounds__(256) buildT0_kernel() {
    extern __shared__ __align__(16) char smem[];   // 67584
    int lt = blockIdx.x, b = blockIdx.y;
    int tid = threadIdx.x;
    uint16_t* sh = (uint16_t*)smem;
    {
        int c = tid >> 1, seg = tid & 1;
        const float* gsrc = sc_g + (unsigned)(b * CO + c) * LL + lt * 128 + seg * 64;
        #pragma unroll 8
        for (int j = 0; j < 64; j++) {
            __nv_bfloat16 hb, lb; split_bf(gsrc[j], hb, lb);
            int l = seg * 64 + j;
            sh[l * 264 + c]       = __bfloat16_as_ushort(hb);
            sh[l * 264 + 128 + c] = __bfloat16_as_ushort(lb);
        }
    }
    __syncthreads();
    int qq = tid & 3, hb2 = tid >> 2;
    #pragma unroll
    for (int rep = 0; rep < 2; rep++) {
        int ll = hb2 + rep * 64;
        int l = lt * 128 + ll;
        __nv_bfloat16* dstp = (qq >> 1) ? sc_TBl : sc_TBh;
        int4* dst = (int4*)(dstp + (unsigned)((b * 5 + 0) * LL + l) * 128 + (qq & 1) * 64);
        const int4* src = (const int4*)((char*)smem + ll * 528 + (qq >> 1) * 256 + (qq & 1) * 128);
        #pragma unroll
        for (int jj = 0; jj < 8; jj++) dst[jj] = src[jj];
    }
}

// ---------------- fused score kernel: q0 tile + 5x k-gemm + reduce ----------------
// grid (NT_L, 1, BB). smem: W 0..64K (2 chunks), B 64K..128K (2 chunks),
// q0s fp32 [128][132] at 131072 (67584), red 8*32 floats at 198656. total 199680.
__global__ void __launch_bounds__(256) score_kernel(const float* __restrict__ qkv_b) {
    extern __shared__ __align__(16) char smem[];
    int tid = threadIdx.x, lane = tid & 31, w = tid >> 5;
    int nt = blockIdx.x, b = blockIdx.z;
    int l0 = nt * 128;
    uint32_t sb = smem_u32(smem);
    int mr0 = (w & 3) * 32, n0 = (w >> 2) * 64;
    int g = lane >> 2, tg = lane & 3;
    float* q0s = (float*)(smem + 131072);
    float* red = (float*)(smem + 198656);

    // load Wq (2 chunks) + B plane 0 (2 chunks)
    for (int ch = 0; ch < 2; ch++) {
        copy_chunk(smem, ch * 32768, sc_qAh + ch * 64, sc_qAl + ch * 64, 128, tid);
        copy_chunk(smem, 65536 + ch * 32768,
                   sc_TBh + (unsigned)((b * 5 + 0) * LL + l0) * 128 + ch * 64,
                   sc_TBl + (unsigned)((b * 5 + 0) * LL + l0) * 128 + ch * 64, 128, tid);
    }
    __syncthreads();

    float c[2][8][4];
    #pragma unroll
    for (int i = 0; i < 2; i++)
        #pragma unroll
        for (int j = 0; j < 8; j++)
            { c[i][j][0]=0.f; c[i][j][1]=0.f; c[i][j][2]=0.f; c[i][j][3]=0.f; }
    mma_tile(sb, 0, 65536, 2, mr0, n0, lane, c);

    // store q0 (+bias) to smem fp32 [c][132]
    #pragma unroll
    for (int mi = 0; mi < 2; mi++) {
        int r0 = mr0 + mi * 16 + g;
        float bq0 = qkv_b[r0], bq1 = qkv_b[r0 + 8];
        #pragma unroll
        for (int ni = 0; ni < 8; ni++) {
            int col = n0 + ni * 8 + tg * 2;
            q0s[r0 * 132 + col]           = c[mi][ni][0] + bq0;
            q0s[r0 * 132 + col + 1]       = c[mi][ni][1] + bq0;
            q0s[(r0 + 8) * 132 + col]     = c[mi][ni][2] + bq1;
            q0s[(r0 + 8) * 132 + col + 1] = c[mi][ni][3] + bq1;
        }
    }
    __syncthreads();
    // overwrite W with Wk
    for (int ch = 0; ch < 2; ch++)
        copy_chunk(smem, ch * 32768, sc_kAh + ch * 64, sc_kAl + ch * 64, 128, tid);

    for (int p = 0; p < 5; p++) {
        if (p > 0) {
            __syncthreads();
            for (int ch = 0; ch < 2; ch++)
                copy_chunk(smem, 65536 + ch * 32768,
                           sc_TBh + (unsigned)((b * 5 + p) * LL + l0) * 128 + ch * 64,
                           sc_TBl + (unsigned)((b * 5 + p) * LL + l0) * 128 + ch * 64, 128, tid);
        }
        __syncthreads();
        #pragma unroll
        for (int i = 0; i < 2; i++)
            #pragma unroll
            for (int j = 0; j < 8; j++)
                { c[i][j][0]=0.f; c[i][j][1]=0.f; c[i][j][2]=0.f; c[i][j][3]=0.f; }
        mma_tile(sb, 0, 65536, 2, mr0, n0, lane, c);

        float part[4] = {0.f, 0.f, 0.f, 0.f};
        #pragma unroll
        for (int mi = 0; mi < 2; mi++) {
            int r0 = mr0 + mi * 16 + g;
            float bk0 = qkv_b[128 + r0], bk1 = qkv_b[128 + r0 + 8];
            #pragma unroll
            for (int ni = 0; ni < 8; ni++) {
                int col = n0 + ni * 8 + tg * 2;
                part[mi*2]   += (c[mi][ni][0] + bk0) * q0s[r0 * 132 + col]
                              + (c[mi][ni][1] + bk0) * q0s[r0 * 132 + col + 1];
                part[mi*2+1] += (c[mi][ni][2] + bk1) * q0s[(r0 + 8) * 132 + col]
                              + (c[mi][ni][3] + bk1) * q0s[(r0 + 8) * 132 + col + 1];
            }
        }
        #pragma unroll
        for (int e = 0; e < 4; e++) {
            part[e] += __shfl_xor_sync(0xffffffffu, part[e], 1);
            part[e] += __shfl_xor_sync(0xffffffffu, part[e], 2);
        }
        if (tg == 0) {
            red[w * 32 + 0 * 16 + g]     = part[0];
            red[w * 32 + 0 * 16 + g + 8] = part[1];
            red[w * 32 + 1 * 16 + g]     = part[2];
            red[w * 32 + 1 * 16 + g + 8] = part[3];
        }
        __syncthreads();
        if (tid < 128) {
            int cch = tid, wa = cch >> 5, loc = cch & 31;
            float s = red[wa * 32 + loc] + red[(wa + 4) * 32 + loc];
            sc_Spart[((b * 5 + p) * NT_L + nt) * 128 + cch] = s;
        }
    }
}

// ---------------- softmax over 5 tokens ----------------
__global__ void softmax_kernel() {
    int b = blockIdx.x, cc = threadIdx.x;   // 128 threads
    float S[5];
    const float scale = 0.08838834764831845f;   // 1/sqrt(128)
    #pragma unroll
    for (int p = 0; p < 5; p++) {
        float s = 0.f;
        const float* sp = sc_Spart + ((b * 5 + p) * NT_L) * 128 + cc;
        for (int blk = 0; blk < NT_L; blk++) s += sp[blk * 128];
        S[p] = s * scale;
    }
    float m = -1e30f;
    #pragma unroll
    for (int p = 0; p < 5; p++) m = fmaxf(m, S[p]);
    float e[5], sum = 0.f;
    #pragma unroll
    for (int p = 0; p < 5; p++) { e[p] = expf(S[p] - m); sum += e[p]; }
    float inv = 1.f / sum;
    #pragma unroll
    for (int p = 0; p < 5; p++) sc_attn[(b * 5 + p) * 128 + cc] = e[p] * inv;
}

// ---------------- effective folded weight [b][o][p*128+c'] hi/lo ----------------
__global__ void feff_kernel(const float* __restrict__ proj_w, const float* __restrict__ qkv_w) {
    int idx = blockIdx.x * 256 + threadIdx.x;   // 8*128*640
    int j = idx % 640;
    int o = (idx / 640) % CO;
    int b = idx / (640 * CO);
    int pp = j >> 7, cpx = j & 127;
    float acc = 0.f;
    for (int cc = 0; cc < CO; cc++)
        acc += proj_w[o * CO + cc] * sc_attn[(b * 5 + pp) * 128 + cc] * qkv_w[(256 + cc) * CO + cpx];
    __nv_bfloat16 h, l; split_bf(acc, h, l);
    sc_fAh[idx] = h; sc_fAl[idx] = l;
}

// ---------------- final GEMM: out = Feff_b @ T_b + beff ----------------
__global__ void __launch_bounds__(256) gemm_fin(float* __restrict__ out) {
    extern __shared__ __align__(16) char smem[];   // 65536
    int tid = threadIdx.x, lane = tid & 31, w = tid >> 5;
    int nt = blockIdx.x, b = blockIdx.z;
    int l0 = nt * 128;
    uint32_t sb = smem_u32(smem);
    int mr0 = (w & 3) * 32, n0 = (w >> 2) * 64;

    float c[2][8][4];
    #pragma unroll
    for (int i = 0; i < 2; i++)
        #pragma unroll
        for (int j = 0; j < 8; j++)
            { c[i][j][0]=0.f; c[i][j][1]=0.f; c[i][j][2]=0.f; c[i][j][3]=0.f; }

    const __nv_bfloat16* Ah = sc_fAh + (unsigned)b * 128 * 640;
    const __nv_bfloat16* Al = sc_fAl + (unsigned)b * 128 * 640;
    for (int kc = 0; kc < 10; kc++) {
        int plane = kc >> 1, half = kc & 1;
        copy_chunk(smem, 0, Ah + kc * 64, Al + kc * 64, 640, tid);
        copy_chunk(smem, 32768,
                   sc_TBh + (unsigned)((b * 5 + plane) * LL + l0) * 128 + half * 64,
                   sc_TBl + (unsigned)((b * 5 + plane) * LL + l0) * 128 + half * 64, 128, tid);
        __syncthreads();
        mma_tile(sb, 0, 32768, 1, mr0, n0, lane, c);
        __syncthreads();
    }
    int g = lane >> 2, tg = lane & 3;
    #pragma unroll
    for (int mi = 0; mi < 2; mi++) {
        int r0 = mr0 + mi * 16 + g;
        float bv0 = sc_beff[r0], bv1 = sc_beff[r0 + 8];
        #pragma unroll
        for (int ni = 0; ni < 8; ni++) {
            int col = n0 + ni * 8 + tg * 2;
            float2 v0 = make_float2(c[mi][ni][0] + bv0, c[mi][ni][1] + bv0);
            float2 v1 = make_float2(c[mi][ni][2] + bv1, c[mi][ni][3] + bv1);
            *(float2*)(out + (unsigned)(b * CO + r0) * LL + l0 + col) = v0;
            *(float2*)(out + (unsigned)(b * CO + r0 + 8) * LL + l0 + col) = v1;
        }
    }
}

// ---------------- launch ----------------
extern "C" void kernel_launch(void* const* d_in, const int* in_sizes, int n_in,
                              void* d_out, int out_size) {
    const float* x      = (const float*)d_in[0];
    const float* dww[4] = {(const float*)d_in[1], (const float*)d_in[3],
                           (const float*)d_in[5], (const float*)d_in[7]};
    const float* dwb[4] = {(const float*)d_in[2], (const float*)d_in[4],
                           (const float*)d_in[6], (const float*)d_in[8]};
    const float* csc_w  = (const float*)d_in[9];
    const float* csc_b  = (const float*)d_in[10];
    const float* bn_g   = (const float*)d_in[11];
    const float* bn_b   = (const float*)d_in[12];
    const float* bn_m   = (const float*)d_in[13];
    const float* bn_v   = (const float*)d_in[14];
    const float* ggm_w  = (const float*)d_in[15];
    const float* ggm_b  = (const float*)d_in[16];
    const float* qkv_w  = (const float*)d_in[17];
    const float* qkv_b  = (const float*)d_in[18];
    const float* proj_w = (const float*)d_in[19];
    const float* proj_b = (const float*)d_in[20];
    float* out = (float*)d_out;

    __nv_bfloat16 *p_cAh, *p_cAl, *p_qAh, *p_qAl, *p_kAh, *p_kAl;
    cudaGetSymbolAddress((void**)&p_cAh, sc_cAh);
    cudaGetSymbolAddress((void**)&p_cAl, sc_cAl);
    cudaGetSymbolAddress((void**)&p_qAh, sc_qAh);
    cudaGetSymbolAddress((void**)&p_qAl, sc_qAl);
    cudaGetSymbolAddress((void**)&p_kAh, sc_kAh);
    cudaGetSymbolAddress((void**)&p_kAl, sc_kAl);

    static bool attr_set = false;
    cudaFuncSetAttribute(gemm_csc, cudaFuncAttributeMaxDynamicSharedMemorySize, 67584);
    cudaFuncSetAttribute(buildT0_kernel, cudaFuncAttributeMaxDynamicSharedMemorySize, 67584);
    cudaFuncSetAttribute(score_kernel, cudaFuncAttributeMaxDynamicSharedMemorySize, 199680);
    cudaFuncSetAttribute(gemm_fin, cudaFuncAttributeMaxDynamicSharedMemorySize, 65536);
    (void)attr_set;

    precompute_kernel<<<1, 128>>>(bn_g, bn_b, bn_m, bn_v, proj_w, qkv_b, proj_b);

    dim3 gdw(HWD / 4 / 256, 16, BB);
    dw_kernel<3><<<gdw, 256>>>(x, dww[0], dwb[0], 0);
    dw_kernel<5><<<gdw, 256>>>(x, dww[1], dwb[1], 1);
    dw_kernel<7><<<gdw, 256>>>(x, dww[2], dwb[2], 2);
    dw_kernel<9><<<gdw, 256>>>(x, dww[3], dwb[3], 3);

    packW_kernel<<<(128*64 + 255)/256, 256>>>(csc_w, 128*64, p_cAh, p_cAl);
    packW_kernel<<<(128*128 + 255)/256, 256>>>(qkv_w, 128*128, p_qAh, p_qAl);
    packW_kernel<<<(128*128 + 255)/256, 256>>>(qkv_w + 128*128, 128*128, p_kAh, p_kAl);

    gemm_csc<<<dim3(NT_S, 1, BB), 256, 67584>>>(csc_b, nullptr);

    actggm_kernel<<<dim3(49, CO, BB), 256>>>(ggm_w, ggm_b);

    buildT0_kernel<<<dim3(NT_L, BB), 256, 67584>>>();

    score_kernel<<<dim3(NT_L, 1, BB), 256, 199680>>>(qkv_b);

    softmax_kernel<<<BB, 128>>>();

    feff_kernel<<<(BB * CO * 640) / 256, 256>>>(proj_w, qkv_w);

    gemm_fin<<<dim3(NT_L, 1, BB), 256, 65536>>>(out);
}

// round 6
// speedup vs baseline: 2.3022x; 1.3976x over previous
#include <cuda_runtime.h>
#include <cuda_bf16.h>
#include <cuda_fp16.h>
#include <stdint.h>
#include <math.h>

#define BB  8
#define CIN 64
#define CO  128
#define HH  224
#define WW  224
#define HO  112
#define WO  112
#define LL  (HO*WO)     // 12544
#define HWD (HH*WW)     // 50176
#define NT_S (HWD/128)  // 392
#define NT_L (LL/128)   // 98

// ---------------- static device scratch ----------------
__device__ __align__(16) float sc_s[(size_t)BB*CIN*HWD];     // dw output [b][c][hw]
__device__ __align__(16) __half sc_y[(size_t)BB*CO*HWD];     // csc output fp16 (guide path)
__device__ __align__(16) float sc_g[(size_t)BB*CO*LL];       // guide tokens [b][c][l]
__device__ __align__(16) float sc_Spart[BB*5*NT_L*128];
__device__ float sc_attn[BB*5*128];
__device__ float sc_beff[CO], sc_bnscale[CO], sc_bnshift[CO];
__device__ __align__(16) __nv_bfloat16 sc_TBh[(size_t)BB*5*LL*128];
__device__ __align__(16) __nv_bfloat16 sc_TBl[(size_t)BB*5*LL*128];
__device__ __align__(16) __nv_bfloat16 sc_cAh[128*64],  sc_cAl[128*64];
__device__ __align__(16) __nv_bfloat16 sc_qAh[128*128], sc_qAl[128*128];
__device__ __align__(16) __nv_bfloat16 sc_kAh[128*128], sc_kAl[128*128];
__device__ __align__(16) __nv_bfloat16 sc_fAh[(size_t)BB*128*640], sc_fAl[(size_t)BB*128*640];

// ---------------- helpers ----------------
__device__ __forceinline__ uint32_t smem_u32(const void* p) {
    uint32_t a;
    asm("{ .reg .u64 t; cvta.to.shared.u64 t, %1; cvt.u32.u64 %0, t; }" : "=r"(a) : "l"(p));
    return a;
}
__device__ __forceinline__ void split_bf(float v, __nv_bfloat16& h, __nv_bfloat16& l) {
    h = __float2bfloat16(v);
    l = __float2bfloat16(v - __bfloat162float(h));
}
__device__ __forceinline__ uint32_t pack2(__nv_bfloat16 a, __nv_bfloat16 b) {
    return (uint32_t)__bfloat16_as_ushort(a) | ((uint32_t)__bfloat16_as_ushort(b) << 16);
}

#define LDSM4(r, a)                                                           \
    asm volatile("ldmatrix.sync.aligned.m8n8.x4.shared.b16 {%0,%1,%2,%3}, [%4];" \
        : "=r"((r)[0]), "=r"((r)[1]), "=r"((r)[2]), "=r"((r)[3]) : "r"(a))

__device__ __forceinline__ void mma16816(float* c, const uint32_t* a, uint32_t b0, uint32_t b1) {
    asm volatile(
        "mma.sync.aligned.m16n8k16.row.col.f32.bf16.bf16.f32 "
        "{%0,%1,%2,%3}, {%4,%5,%6,%7}, {%8,%9}, {%0,%1,%2,%3};"
        : "+f"(c[0]), "+f"(c[1]), "+f"(c[2]), "+f"(c[3])
        : "r"(a[0]), "r"(a[1]), "r"(a[2]), "r"(a[3]), "r"(b0), "r"(b1));
}

__device__ __forceinline__ void cpa16(uint32_t saddr, const void* g) {
    asm volatile("cp.async.cg.shared.global [%0], [%1], 16;" :: "r"(saddr), "l"(g));
}
#define CPA_COMMIT() asm volatile("cp.async.commit_group;" ::: "memory")
#define CPA_WAIT1()  asm volatile("cp.async.wait_group 1;" ::: "memory")

// regular copy of one 64-k chunk (hi at off, lo at off+16384) into swizzled smem
__device__ __forceinline__ void copy_chunk(char* smem, uint32_t off,
                                           const __nv_bfloat16* gh, const __nv_bfloat16* gl,
                                           int ld, int tid) {
    for (int i = tid; i < 1024; i += 256) {
        int r = i >> 3, cc = i & 7;
        uint32_t d = (uint32_t)(r * 128 + ((cc ^ (r & 7)) << 4));
        *(int4*)(smem + off + d)         = *(const int4*)(gh + r * ld + cc * 8);
        *(int4*)(smem + off + 16384 + d) = *(const int4*)(gl + r * ld + cc * 8);
    }
}
// async version
__device__ __forceinline__ void copy_chunk_async(uint32_t sb, uint32_t off,
                                                 const __nv_bfloat16* gh, const __nv_bfloat16* gl,
                                                 int ld, int tid) {
    for (int i = tid; i < 1024; i += 256) {
        int r = i >> 3, cc = i & 7;
        uint32_t d = (uint32_t)(r * 128 + ((cc ^ (r & 7)) << 4));
        cpa16(sb + off + d,         gh + r * ld + cc * 8);
        cpa16(sb + off + 16384 + d, gl + r * ld + cc * 8);
    }
}

// 128x128 tile gemm over nch 64-k chunks
__device__ __forceinline__ void mma_tile(uint32_t sb, uint32_t aOff, uint32_t bOff, int nch,
                                         int mr0, int n0, int lane, float c[2][8][4]) {
    int ar = lane & 15, ac = lane >> 4;
    int br = (lane & 7) + ((lane >> 4) << 3), bc = (lane >> 3) & 1;
    for (int ch = 0; ch < nch; ch++) {
        #pragma unroll
        for (int kk = 0; kk < 4; kk++) {
            uint32_t aH[2][4], aL[2][4], bH[4][4], bL[4][4];
            #pragma unroll
            for (int mi = 0; mi < 2; mi++) {
                int r = mr0 + mi * 16 + ar;
                uint32_t addr = sb + aOff + ch * 32768 + r * 128 + (((kk * 2 + ac) ^ (r & 7)) << 4);
                LDSM4(aH[mi], addr);
                LDSM4(aL[mi], addr + 16384);
            }
            #pragma unroll
            for (int np = 0; np < 4; np++) {
                int r = n0 + np * 16 + br;
                uint32_t addr = sb + bOff + ch * 32768 + r * 128 + (((kk * 2 + bc) ^ (r & 7)) << 4);
                LDSM4(bH[np], addr);
                LDSM4(bL[np], addr + 16384);
            }
            #pragma unroll
            for (int mi = 0; mi < 2; mi++)
                #pragma unroll
                for (int np = 0; np < 4; np++) {
                    mma16816(c[mi][np*2],     aH[mi], bH[np][0], bH[np][1]);
                    mma16816(c[mi][np*2],     aH[mi], bL[np][0], bL[np][1]);
                    mma16816(c[mi][np*2],     aL[mi], bH[np][0], bH[np][1]);
                    mma16816(c[mi][np*2 + 1], aH[mi], bH[np][2], bH[np][3]);
                    mma16816(c[mi][np*2 + 1], aH[mi], bL[np][2], bL[np][3]);
                    mma16816(c[mi][np*2 + 1], aL[mi], bH[np][2], bH[np][3]);
                }
        }
    }
}

// ---------------- depthwise conv + channel shuffle: 8 outputs/thread, float4 loads ----------------
template<int KSZ>
__global__ void __launch_bounds__(224) dw_kernel(const float* __restrict__ x,
                                                 const float* __restrict__ w,
                                                 const float* __restrict__ bias, int head) {
    const int pad = KSZ / 2;
    __shared__ float wks[KSZ * KSZ];
    int tid = threadIdx.x;
    int j = blockIdx.y, b = blockIdx.z;
    if (tid < KSZ * KSZ) wks[tid] = w[j * KSZ * KSZ + tid];
    __syncthreads();
    int q = blockIdx.x * 224 + tid;
    int h = q / 28;
    int wg = q % 28;
    int w0 = wg * 8;
    const float* xin = x + (unsigned)(b * CIN + head * 16 + j) * HWD;
    float bv = bias[j];
    float acc[8];
    #pragma unroll
    for (int o = 0; o < 8; o++) acc[o] = bv;
    const float4 z4 = make_float4(0.f, 0.f, 0.f, 0.f);
    #pragma unroll
    for (int ky = 0; ky < KSZ; ky++) {
        int ih = h + ky - pad;
        if (ih < 0 || ih >= HH) continue;
        const float4* row = (const float4*)(xin + (unsigned)ih * WW);
        int i0 = wg * 2 - 1;
        float4 v0 = (i0 >= 0) ? row[i0] : z4;
        float4 v1 = row[i0 + 1];
        float4 v2 = row[i0 + 2];
        float4 v3 = (i0 + 3 < 56) ? row[i0 + 3] : z4;
        float win[16];
        win[0]=v0.x; win[1]=v0.y; win[2]=v0.z; win[3]=v0.w;
        win[4]=v1.x; win[5]=v1.y; win[6]=v1.z; win[7]=v1.w;
        win[8]=v2.x; win[9]=v2.y; win[10]=v2.z; win[11]=v2.w;
        win[12]=v3.x; win[13]=v3.y; win[14]=v3.z; win[15]=v3.w;
        #pragma unroll
        for (int kx = 0; kx < KSZ; kx++) {
            float wv = wks[ky * KSZ + kx];
            #pragma unroll
            for (int o = 0; o < 8; o++)
                acc[o] += win[o + kx + 4 - pad] * wv;
        }
    }
    float* dst = sc_s + (unsigned)(b * CIN + j * 4 + head) * HWD + (unsigned)h * WW + w0;
    *(float4*)dst       = make_float4(acc[0], acc[1], acc[2], acc[3]);
    *(float4*)(dst + 4) = make_float4(acc[4], acc[5], acc[6], acc[7]);
}

// ---------------- precompute ----------------
__global__ void precompute_kernel(const float* g, const float* be, const float* mn,
                                  const float* vr, const float* proj_w,
                                  const float* qkv_b, const float* proj_b) {
    int c = threadIdx.x;
    float sc = g[c] * rsqrtf(vr[c] + 1e-5f);
    sc_bnscale[c] = sc;
    sc_bnshift[c] = be[c] - mn[c] * sc;
    float acc = proj_b[c];
    for (int k = 0; k < CO; k++) acc += proj_w[c * CO + k] * qkv_b[256 + k];
    sc_beff[c] = acc;
}

// ---------------- pack weight matrix into hi/lo planes ----------------
__global__ void packW_kernel(const float* __restrict__ W, int n,
                             __nv_bfloat16* __restrict__ Hd, __nv_bfloat16* __restrict__ Ld) {
    int i = blockIdx.x * 256 + threadIdx.x;
    if (i >= n) return;
    __nv_bfloat16 h, l; split_bf(W[i], h, l);
    Hd[i] = h; Ld[i] = l;
}

// ---------------- csc GEMM with fused B transpose-split and TB epilogue ----------------
__global__ void __launch_bounds__(256) gemm_csc(const float* __restrict__ bias) {
    extern __shared__ __align__(16) char smem[];
    int tid = threadIdx.x, lane = tid & 31, w = tid >> 5;
    int nt = blockIdx.x, b = blockIdx.z;
    int hw0 = nt * 128;
    uint32_t sb = smem_u32(smem);
    int mr0 = (w & 3) * 32, n0 = (w >> 2) * 64;

    // A: csc weights (single chunk K=64)
    copy_chunk(smem, 0, sc_cAh, sc_cAl, 64, tid);
    // B: transpose-split sc_s fp32 [c][hw] -> smem [hw][64c] swizzled (channel pairs, u32 stores)
    {
        int r = tid & 31;          // channel pair
        int seg = tid >> 5;        // 8 segments x 16 hw
        int c0 = 2 * r;
        int cc = c0 >> 3, cbw = (c0 & 7) * 2;
        const float* src0 = sc_s + (unsigned)(b * CIN + c0) * HWD + hw0 + seg * 16;
        const float* src1 = src0 + HWD;
        #pragma unroll
        for (int jj = 0; jj < 4; jj++) {
            float4 a4 = *(const float4*)(src0 + jj * 4);
            float4 b4 = *(const float4*)(src1 + jj * 4);
            float va[4] = {a4.x, a4.y, a4.z, a4.w};
            float vb[4] = {b4.x, b4.y, b4.z, b4.w};
            #pragma unroll
            for (int e = 0; e < 4; e++) {
                int hwl = seg * 16 + jj * 4 + e;
                __nv_bfloat16 h0, l0, h1, l1;
                split_bf(va[e], h0, l0); split_bf(vb[e], h1, l1);
                uint32_t off = (uint32_t)(hwl * 128 + ((cc ^ (hwl & 7)) << 4) + cbw);
                *(uint32_t*)(smem + 32768 + off) = pack2(h0, h1);
                *(uint32_t*)(smem + 49152 + off) = pack2(l0, l1);
            }
        }
    }
    __syncthreads();

    float c[2][8][4];
    #pragma unroll
    for (int i = 0; i < 2; i++)
        #pragma unroll
        for (int j = 0; j < 8; j++)
            { c[i][j][0]=0.f; c[i][j][1]=0.f; c[i][j][2]=0.f; c[i][j][3]=0.f; }
    mma_tile(sb, 0, 32768, 1, mr0, n0, lane, c);

    int g = lane >> 2, tg = lane & 3;
    // epilogue (a): y fp16
    #pragma unroll
    for (int mi = 0; mi < 2; mi++) {
        int r0 = mr0 + mi * 16 + g;
        float bv0 = bias[r0], bv1 = bias[r0 + 8];
        #pragma unroll
        for (int ni = 0; ni < 8; ni++) {
            int col = n0 + ni * 8 + tg * 2;
            __half2 v0 = __floats2half2_rn(c[mi][ni][0] + bv0, c[mi][ni][1] + bv0);
            __half2 v1 = __floats2half2_rn(c[mi][ni][2] + bv1, c[mi][ni][3] + bv1);
            *(__half2*)(sc_y + (unsigned)(b * CO + r0) * HWD + hw0 + col) = v0;
            *(__half2*)(sc_y + (unsigned)(b * CO + r0 + 8) * HWD + hw0 + col) = v1;
        }
    }
    __syncthreads();
    // epilogue (b): stage transposed [hw][hi128|lo128], row stride 264 u16
    {
        uint16_t* sh = (uint16_t*)smem;
        #pragma unroll
        for (int mi = 0; mi < 2; mi++) {
            int r0 = mr0 + mi * 16 + g;
            float bv0 = bias[r0], bv1 = bias[r0 + 8];
            #pragma unroll
            for (int ni = 0; ni < 8; ni++) {
                int col = n0 + ni * 8 + tg * 2;
                float vals[4] = {c[mi][ni][0] + bv0, c[mi][ni][1] + bv0,
                                 c[mi][ni][2] + bv1, c[mi][ni][3] + bv1};
                int rows[4] = {r0, r0, r0 + 8, r0 + 8};
                int cols[4] = {col, col + 1, col, col + 1};
                #pragma unroll
                for (int e = 0; e < 4; e++) {
                    __nv_bfloat16 hb, lb; split_bf(vals[e], hb, lb);
                    sh[cols[e] * 264 + rows[e]]       = __bfloat16_as_ushort(hb);
                    sh[cols[e] * 264 + 128 + rows[e]] = __bfloat16_as_ushort(lb);
                }
            }
        }
    }
    __syncthreads();
    // write out to TB planes 1..4
    {
        int qq = tid & 3, hb = tid >> 2;
        #pragma unroll
        for (int rep = 0; rep < 2; rep++) {
            int hwl = hb + rep * 64;
            int hw = hw0 + hwl;
            int h = hw / WW, wv = hw % WW;
            int p = 1 + ((h & 1) << 1) + (wv & 1);
            int l = (h >> 1) * WO + (wv >> 1);
            __nv_bfloat16* dstp = (qq >> 1) ? sc_TBl : sc_TBh;
            int4* dst = (int4*)(dstp + (unsigned)((b * 5 + p) * LL + l) * 128 + (qq & 1) * 64);
            const int4* src = (const int4*)((char*)smem + hwl * 528 + (qq >> 1) * 256 + (qq & 1) * 128);
            #pragma unroll
            for (int jj = 0; jj < 8; jj++) dst[jj] = src[jj];
        }
    }
}

// ---------------- fused BN + GELU + dwconv7 stride2 (fp16 y in) ----------------
__global__ void __launch_bounds__(256) actggm_kernel(const float* __restrict__ w,
                                                     const float* __restrict__ bias) {
    __shared__ float a[38 * 38];
    __shared__ float wk[49];
    int t = blockIdx.x, c = blockIdx.y, b = blockIdx.z;
    int ty = t / 7, tx = t % 7;
    int ho0 = ty * 16, wo0 = tx * 16;
    if (threadIdx.x < 49) wk[threadIdx.x] = w[c * 49 + threadIdx.x];
    const __half* y = sc_y + (unsigned)(b * CO + c) * HWD;
    float bs = sc_bnscale[c], bh = sc_bnshift[c];
    for (int ii = threadIdx.x; ii < 38 * 38; ii += 256) {
        int r = ii / 38, col = ii % 38;
        int ih = 2 * ho0 - 3 + r, iw = 2 * wo0 - 3 + col;
        float v = 0.f;
        if (ih >= 0 && ih < HH && iw >= 0 && iw < WW) {
            v = __half2float(y[(unsigned)ih * WW + iw]) * bs + bh;
            v = 0.5f * v * (1.f + erff(v * 0.7071067811865476f));
        }
        a[ii] = v;
    }
    __syncthreads();
    int oy = threadIdx.x / 16, ox = threadIdx.x % 16;
    float acc = bias[c];
    #pragma unroll
    for (int i = 0; i < 7; i++)
        #pragma unroll
        for (int j = 0; j < 7; j++)
            acc += a[(2 * oy + i) * 38 + (2 * ox + j)] * wk[i * 7 + j];
    sc_g[(unsigned)(b * CO + c) * LL + (unsigned)(ho0 + oy) * WO + wo0 + ox] = acc;
}

// ---------------- g -> TB plane 0 ----------------
__global__ void __launch_bounds__(256) buildT0_kernel() {
    extern __shared__ __align__(16) char smem[];
    int lt = blockIdx.x, b = blockIdx.y;
    int tid = threadIdx.x;
    uint16_t* sh = (uint16_t*)smem;
    {
        int c = tid >> 1, seg = tid & 1;
        const float* gsrc = sc_g + (unsigned)(b * CO + c) * LL + lt * 128 + seg * 64;
        #pragma unroll 8
        for (int j = 0; j < 64; j++) {
            __nv_bfloat16 hb, lb; split_bf(gsrc[j], hb, lb);
            int l = seg * 64 + j;
            sh[l * 264 + c]       = __bfloat16_as_ushort(hb);
            sh[l * 264 + 128 + c] = __bfloat16_as_ushort(lb);
        }
    }
    __syncthreads();
    int qq = tid & 3, hb2 = tid >> 2;
    #pragma unroll
    for (int rep = 0; rep < 2; rep++) {
        int ll = hb2 + rep * 64;
        int l = lt * 128 + ll;
        __nv_bfloat16* dstp = (qq >> 1) ? sc_TBl : sc_TBh;
        int4* dst = (int4*)(dstp + (unsigned)((b * 5 + 0) * LL + l) * 128 + (qq & 1) * 64);
        const int4* src = (const int4*)((char*)smem + ll * 528 + (qq >> 1) * 256 + (qq & 1) * 128);
        #pragma unroll
        for (int jj = 0; jj < 8; jj++) dst[jj] = src[jj];
    }
}

// ---------------- fused score kernel: q0 in regs + cp.async double-buffered planes ----------------
// smem: W 0..64K (2 chunks), B buf0 64K..128K, buf1 128K..192K, red at 196608. total 197632.
__global__ void __launch_bounds__(256) score_kernel(const float* __restrict__ qkv_b) {
    extern __shared__ __align__(16) char smem[];
    int tid = threadIdx.x, lane = tid & 31, w = tid >> 5;
    int nt = blockIdx.x, b = blockIdx.z;
    int l0 = nt * 128;
    uint32_t sb = smem_u32(smem);
    int mr0 = (w & 3) * 32, n0 = (w >> 2) * 64;
    int g = lane >> 2, tg = lane & 3;
    float* red = (float*)(smem + 196608);

    // Wq (regular) + plane0 -> buf0, plane1 -> buf1 (async groups)
    for (int ch = 0; ch < 2; ch++)
        copy_chunk(smem, ch * 32768, sc_qAh + ch * 64, sc_qAl + ch * 64, 128, tid);
    for (int ch = 0; ch < 2; ch++)
        copy_chunk_async(sb, 65536 + ch * 32768,
                         sc_TBh + (unsigned)((b * 5 + 0) * LL + l0) * 128 + ch * 64,
                         sc_TBl + (unsigned)((b * 5 + 0) * LL + l0) * 128 + ch * 64, 128, tid);
    CPA_COMMIT();
    for (int ch = 0; ch < 2; ch++)
        copy_chunk_async(sb, 131072 + ch * 32768,
                         sc_TBh + (unsigned)((b * 5 + 1) * LL + l0) * 128 + ch * 64,
                         sc_TBl + (unsigned)((b * 5 + 1) * LL + l0) * 128 + ch * 64, 128, tid);
    CPA_COMMIT();
    CPA_WAIT1();           // plane0 complete (plane1 may be in flight)
    __syncthreads();

    float c[2][8][4];
    #pragma unroll
    for (int i = 0; i < 2; i++)
        #pragma unroll
        for (int j = 0; j < 8; j++)
            { c[i][j][0]=0.f; c[i][j][1]=0.f; c[i][j][2]=0.f; c[i][j][3]=0.f; }
    mma_tile(sb, 0, 65536, 2, mr0, n0, lane, c);

    // q0 -> registers with bias folded
    float qreg[2][8][4];
    #pragma unroll
    for (int mi = 0; mi < 2; mi++) {
        int r0 = mr0 + mi * 16 + g;
        float bq0 = qkv_b[r0], bq1 = qkv_b[r0 + 8];
        #pragma unroll
        for (int ni = 0; ni < 8; ni++) {
            qreg[mi][ni][0] = c[mi][ni][0] + bq0;
            qreg[mi][ni][1] = c[mi][ni][1] + bq0;
            qreg[mi][ni][2] = c[mi][ni][2] + bq1;
            qreg[mi][ni][3] = c[mi][ni][3] + bq1;
        }
    }
    __syncthreads();    // all warps done reading W region
    for (int ch = 0; ch < 2; ch++)
        copy_chunk(smem, ch * 32768, sc_kAh + ch * 64, sc_kAl + ch * 64, 128, tid);
    __syncthreads();    // Wk visible

    for (int p = 0; p < 5; p++) {
        int buf = p & 1;
        uint32_t bOff = 65536 + (uint32_t)buf * 65536;
        if (p >= 1) { CPA_WAIT1(); __syncthreads(); }
        #pragma unroll
        for (int i = 0; i < 2; i++)
            #pragma unroll
            for (int j = 0; j < 8; j++)
                { c[i][j][0]=0.f; c[i][j][1]=0.f; c[i][j][2]=0.f; c[i][j][3]=0.f; }
        mma_tile(sb, 0, bOff, 2, mr0, n0, lane, c);

        float part[4] = {0.f, 0.f, 0.f, 0.f};
        #pragma unroll
        for (int mi = 0; mi < 2; mi++) {
            int r0 = mr0 + mi * 16 + g;
            float bk0 = qkv_b[128 + r0], bk1 = qkv_b[128 + r0 + 8];
            #pragma unroll
            for (int ni = 0; ni < 8; ni++) {
                part[mi*2]   += (c[mi][ni][0] + bk0) * qreg[mi][ni][0]
                              + (c[mi][ni][1] + bk0) * qreg[mi][ni][1];
                part[mi*2+1] += (c[mi][ni][2] + bk1) * qreg[mi][ni][2]
                              + (c[mi][ni][3] + bk1) * qreg[mi][ni][3];
            }
        }
        #pragma unroll
        for (int e = 0; e < 4; e++) {
            part[e] += __shfl_xor_sync(0xffffffffu, part[e], 1);
            part[e] += __shfl_xor_sync(0xffffffffu, part[e], 2);
        }
        if (tg == 0) {
            red[w * 32 + 0 * 16 + g]     = part[0];
            red[w * 32 + 0 * 16 + g + 8] = part[1];
            red[w * 32 + 1 * 16 + g]     = part[2];
            red[w * 32 + 1 * 16 + g + 8] = part[3];
        }
        __syncthreads();
        if (tid < 128) {
            int cch = tid, wa = cch >> 5, loc = cch & 31;
            sc_Spart[((b * 5 + p) * NT_L + nt) * 128 + cch] =
                red[wa * 32 + loc] + red[(wa + 4) * 32 + loc];
        }
        if (p + 2 <= 4) {   // prefetch plane p+2 into the buffer just consumed
            for (int ch = 0; ch < 2; ch++)
                copy_chunk_async(sb, bOff + ch * 32768,
                                 sc_TBh + (unsigned)((b * 5 + p + 2) * LL + l0) * 128 + ch * 64,
                                 sc_TBl + (unsigned)((b * 5 + p + 2) * LL + l0) * 128 + ch * 64, 128, tid);
            CPA_COMMIT();
        }
    }
}

// ---------------- softmax over 5 tokens ----------------
__global__ void softmax_kernel() {
    int b = blockIdx.x, cc = threadIdx.x;
    float S[5];
    const float scale = 0.08838834764831845f;
    #pragma unroll
    for (int p = 0; p < 5; p++) {
        float s = 0.f;
        const float* sp = sc_Spart + ((b * 5 + p) * NT_L) * 128 + cc;
        for (int blk = 0; blk < NT_L; blk++) s += sp[blk * 128];
        S[p] = s * scale;
    }
    float m = -1e30f;
    #pragma unroll
    for (int p = 0; p < 5; p++) m = fmaxf(m, S[p]);
    float e[5], sum = 0.f;
    #pragma unroll
    for (int p = 0; p < 5; p++) { e[p] = expf(S[p] - m); sum += e[p]; }
    float inv = 1.f / sum;
    #pragma unroll
    for (int p = 0; p < 5; p++) sc_attn[(b * 5 + p) * 128 + cc] = e[p] * inv;
}

// ---------------- effective folded weight ----------------
__global__ void feff_kernel(const float* __restrict__ proj_w, const float* __restrict__ qkv_w) {
    int idx = blockIdx.x * 256 + threadIdx.x;
    int j = idx % 640;
    int o = (idx / 640) % CO;
    int b = idx / (640 * CO);
    int pp = j >> 7, cpx = j & 127;
    float acc = 0.f;
    for (int cc = 0; cc < CO; cc++)
        acc += proj_w[o * CO + cc] * sc_attn[(b * 5 + pp) * 128 + cc] * qkv_w[(256 + cc) * CO + cpx];
    __nv_bfloat16 h, l; split_bf(acc, h, l);
    sc_fAh[idx] = h; sc_fAl[idx] = l;
}

// ---------------- final GEMM: out = Feff_b @ T_b + beff (cp.async double-buffered) ----------------
__global__ void __launch_bounds__(256) gemm_fin(float* __restrict__ out) {
    extern __shared__ __align__(16) char smem[];   // 131072: buf{0,1} x (A 32K | B 32K)
    int tid = threadIdx.x, lane = tid & 31, w = tid >> 5;
    int nt = blockIdx.x, b = blockIdx.z;
    int l0 = nt * 128;
    uint32_t sb = smem_u32(smem);
    int mr0 = (w & 3) * 32, n0 = (w >> 2) * 64;

    const __nv_bfloat16* Ah = sc_fAh + (unsigned)b * 128 * 640;
    const __nv_bfloat16* Al = sc_fAl + (unsigned)b * 128 * 640;

    auto issue = [&](int kc, int buf) {
        int plane = kc >> 1, half = kc & 1;
        uint32_t base = (uint32_t)buf * 65536;
        copy_chunk_async(sb, base, Ah + kc * 64, Al + kc * 64, 640, tid);
        copy_chunk_async(sb, base + 32768,
                         sc_TBh + (unsigned)((b * 5 + plane) * LL + l0) * 128 + half * 64,
                         sc_TBl + (unsigned)((b * 5 + plane) * LL + l0) * 128 + half * 64, 128, tid);
        CPA_COMMIT();
    };
    issue(0, 0);
    issue(1, 1);

    float c[2][8][4];
    #pragma unroll
    for (int i = 0; i < 2; i++)
        #pragma unroll
        for (int j = 0; j < 8; j++)
            { c[i][j][0]=0.f; c[i][j][1]=0.f; c[i][j][2]=0.f; c[i][j][3]=0.f; }

    for (int kc = 0; kc < 10; kc++) {
        int buf = kc & 1;
        CPA_WAIT1();
        __syncthreads();
        mma_tile(sb, (uint32_t)buf * 65536, (uint32_t)buf * 65536 + 32768, 1, mr0, n0, lane, c);
        __syncthreads();
        if (kc + 2 < 10) issue(kc + 2, buf);
    }
    int g = lane >> 2, tg = lane & 3;
    #pragma unroll
    for (int mi = 0; mi < 2; mi++) {
        int r0 = mr0 + mi * 16 + g;
        float bv0 = sc_beff[r0], bv1 = sc_beff[r0 + 8];
        #pragma unroll
        for (int ni = 0; ni < 8; ni++) {
            int col = n0 + ni * 8 + tg * 2;
            float2 v0 = make_float2(c[mi][ni][0] + bv0, c[mi][ni][1] + bv0);
            float2 v1 = make_float2(c[mi][ni][2] + bv1, c[mi][ni][3] + bv1);
            *(float2*)(out + (unsigned)(b * CO + r0) * LL + l0 + col) = v0;
            *(float2*)(out + (unsigned)(b * CO + r0 + 8) * LL + l0 + col) = v1;
        }
    }
}

// ---------------- launch ----------------
extern "C" void kernel_launch(void* const* d_in, const int* in_sizes, int n_in,
                              void* d_out, int out_size) {
    const float* x      = (const float*)d_in[0];
    const float* dww[4] = {(const float*)d_in[1], (const float*)d_in[3],
                           (const float*)d_in[5], (const float*)d_in[7]};
    const float* dwb[4] = {(const float*)d_in[2], (const float*)d_in[4],
                           (const float*)d_in[6], (const float*)d_in[8]};
    const float* csc_w  = (const float*)d_in[9];
    const float* csc_b  = (const float*)d_in[10];
    const float* bn_g   = (const float*)d_in[11];
    const float* bn_b   = (const float*)d_in[12];
    const float* bn_m   = (const float*)d_in[13];
    const float* bn_v   = (const float*)d_in[14];
    const float* ggm_w  = (const float*)d_in[15];
    const float* ggm_b  = (const float*)d_in[16];
    const float* qkv_w  = (const float*)d_in[17];
    const float* qkv_b  = (const float*)d_in[18];
    const float* proj_w = (const float*)d_in[19];
    const float* proj_b = (const float*)d_in[20];
    float* out = (float*)d_out;

    __nv_bfloat16 *p_cAh, *p_cAl, *p_qAh, *p_qAl, *p_kAh, *p_kAl;
    cudaGetSymbolAddress((void**)&p_cAh, sc_cAh);
    cudaGetSymbolAddress((void**)&p_cAl, sc_cAl);
    cudaGetSymbolAddress((void**)&p_qAh, sc_qAh);
    cudaGetSymbolAddress((void**)&p_qAl, sc_qAl);
    cudaGetSymbolAddress((void**)&p_kAh, sc_kAh);
    cudaGetSymbolAddress((void**)&p_kAl, sc_kAl);

    cudaFuncSetAttribute(gemm_csc, cudaFuncAttributeMaxDynamicSharedMemorySize, 67584);
    cudaFuncSetAttribute(buildT0_kernel, cudaFuncAttributeMaxDynamicSharedMemorySize, 67584);
    cudaFuncSetAttribute(score_kernel, cudaFuncAttributeMaxDynamicSharedMemorySize, 197632);
    cudaFuncSetAttribute(gemm_fin, cudaFuncAttributeMaxDynamicSharedMemorySize, 131072);

    precompute_kernel<<<1, 128>>>(bn_g, bn_b, bn_m, bn_v, proj_w, qkv_b, proj_b);

    dim3 gdw(28, 16, BB);
    dw_kernel<3><<<gdw, 224>>>(x, dww[0], dwb[0], 0);
    dw_kernel<5><<<gdw, 224>>>(x, dww[1], dwb[1], 1);
    dw_kernel<7><<<gdw, 224>>>(x, dww[2], dwb[2], 2);
    dw_kernel<9><<<gdw, 224>>>(x, dww[3], dwb[3], 3);

    packW_kernel<<<(128*64 + 255)/256, 256>>>(csc_w, 128*64, p_cAh, p_cAl);
    packW_kernel<<<(128*128 + 255)/256, 256>>>(qkv_w, 128*128, p_qAh, p_qAl);
    packW_kernel<<<(128*128 + 255)/256, 256>>>(qkv_w + 128*128, 128*128, p_kAh, p_kAl);

    gemm_csc<<<dim3(NT_S, 1, BB), 256, 67584>>>(csc_b);

    actggm_kernel<<<dim3(49, CO, BB), 256>>>(ggm_w, ggm_b);

    buildT0_kernel<<<dim3(NT_L, BB), 256, 67584>>>();

    score_kernel<<<dim3(NT_L, 1, BB), 256, 197632>>>(qkv_b);

    softmax_kernel<<<BB, 128>>>();

    feff_kernel<<<(BB * CO * 640) / 256, 256>>>(proj_w, qkv_w);

    gemm_fin<<<dim3(NT_L, 1, BB), 256, 131072>>>(out);
}

// round 7
// speedup vs baseline: 2.5606x; 1.1123x over previous
#include <cuda_runtime.h>
#include <cuda_fp16.h>
#include <stdint.h>
#include <math.h>

#define BB  8
#define CIN 64
#define CO  128
#define HH  224
#define WW  224
#define HO  112
#define WO  112
#define LL  (HO*WO)     // 12544
#define HWD (HH*WW)     // 50176
#define NT_S (HWD/128)  // 392
#define NT_L (LL/128)   // 98

// ---------------- static device scratch ----------------
__device__ __align__(16) float sc_s[(size_t)BB*CIN*HWD];     // dw output [b][c][hw]
__device__ __align__(16) __half sc_y[(size_t)BB*CO*HWD];     // csc output fp16 (guide path)
__device__ __align__(16) float sc_g[(size_t)BB*CO*LL];       // guide tokens [b][c][l]
__device__ __align__(16) float sc_Spart[BB*5*NT_L*128];
__device__ float sc_attn[BB*5*128];
__device__ float sc_beff[CO], sc_bnscale[CO], sc_bnshift[CO];
// token planes [b][p][l][c], fp16 hi/lo
__device__ __align__(16) __half sc_TBh[(size_t)BB*5*LL*128];
__device__ __align__(16) __half sc_TBl[(size_t)BB*5*LL*128];
__device__ __align__(16) __half sc_cAh[128*64],  sc_cAl[128*64];
__device__ __align__(16) __half sc_qA[128*128];   // Wq hi only (score path)
__device__ __align__(16) __half sc_kA[128*128];   // Wk hi only
__device__ __align__(16) __half sc_fAh[(size_t)BB*128*640], sc_fAl[(size_t)BB*128*640];

// ---------------- helpers ----------------
__device__ __forceinline__ uint32_t smem_u32(const void* p) {
    uint32_t a;
    asm("{ .reg .u64 t; cvta.to.shared.u64 t, %1; cvt.u32.u64 %0, t; }" : "=r"(a) : "l"(p));
    return a;
}
__device__ __forceinline__ void split_h(float v, __half& h, __half& l) {
    h = __float2half_rn(v);
    l = __float2half_rn(v - __half2float(h));
}
__device__ __forceinline__ uint32_t pack2h(__half a, __half b) {
    return (uint32_t)__half_as_ushort(a) | ((uint32_t)__half_as_ushort(b) << 16);
}

#define LDSM4(r, a)                                                           \
    asm volatile("ldmatrix.sync.aligned.m8n8.x4.shared.b16 {%0,%1,%2,%3}, [%4];" \
        : "=r"((r)[0]), "=r"((r)[1]), "=r"((r)[2]), "=r"((r)[3]) : "r"(a))

__device__ __forceinline__ void mma16816(float* c, const uint32_t* a, uint32_t b0, uint32_t b1) {
    asm volatile(
        "mma.sync.aligned.m16n8k16.row.col.f32.f16.f16.f32 "
        "{%0,%1,%2,%3}, {%4,%5,%6,%7}, {%8,%9}, {%0,%1,%2,%3};"
        : "+f"(c[0]), "+f"(c[1]), "+f"(c[2]), "+f"(c[3])
        : "r"(a[0]), "r"(a[1]), "r"(a[2]), "r"(a[3]), "r"(b0), "r"(b1));
}

__device__ __forceinline__ void cpa16(uint32_t saddr, const void* g) {
    asm volatile("cp.async.cg.shared.global [%0], [%1], 16;" :: "r"(saddr), "l"(g));
}
#define CPA_COMMIT() asm volatile("cp.async.commit_group;" ::: "memory")
#define CPA_WAIT1()  asm volatile("cp.async.wait_group 1;" ::: "memory")

// pair chunk: hi at off, lo at off+16384 (32KB)
__device__ __forceinline__ void copy_chunk(char* smem, uint32_t off,
                                           const __half* gh, const __half* gl,
                                           int ld, int tid) {
    for (int i = tid; i < 1024; i += 256) {
        int r = i >> 3, cc = i & 7;
        uint32_t d = (uint32_t)(r * 128 + ((cc ^ (r & 7)) << 4));
        *(int4*)(smem + off + d)         = *(const int4*)(gh + r * ld + cc * 8);
        *(int4*)(smem + off + 16384 + d) = *(const int4*)(gl + r * ld + cc * 8);
    }
}
__device__ __forceinline__ void copy_chunk_async(uint32_t sb, uint32_t off,
                                                 const __half* gh, const __half* gl,
                                                 int ld, int tid) {
    for (int i = tid; i < 1024; i += 256) {
        int r = i >> 3, cc = i & 7;
        uint32_t d = (uint32_t)(r * 128 + ((cc ^ (r & 7)) << 4));
        cpa16(sb + off + d,         gh + r * ld + cc * 8);
        cpa16(sb + off + 16384 + d, gl + r * ld + cc * 8);
    }
}
// hi-only chunk (16KB)
__device__ __forceinline__ void copy_chunk_h(char* smem, uint32_t off,
                                             const __half* gh, int ld, int tid) {
    for (int i = tid; i < 1024; i += 256) {
        int r = i >> 3, cc = i & 7;
        uint32_t d = (uint32_t)(r * 128 + ((cc ^ (r & 7)) << 4));
        *(int4*)(smem + off + d) = *(const int4*)(gh + r * ld + cc * 8);
    }
}
__device__ __forceinline__ void copy_chunk_h_async(uint32_t sb, uint32_t off,
                                                   const __half* gh, int ld, int tid) {
    for (int i = tid; i < 1024; i += 256) {
        int r = i >> 3, cc = i & 7;
        uint32_t d = (uint32_t)(r * 128 + ((cc ^ (r & 7)) << 4));
        cpa16(sb + off + d, gh + r * ld + cc * 8);
    }
}

// 3-term pair gemm over nch 32KB chunks
__device__ __forceinline__ void mma_tile(uint32_t sb, uint32_t aOff, uint32_t bOff, int nch,
                                         int mr0, int n0, int lane, float c[2][8][4]) {
    int ar = lane & 15, ac = lane >> 4;
    int br = (lane & 7) + ((lane >> 4) << 3), bc = (lane >> 3) & 1;
    for (int ch = 0; ch < nch; ch++) {
        #pragma unroll
        for (int kk = 0; kk < 4; kk++) {
            uint32_t aH[2][4], aL[2][4], bH[4][4], bL[4][4];
            #pragma unroll
            for (int mi = 0; mi < 2; mi++) {
                int r = mr0 + mi * 16 + ar;
                uint32_t addr = sb + aOff + ch * 32768 + r * 128 + (((kk * 2 + ac) ^ (r & 7)) << 4);
                LDSM4(aH[mi], addr);
                LDSM4(aL[mi], addr + 16384);
            }
            #pragma unroll
            for (int np = 0; np < 4; np++) {
                int r = n0 + np * 16 + br;
                uint32_t addr = sb + bOff + ch * 32768 + r * 128 + (((kk * 2 + bc) ^ (r & 7)) << 4);
                LDSM4(bH[np], addr);
                LDSM4(bL[np], addr + 16384);
            }
            #pragma unroll
            for (int mi = 0; mi < 2; mi++)
                #pragma unroll
                for (int np = 0; np < 4; np++) {
                    mma16816(c[mi][np*2],     aH[mi], bH[np][0], bH[np][1]);
                    mma16816(c[mi][np*2],     aH[mi], bL[np][0], bL[np][1]);
                    mma16816(c[mi][np*2],     aL[mi], bH[np][0], bH[np][1]);
                    mma16816(c[mi][np*2 + 1], aH[mi], bH[np][2], bH[np][3]);
                    mma16816(c[mi][np*2 + 1], aH[mi], bL[np][2], bL[np][3]);
                    mma16816(c[mi][np*2 + 1], aL[mi], bH[np][2], bH[np][3]);
                }
        }
    }
}

// 1-term hi-only gemm over nch 16KB chunks (score path)
__device__ __forceinline__ void mma_tile_h(uint32_t sb, uint32_t aOff, uint32_t bOff, int nch,
                                           int mr0, int n0, int lane, float c[2][8][4]) {
    int ar = lane & 15, ac = lane >> 4;
    int br = (lane & 7) + ((lane >> 4) << 3), bc = (lane >> 3) & 1;
    for (int ch = 0; ch < nch; ch++) {
        #pragma unroll
        for (int kk = 0; kk < 4; kk++) {
            uint32_t aH[2][4], bH[4][4];
            #pragma unroll
            for (int mi = 0; mi < 2; mi++) {
                int r = mr0 + mi * 16 + ar;
                uint32_t addr = sb + aOff + ch * 16384 + r * 128 + (((kk * 2 + ac) ^ (r & 7)) << 4);
                LDSM4(aH[mi], addr);
            }
            #pragma unroll
            for (int np = 0; np < 4; np++) {
                int r = n0 + np * 16 + br;
                uint32_t addr = sb + bOff + ch * 16384 + r * 128 + (((kk * 2 + bc) ^ (r & 7)) << 4);
                LDSM4(bH[np], addr);
            }
            #pragma unroll
            for (int mi = 0; mi < 2; mi++)
                #pragma unroll
                for (int np = 0; np < 4; np++) {
                    mma16816(c[mi][np*2],     aH[mi], bH[np][0], bH[np][1]);
                    mma16816(c[mi][np*2 + 1], aH[mi], bH[np][2], bH[np][3]);
                }
        }
    }
}

// ---------------- depthwise conv + channel shuffle ----------------
template<int KSZ>
__global__ void __launch_bounds__(224) dw_kernel(const float* __restrict__ x,
                                                 const float* __restrict__ w,
                                                 const float* __restrict__ bias, int head) {
    const int pad = KSZ / 2;
    __shared__ float wks[KSZ * KSZ];
    int tid = threadIdx.x;
    int j = blockIdx.y, b = blockIdx.z;
    if (tid < KSZ * KSZ) wks[tid] = w[j * KSZ * KSZ + tid];
    __syncthreads();
    int q = blockIdx.x * 224 + tid;
    int h = q / 28;
    int wg = q % 28;
    int w0 = wg * 8;
    const float* xin = x + (unsigned)(b * CIN + head * 16 + j) * HWD;
    float bv = bias[j];
    float acc[8];
    #pragma unroll
    for (int o = 0; o < 8; o++) acc[o] = bv;
    const float4 z4 = make_float4(0.f, 0.f, 0.f, 0.f);
    #pragma unroll
    for (int ky = 0; ky < KSZ; ky++) {
        int ih = h + ky - pad;
        if (ih < 0 || ih >= HH) continue;
        const float4* row = (const float4*)(xin + (unsigned)ih * WW);
        int i0 = wg * 2 - 1;
        float4 v0 = (i0 >= 0) ? row[i0] : z4;
        float4 v1 = row[i0 + 1];
        float4 v2 = row[i0 + 2];
        float4 v3 = (i0 + 3 < 56) ? row[i0 + 3] : z4;
        float win[16];
        win[0]=v0.x; win[1]=v0.y; win[2]=v0.z; win[3]=v0.w;
        win[4]=v1.x; win[5]=v1.y; win[6]=v1.z; win[7]=v1.w;
        win[8]=v2.x; win[9]=v2.y; win[10]=v2.z; win[11]=v2.w;
        win[12]=v3.x; win[13]=v3.y; win[14]=v3.z; win[15]=v3.w;
        #pragma unroll
        for (int kx = 0; kx < KSZ; kx++) {
            float wv = wks[ky * KSZ + kx];
            #pragma unroll
            for (int o = 0; o < 8; o++)
                acc[o] += win[o + kx + 4 - pad] * wv;
        }
    }
    float* dst = sc_s + (unsigned)(b * CIN + j * 4 + head) * HWD + (unsigned)h * WW + w0;
    *(float4*)dst       = make_float4(acc[0], acc[1], acc[2], acc[3]);
    *(float4*)(dst + 4) = make_float4(acc[4], acc[5], acc[6], acc[7]);
}

// ---------------- precompute ----------------
__global__ void precompute_kernel(const float* g, const float* be, const float* mn,
                                  const float* vr, const float* proj_w,
                                  const float* qkv_b, const float* proj_b) {
    int c = threadIdx.x;
    float sc = g[c] * rsqrtf(vr[c] + 1e-5f);
    sc_bnscale[c] = sc;
    sc_bnshift[c] = be[c] - mn[c] * sc;
    float acc = proj_b[c];
    for (int k = 0; k < CO; k++) acc += proj_w[c * CO + k] * qkv_b[256 + k];
    sc_beff[c] = acc;
}

// ---------------- pack weights ----------------
__global__ void packW_pair(const float* __restrict__ W, int n,
                           __half* __restrict__ Hd, __half* __restrict__ Ld) {
    int i = blockIdx.x * 256 + threadIdx.x;
    if (i >= n) return;
    __half h, l; split_h(W[i], h, l);
    Hd[i] = h; Ld[i] = l;
}
__global__ void packW_hi(const float* __restrict__ W, int n, __half* __restrict__ Hd) {
    int i = blockIdx.x * 256 + threadIdx.x;
    if (i >= n) return;
    Hd[i] = __float2half_rn(W[i]);
}

// ---------------- csc GEMM with fused B transpose-split and TB epilogue ----------------
__global__ void __launch_bounds__(256) gemm_csc(const float* __restrict__ bias) {
    extern __shared__ __align__(16) char smem[];
    int tid = threadIdx.x, lane = tid & 31, w = tid >> 5;
    int nt = blockIdx.x, b = blockIdx.z;
    int hw0 = nt * 128;
    uint32_t sb = smem_u32(smem);
    int mr0 = (w & 3) * 32, n0 = (w >> 2) * 64;

    copy_chunk(smem, 0, sc_cAh, sc_cAl, 64, tid);
    // B: transpose-split sc_s fp32 [c][hw] -> smem [hw][64c] swizzled
    {
        int r = tid & 31;          // channel pair
        int seg = tid >> 5;
        int c0 = 2 * r;
        int cc = c0 >> 3, cbw = (c0 & 7) * 2;
        const float* src0 = sc_s + (unsigned)(b * CIN + c0) * HWD + hw0 + seg * 16;
        const float* src1 = src0 + HWD;
        #pragma unroll
        for (int jj = 0; jj < 4; jj++) {
            float4 a4 = *(const float4*)(src0 + jj * 4);
            float4 b4 = *(const float4*)(src1 + jj * 4);
            float va[4] = {a4.x, a4.y, a4.z, a4.w};
            float vb[4] = {b4.x, b4.y, b4.z, b4.w};
            #pragma unroll
            for (int e = 0; e < 4; e++) {
                int hwl = seg * 16 + jj * 4 + e;
                __half h0, l0, h1, l1;
                split_h(va[e], h0, l0); split_h(vb[e], h1, l1);
                uint32_t off = (uint32_t)(hwl * 128 + ((cc ^ (hwl & 7)) << 4) + cbw);
                *(uint32_t*)(smem + 32768 + off) = pack2h(h0, h1);
                *(uint32_t*)(smem + 49152 + off) = pack2h(l0, l1);
            }
        }
    }
    __syncthreads();

    float c[2][8][4];
    #pragma unroll
    for (int i = 0; i < 2; i++)
        #pragma unroll
        for (int j = 0; j < 8; j++)
            { c[i][j][0]=0.f; c[i][j][1]=0.f; c[i][j][2]=0.f; c[i][j][3]=0.f; }
    mma_tile(sb, 0, 32768, 1, mr0, n0, lane, c);

    int g = lane >> 2, tg = lane & 3;
    // epilogue (a): y fp16
    #pragma unroll
    for (int mi = 0; mi < 2; mi++) {
        int r0 = mr0 + mi * 16 + g;
        float bv0 = bias[r0], bv1 = bias[r0 + 8];
        #pragma unroll
        for (int ni = 0; ni < 8; ni++) {
            int col = n0 + ni * 8 + tg * 2;
            __half2 v0 = __floats2half2_rn(c[mi][ni][0] + bv0, c[mi][ni][1] + bv0);
            __half2 v1 = __floats2half2_rn(c[mi][ni][2] + bv1, c[mi][ni][3] + bv1);
            *(__half2*)(sc_y + (unsigned)(b * CO + r0) * HWD + hw0 + col) = v0;
            *(__half2*)(sc_y + (unsigned)(b * CO + r0 + 8) * HWD + hw0 + col) = v1;
        }
    }
    __syncthreads();
    // epilogue (b): stage transposed [hw][hi128|lo128], row stride 264 u16
    {
        uint16_t* sh = (uint16_t*)smem;
        #pragma unroll
        for (int mi = 0; mi < 2; mi++) {
            int r0 = mr0 + mi * 16 + g;
            float bv0 = bias[r0], bv1 = bias[r0 + 8];
            #pragma unroll
            for (int ni = 0; ni < 8; ni++) {
                int col = n0 + ni * 8 + tg * 2;
                float vals[4] = {c[mi][ni][0] + bv0, c[mi][ni][1] + bv0,
                                 c[mi][ni][2] + bv1, c[mi][ni][3] + bv1};
                int rows[4] = {r0, r0, r0 + 8, r0 + 8};
                int cols[4] = {col, col + 1, col, col + 1};
                #pragma unroll
                for (int e = 0; e < 4; e++) {
                    __half hb, lb; split_h(vals[e], hb, lb);
                    sh[cols[e] * 264 + rows[e]]       = __half_as_ushort(hb);
                    sh[cols[e] * 264 + 128 + rows[e]] = __half_as_ushort(lb);
                }
            }
        }
    }
    __syncthreads();
    // write out to TB planes 1..4
    {
        int qq = tid & 3, hb = tid >> 2;
        #pragma unroll
        for (int rep = 0; rep < 2; rep++) {
            int hwl = hb + rep * 64;
            int hw = hw0 + hwl;
            int h = hw / WW, wv = hw % WW;
            int p = 1 + ((h & 1) << 1) + (wv & 1);
            int l = (h >> 1) * WO + (wv >> 1);
            __half* dstp = (qq >> 1) ? sc_TBl : sc_TBh;
            int4* dst = (int4*)(dstp + (unsigned)((b * 5 + p) * LL + l) * 128 + (qq & 1) * 64);
            const int4* src = (const int4*)((char*)smem + hwl * 528 + (qq >> 1) * 256 + (qq & 1) * 128);
            #pragma unroll
            for (int jj = 0; jj < 8; jj++) dst[jj] = src[jj];
        }
    }
}

// ---------------- fused BN + GELU + dwconv7 stride2 (fp16 y in) ----------------
__global__ void __launch_bounds__(256) actggm_kernel(const float* __restrict__ w,
                                                     const float* __restrict__ bias) {
    __shared__ float a[38 * 38];
    __shared__ float wk[49];
    int t = blockIdx.x, c = blockIdx.y, b = blockIdx.z;
    int ty = t / 7, tx = t % 7;
    int ho0 = ty * 16, wo0 = tx * 16;
    if (threadIdx.x < 49) wk[threadIdx.x] = w[c * 49 + threadIdx.x];
    const __half* y = sc_y + (unsigned)(b * CO + c) * HWD;
    float bs = sc_bnscale[c], bh = sc_bnshift[c];
    for (int ii = threadIdx.x; ii < 38 * 38; ii += 256) {
        int r = ii / 38, col = ii % 38;
        int ih = 2 * ho0 - 3 + r, iw = 2 * wo0 - 3 + col;
        float v = 0.f;
        if (ih >= 0 && ih < HH && iw >= 0 && iw < WW) {
            v = __half2float(y[(unsigned)ih * WW + iw]) * bs + bh;
            v = 0.5f * v * (1.f + erff(v * 0.7071067811865476f));
        }
        a[ii] = v;
    }
    __syncthreads();
    int oy = threadIdx.x / 16, ox = threadIdx.x % 16;
    float acc = bias[c];
    #pragma unroll
    for (int i = 0; i < 7; i++)
        #pragma unroll
        for (int j = 0; j < 7; j++)
            acc += a[(2 * oy + i) * 38 + (2 * ox + j)] * wk[i * 7 + j];
    sc_g[(unsigned)(b * CO + c) * LL + (unsigned)(ho0 + oy) * WO + wo0 + ox] = acc;
}

// ---------------- g -> TB plane 0 ----------------
__global__ void __launch_bounds__(256) buildT0_kernel() {
    extern __shared__ __align__(16) char smem[];
    int lt = blockIdx.x, b = blockIdx.y;
    int tid = threadIdx.x;
    uint16_t* sh = (uint16_t*)smem;
    {
        int c = tid >> 1, seg = tid & 1;
        const float* gsrc = sc_g + (unsigned)(b * CO + c) * LL + lt * 128 + seg * 64;
        #pragma unroll 8
        for (int j = 0; j < 64; j++) {
            __half hb, lb; split_h(gsrc[j], hb, lb);
            int l = seg * 64 + j;
            sh[l * 264 + c]       = __half_as_ushort(hb);
            sh[l * 264 + 128 + c] = __half_as_ushort(lb);
        }
    }
    __syncthreads();
    int qq = tid & 3, hb2 = tid >> 2;
    #pragma unroll
    for (int rep = 0; rep < 2; rep++) {
        int ll = hb2 + rep * 64;
        int l = lt * 128 + ll;
        __half* dstp = (qq >> 1) ? sc_TBl : sc_TBh;
        int4* dst = (int4*)(dstp + (unsigned)((b * 5 + 0) * LL + l) * 128 + (qq & 1) * 64);
        const int4* src = (const int4*)((char*)smem + ll * 528 + (qq >> 1) * 256 + (qq & 1) * 128);
        #pragma unroll
        for (int jj = 0; jj < 8; jj++) dst[jj] = src[jj];
    }
}

// ---------------- fused score kernel: hi-only 1-term MMA, q0 in regs, double-buffered ----------------
// smem: W 0..32K (2 hi chunks), B buf0 32K..64K, buf1 64K..96K, red at 98304. total 99328.
__global__ void __launch_bounds__(256) score_kernel(const float* __restrict__ qkv_b) {
    extern __shared__ __align__(16) char smem[];
    int tid = threadIdx.x, lane = tid & 31, w = tid >> 5;
    int nt = blockIdx.x, b = blockIdx.z;
    int l0 = nt * 128;
    uint32_t sb = smem_u32(smem);
    int mr0 = (w & 3) * 32, n0 = (w >> 2) * 64;
    int g = lane >> 2, tg = lane & 3;
    float* red = (float*)(smem + 98304);

    for (int ch = 0; ch < 2; ch++)
        copy_chunk_h(smem, ch * 16384, sc_qA + ch * 64, 128, tid);
    for (int ch = 0; ch < 2; ch++)
        copy_chunk_h_async(sb, 32768 + ch * 16384,
                           sc_TBh + (unsigned)((b * 5 + 0) * LL + l0) * 128 + ch * 64, 128, tid);
    CPA_COMMIT();
    for (int ch = 0; ch < 2; ch++)
        copy_chunk_h_async(sb, 65536 + ch * 16384,
                           sc_TBh + (unsigned)((b * 5 + 1) * LL + l0) * 128 + ch * 64, 128, tid);
    CPA_COMMIT();
    CPA_WAIT1();
    __syncthreads();

    float c[2][8][4];
    #pragma unroll
    for (int i = 0; i < 2; i++)
        #pragma unroll
        for (int j = 0; j < 8; j++)
            { c[i][j][0]=0.f; c[i][j][1]=0.f; c[i][j][2]=0.f; c[i][j][3]=0.f; }
    mma_tile_h(sb, 0, 32768, 2, mr0, n0, lane, c);

    float qreg[2][8][4];
    #pragma unroll
    for (int mi = 0; mi < 2; mi++) {
        int r0 = mr0 + mi * 16 + g;
        float bq0 = qkv_b[r0], bq1 = qkv_b[r0 + 8];
        #pragma unroll
        for (int ni = 0; ni < 8; ni++) {
            qreg[mi][ni][0] = c[mi][ni][0] + bq0;
            qreg[mi][ni][1] = c[mi][ni][1] + bq0;
            qreg[mi][ni][2] = c[mi][ni][2] + bq1;
            qreg[mi][ni][3] = c[mi][ni][3] + bq1;
        }
    }
    __syncthreads();
    for (int ch = 0; ch < 2; ch++)
        copy_chunk_h(smem, ch * 16384, sc_kA + ch * 64, 128, tid);
    __syncthreads();

    for (int p = 0; p < 5; p++) {
        int buf = p & 1;
        uint32_t bOff = 32768 + (uint32_t)buf * 32768;
        if (p >= 1) { CPA_WAIT1(); __syncthreads(); }
        #pragma unroll
        for (int i = 0; i < 2; i++)
            #pragma unroll
            for (int j = 0; j < 8; j++)
                { c[i][j][0]=0.f; c[i][j][1]=0.f; c[i][j][2]=0.f; c[i][j][3]=0.f; }
        mma_tile_h(sb, 0, bOff, 2, mr0, n0, lane, c);

        float part[4] = {0.f, 0.f, 0.f, 0.f};
        #pragma unroll
        for (int mi = 0; mi < 2; mi++) {
            int r0 = mr0 + mi * 16 + g;
            float bk0 = qkv_b[128 + r0], bk1 = qkv_b[128 + r0 + 8];
            #pragma unroll
            for (int ni = 0; ni < 8; ni++) {
                part[mi*2]   += (c[mi][ni][0] + bk0) * qreg[mi][ni][0]
                              + (c[mi][ni][1] + bk0) * qreg[mi][ni][1];
                part[mi*2+1] += (c[mi][ni][2] + bk1) * qreg[mi][ni][2]
                              + (c[mi][ni][3] + bk1) * qreg[mi][ni][3];
            }
        }
        #pragma unroll
        for (int e = 0; e < 4; e++) {
            part[e] += __shfl_xor_sync(0xffffffffu, part[e], 1);
            part[e] += __shfl_xor_sync(0xffffffffu, part[e], 2);
        }
        if (tg == 0) {
            red[w * 32 + 0 * 16 + g]     = part[0];
            red[w * 32 + 0 * 16 + g + 8] = part[1];
            red[w * 32 + 1 * 16 + g]     = part[2];
            red[w * 32 + 1 * 16 + g + 8] = part[3];
        }
        __syncthreads();
        if (tid < 128) {
            int cch = tid, wa = cch >> 5, loc = cch & 31;
            sc_Spart[((b * 5 + p) * NT_L + nt) * 128 + cch] =
                red[wa * 32 + loc] + red[(wa + 4) * 32 + loc];
        }
        if (p + 2 <= 4) {
            for (int ch = 0; ch < 2; ch++)
                copy_chunk_h_async(sb, bOff + ch * 16384,
                                   sc_TBh + (unsigned)((b * 5 + p + 2) * LL + l0) * 128 + ch * 64, 128, tid);
            CPA_COMMIT();
        }
    }
}

// ---------------- softmax over 5 tokens ----------------
__global__ void softmax_kernel() {
    int b = blockIdx.x, cc = threadIdx.x;
    float S[5];
    const float scale = 0.08838834764831845f;
    #pragma unroll
    for (int p = 0; p < 5; p++) {
        float s = 0.f;
        const float* sp = sc_Spart + ((b * 5 + p) * NT_L) * 128 + cc;
        for (int blk = 0; blk < NT_L; blk++) s += sp[blk * 128];
        S[p] = s * scale;
    }
    float m = -1e30f;
    #pragma unroll
    for (int p = 0; p < 5; p++) m = fmaxf(m, S[p]);
    float e[5], sum = 0.f;
    #pragma unroll
    for (int p = 0; p < 5; p++) { e[p] = expf(S[p] - m); sum += e[p]; }
    float inv = 1.f / sum;
    #pragma unroll
    for (int p = 0; p < 5; p++) sc_attn[(b * 5 + p) * 128 + cc] = e[p] * inv;
}

// ---------------- effective folded weight ----------------
__global__ void feff_kernel(const float* __restrict__ proj_w, const float* __restrict__ qkv_w) {
    int idx = blockIdx.x * 256 + threadIdx.x;
    int j = idx % 640;
    int o = (idx / 640) % CO;
    int b = idx / (640 * CO);
    int pp = j >> 7, cpx = j & 127;
    float acc = 0.f;
    for (int cc = 0; cc < CO; cc++)
        acc += proj_w[o * CO + cc] * sc_attn[(b * 5 + pp) * 128 + cc] * qkv_w[(256 + cc) * CO + cpx];
    __half h, l; split_h(acc, h, l);
    sc_fAh[idx] = h; sc_fAl[idx] = l;
}

// ---------------- final GEMM: out = Feff_b @ T_b + beff (3-term, double-buffered) ----------------
__global__ void __launch_bounds__(256) gemm_fin(float* __restrict__ out) {
    extern __shared__ __align__(16) char smem[];   // 131072
    int tid = threadIdx.x, lane = tid & 31, w = tid >> 5;
    int nt = blockIdx.x, b = blockIdx.z;
    int l0 = nt * 128;
    uint32_t sb = smem_u32(smem);
    int mr0 = (w & 3) * 32, n0 = (w >> 2) * 64;

    const __half* Ah = sc_fAh + (unsigned)b * 128 * 640;
    const __half* Al = sc_fAl + (unsigned)b * 128 * 640;

    auto issue = [&](int kc, int buf) {
        int plane = kc >> 1, half = kc & 1;
        uint32_t base = (uint32_t)buf * 65536;
        copy_chunk_async(sb, base, Ah + kc * 64, Al + kc * 64, 640, tid);
        copy_chunk_async(sb, base + 32768,
                         sc_TBh + (unsigned)((b * 5 + plane) * LL + l0) * 128 + half * 64,
                         sc_TBl + (unsigned)((b * 5 + plane) * LL + l0) * 128 + half * 64, 128, tid);
        CPA_COMMIT();
    };
    issue(0, 0);
    issue(1, 1);

    float c[2][8][4];
    #pragma unroll
    for (int i = 0; i < 2; i++)
        #pragma unroll
        for (int j = 0; j < 8; j++)
            { c[i][j][0]=0.f; c[i][j][1]=0.f; c[i][j][2]=0.f; c[i][j][3]=0.f; }

    for (int kc = 0; kc < 10; kc++) {
        int buf = kc & 1;
        CPA_WAIT1();
        __syncthreads();
        mma_tile(sb, (uint32_t)buf * 65536, (uint32_t)buf * 65536 + 32768, 1, mr0, n0, lane, c);
        __syncthreads();
        if (kc + 2 < 10) issue(kc + 2, buf);
    }
    int g = lane >> 2, tg = lane & 3;
    #pragma unroll
    for (int mi = 0; mi < 2; mi++) {
        int r0 = mr0 + mi * 16 + g;
        float bv0 = sc_beff[r0], bv1 = sc_beff[r0 + 8];
        #pragma unroll
        for (int ni = 0; ni < 8; ni++) {
            int col = n0 + ni * 8 + tg * 2;
            float2 v0 = make_float2(c[mi][ni][0] + bv0, c[mi][ni][1] + bv0);
            float2 v1 = make_float2(c[mi][ni][2] + bv1, c[mi][ni][3] + bv1);
            *(float2*)(out + (unsigned)(b * CO + r0) * LL + l0 + col) = v0;
            *(float2*)(out + (unsigned)(b * CO + r0 + 8) * LL + l0 + col) = v1;
        }
    }
}

// ---------------- launch ----------------
extern "C" void kernel_launch(void* const* d_in, const int* in_sizes, int n_in,
                              void* d_out, int out_size) {
    const float* x      = (const float*)d_in[0];
    const float* dww[4] = {(const float*)d_in[1], (const float*)d_in[3],
                           (const float*)d_in[5], (const float*)d_in[7]};
    const float* dwb[4] = {(const float*)d_in[2], (const float*)d_in[4],
                           (const float*)d_in[6], (const float*)d_in[8]};
    const float* csc_w  = (const float*)d_in[9];
    const float* csc_b  = (const float*)d_in[10];
    const float* bn_g   = (const float*)d_in[11];
    const float* bn_b   = (const float*)d_in[12];
    const float* bn_m   = (const float*)d_in[13];
    const float* bn_v   = (const float*)d_in[14];
    const float* ggm_w  = (const float*)d_in[15];
    const float* ggm_b  = (const float*)d_in[16];
    const float* qkv_w  = (const float*)d_in[17];
    const float* qkv_b  = (const float*)d_in[18];
    const float* proj_w = (const float*)d_in[19];
    const float* proj_b = (const float*)d_in[20];
    float* out = (float*)d_out;

    __half *p_cAh, *p_cAl, *p_qA, *p_kA;
    cudaGetSymbolAddress((void**)&p_cAh, sc_cAh);
    cudaGetSymbolAddress((void**)&p_cAl, sc_cAl);
    cudaGetSymbolAddress((void**)&p_qA,  sc_qA);
    cudaGetSymbolAddress((void**)&p_kA,  sc_kA);

    cudaFuncSetAttribute(gemm_csc, cudaFuncAttributeMaxDynamicSharedMemorySize, 67584);
    cudaFuncSetAttribute(buildT0_kernel, cudaFuncAttributeMaxDynamicSharedMemorySize, 67584);
    cudaFuncSetAttribute(score_kernel, cudaFuncAttributeMaxDynamicSharedMemorySize, 99328);
    cudaFuncSetAttribute(gemm_fin, cudaFuncAttributeMaxDynamicSharedMemorySize, 131072);

    precompute_kernel<<<1, 128>>>(bn_g, bn_b, bn_m, bn_v, proj_w, qkv_b, proj_b);

    dim3 gdw(28, 16, BB);
    dw_kernel<3><<<gdw, 224>>>(x, dww[0], dwb[0], 0);
    dw_kernel<5><<<gdw, 224>>>(x, dww[1], dwb[1], 1);
    dw_kernel<7><<<gdw, 224>>>(x, dww[2], dwb[2], 2);
    dw_kernel<9><<<gdw, 224>>>(x, dww[3], dwb[3], 3);

    packW_pair<<<(128*64 + 255)/256, 256>>>(csc_w, 128*64, p_cAh, p_cAl);
    packW_hi<<<(128*128 + 255)/256, 256>>>(qkv_w, 128*128, p_qA);
    packW_hi<<<(128*128 + 255)/256, 256>>>(qkv_w + 128*128, 128*128, p_kA);

    gemm_csc<<<dim3(NT_S, 1, BB), 256, 67584>>>(csc_b);

    actggm_kernel<<<dim3(49, CO, BB), 256>>>(ggm_w, ggm_b);

    buildT0_kernel<<<dim3(NT_L, BB), 256, 67584>>>();

    score_kernel<<<dim3(NT_L, 1, BB), 256, 99328>>>(qkv_b);

    softmax_kernel<<<BB, 128>>>();

    feff_kernel<<<(BB * CO * 640) / 256, 256>>>(proj_w, qkv_w);

    gemm_fin<<<dim3(NT_L, 1, BB), 256, 131072>>>(out);
}

// round 9
// speedup vs baseline: 2.9420x; 1.1490x over previous
#include <cuda_runtime.h>
#include <cuda_fp16.h>
#include <stdint.h>
#include <math.h>

#define BB  8
#define CIN 64
#define CO  128
#define HH  224
#define WW  224
#define HO  112
#define WO  112
#define LL  (HO*WO)     // 12544
#define HWD (HH*WW)     // 50176
#define NT_S (HWD/128)  // 392
#define NT_L (LL/128)   // 98

// ---------------- static device scratch ----------------
__device__ __align__(16) float sc_s[(size_t)BB*CIN*HWD];     // dw output [b][c][hw]
__device__ __align__(16) __half sc_y[(size_t)BB*CO*HWD];     // csc output fp16 (guide path)
__device__ __align__(16) float sc_g[(size_t)BB*CO*LL];       // guide tokens [b][c][l]
__device__ __align__(16) float sc_Spart[BB*5*NT_L*128];
__device__ float sc_attn[BB*5*128];
__device__ float sc_beff[CO], sc_bnscale[CO], sc_bnshift[CO];
// token planes [b][p][l][c], fp16 HI ONLY
__device__ __align__(16) __half sc_TBh[(size_t)BB*5*LL*128];
__device__ __align__(16) __half sc_cAh[128*64],  sc_cAl[128*64];
__device__ __align__(16) __half sc_qA[128*128];   // Wq hi only
__device__ __align__(16) __half sc_kA[128*128];   // Wk hi only
__device__ __align__(16) __half sc_fAh[(size_t)BB*128*640], sc_fAl[(size_t)BB*128*640];

// staging row stride for transposed epilogue: 136 u16 = 272 bytes = 17*16 (int4-aligned)
#define TSTR 136

// ---------------- helpers ----------------
__device__ __forceinline__ uint32_t smem_u32(const void* p) {
    uint32_t a;
    asm("{ .reg .u64 t; cvta.to.shared.u64 t, %1; cvt.u32.u64 %0, t; }" : "=r"(a) : "l"(p));
    return a;
}
__device__ __forceinline__ void split_h(float v, __half& h, __half& l) {
    h = __float2half_rn(v);
    l = __float2half_rn(v - __half2float(h));
}
__device__ __forceinline__ uint32_t pack2h(__half a, __half b) {
    return (uint32_t)__half_as_ushort(a) | ((uint32_t)__half_as_ushort(b) << 16);
}

#define LDSM4(r, a)                                                           \
    asm volatile("ldmatrix.sync.aligned.m8n8.x4.shared.b16 {%0,%1,%2,%3}, [%4];" \
        : "=r"((r)[0]), "=r"((r)[1]), "=r"((r)[2]), "=r"((r)[3]) : "r"(a))

__device__ __forceinline__ void mma16816(float* c, const uint32_t* a, uint32_t b0, uint32_t b1) {
    asm volatile(
        "mma.sync.aligned.m16n8k16.row.col.f32.f16.f16.f32 "
        "{%0,%1,%2,%3}, {%4,%5,%6,%7}, {%8,%9}, {%0,%1,%2,%3};"
        : "+f"(c[0]), "+f"(c[1]), "+f"(c[2]), "+f"(c[3])
        : "r"(a[0]), "r"(a[1]), "r"(a[2]), "r"(a[3]), "r"(b0), "r"(b1));
}

__device__ __forceinline__ void cpa16(uint32_t saddr, const void* g) {
    asm volatile("cp.async.cg.shared.global [%0], [%1], 16;" :: "r"(saddr), "l"(g));
}
#define CPA_COMMIT() asm volatile("cp.async.commit_group;" ::: "memory")
#define CPA_WAIT1()  asm volatile("cp.async.wait_group 1;" ::: "memory")

// pair chunk: hi at off, lo at off+16384 (32KB)
__device__ __forceinline__ void copy_chunk(char* smem, uint32_t off,
                                           const __half* gh, const __half* gl,
                                           int ld, int tid) {
    for (int i = tid; i < 1024; i += 256) {
        int r = i >> 3, cc = i & 7;
        uint32_t d = (uint32_t)(r * 128 + ((cc ^ (r & 7)) << 4));
        *(int4*)(smem + off + d)         = *(const int4*)(gh + r * ld + cc * 8);
        *(int4*)(smem + off + 16384 + d) = *(const int4*)(gl + r * ld + cc * 8);
    }
}
__device__ __forceinline__ void copy_chunk_async(uint32_t sb, uint32_t off,
                                                 const __half* gh, const __half* gl,
                                                 int ld, int tid) {
    for (int i = tid; i < 1024; i += 256) {
        int r = i >> 3, cc = i & 7;
        uint32_t d = (uint32_t)(r * 128 + ((cc ^ (r & 7)) << 4));
        cpa16(sb + off + d,         gh + r * ld + cc * 8);
        cpa16(sb + off + 16384 + d, gl + r * ld + cc * 8);
    }
}
// hi-only chunk (16KB)
__device__ __forceinline__ void copy_chunk_h(char* smem, uint32_t off,
                                             const __half* gh, int ld, int tid) {
    for (int i = tid; i < 1024; i += 256) {
        int r = i >> 3, cc = i & 7;
        uint32_t d = (uint32_t)(r * 128 + ((cc ^ (r & 7)) << 4));
        *(int4*)(smem + off + d) = *(const int4*)(gh + r * ld + cc * 8);
    }
}
__device__ __forceinline__ void copy_chunk_h_async(uint32_t sb, uint32_t off,
                                                   const __half* gh, int ld, int tid) {
    for (int i = tid; i < 1024; i += 256) {
        int r = i >> 3, cc = i & 7;
        uint32_t d = (uint32_t)(r * 128 + ((cc ^ (r & 7)) << 4));
        cpa16(sb + off + d, gh + r * ld + cc * 8);
    }
}

// 3-term pair gemm over nch 32KB A + 32KB B chunks (csc value path)
__device__ __forceinline__ void mma_tile(uint32_t sb, uint32_t aOff, uint32_t bOff, int nch,
                                         int mr0, int n0, int lane, float c[2][8][4]) {
    int ar = lane & 15, ac = lane >> 4;
    int br = (lane & 7) + ((lane >> 4) << 3), bc = (lane >> 3) & 1;
    for (int ch = 0; ch < nch; ch++) {
        #pragma unroll
        for (int kk = 0; kk < 4; kk++) {
            uint32_t aH[2][4], aL[2][4], bH[4][4], bL[4][4];
            #pragma unroll
            for (int mi = 0; mi < 2; mi++) {
                int r = mr0 + mi * 16 + ar;
                uint32_t addr = sb + aOff + ch * 32768 + r * 128 + (((kk * 2 + ac) ^ (r & 7)) << 4);
                LDSM4(aH[mi], addr);
                LDSM4(aL[mi], addr + 16384);
            }
            #pragma unroll
            for (int np = 0; np < 4; np++) {
                int r = n0 + np * 16 + br;
                uint32_t addr = sb + bOff + ch * 32768 + r * 128 + (((kk * 2 + bc) ^ (r & 7)) << 4);
                LDSM4(bH[np], addr);
                LDSM4(bL[np], addr + 16384);
            }
            #pragma unroll
            for (int mi = 0; mi < 2; mi++)
                #pragma unroll
                for (int np = 0; np < 4; np++) {
                    mma16816(c[mi][np*2],     aH[mi], bH[np][0], bH[np][1]);
                    mma16816(c[mi][np*2],     aH[mi], bL[np][0], bL[np][1]);
                    mma16816(c[mi][np*2],     aL[mi], bH[np][0], bH[np][1]);
                    mma16816(c[mi][np*2 + 1], aH[mi], bH[np][2], bH[np][3]);
                    mma16816(c[mi][np*2 + 1], aH[mi], bL[np][2], bL[np][3]);
                    mma16816(c[mi][np*2 + 1], aL[mi], bH[np][2], bH[np][3]);
                }
        }
    }
}

// 1-term hi-only gemm (score path), 16KB chunks
__device__ __forceinline__ void mma_tile_h(uint32_t sb, uint32_t aOff, uint32_t bOff, int nch,
                                           int mr0, int n0, int lane, float c[2][8][4]) {
    int ar = lane & 15, ac = lane >> 4;
    int br = (lane & 7) + ((lane >> 4) << 3), bc = (lane >> 3) & 1;
    for (int ch = 0; ch < nch; ch++) {
        #pragma unroll
        for (int kk = 0; kk < 4; kk++) {
            uint32_t aH[2][4], bH[4][4];
            #pragma unroll
            for (int mi = 0; mi < 2; mi++) {
                int r = mr0 + mi * 16 + ar;
                uint32_t addr = sb + aOff + ch * 16384 + r * 128 + (((kk * 2 + ac) ^ (r & 7)) << 4);
                LDSM4(aH[mi], addr);
            }
            #pragma unroll
            for (int np = 0; np < 4; np++) {
                int r = n0 + np * 16 + br;
                uint32_t addr = sb + bOff + ch * 16384 + r * 128 + (((kk * 2 + bc) ^ (r & 7)) << 4);
                LDSM4(bH[np], addr);
            }
            #pragma unroll
            for (int mi = 0; mi < 2; mi++)
                #pragma unroll
                for (int np = 0; np < 4; np++) {
                    mma16816(c[mi][np*2],     aH[mi], bH[np][0], bH[np][1]);
                    mma16816(c[mi][np*2 + 1], aH[mi], bH[np][2], bH[np][3]);
                }
        }
    }
}

// 2-term gemm: A pair (hi at aOff, lo at +16384), B hi-only at bOff (fin path)
__device__ __forceinline__ void mma_tile_fin(uint32_t sb, uint32_t aOff, uint32_t bOff,
                                             int mr0, int n0, int lane, float c[2][8][4]) {
    int ar = lane & 15, ac = lane >> 4;
    int br = (lane & 7) + ((lane >> 4) << 3), bc = (lane >> 3) & 1;
    #pragma unroll
    for (int kk = 0; kk < 4; kk++) {
        uint32_t aH[2][4], aL[2][4], bH[4][4];
        #pragma unroll
        for (int mi = 0; mi < 2; mi++) {
            int r = mr0 + mi * 16 + ar;
            uint32_t addr = sb + aOff + r * 128 + (((kk * 2 + ac) ^ (r & 7)) << 4);
            LDSM4(aH[mi], addr);
            LDSM4(aL[mi], addr + 16384);
        }
        #pragma unroll
        for (int np = 0; np < 4; np++) {
            int r = n0 + np * 16 + br;
            uint32_t addr = sb + bOff + r * 128 + (((kk * 2 + bc) ^ (r & 7)) << 4);
            LDSM4(bH[np], addr);
        }
        #pragma unroll
        for (int mi = 0; mi < 2; mi++)
            #pragma unroll
            for (int np = 0; np < 4; np++) {
                mma16816(c[mi][np*2],     aH[mi], bH[np][0], bH[np][1]);
                mma16816(c[mi][np*2],     aL[mi], bH[np][0], bH[np][1]);
                mma16816(c[mi][np*2 + 1], aH[mi], bH[np][2], bH[np][3]);
                mma16816(c[mi][np*2 + 1], aL[mi], bH[np][2], bH[np][3]);
            }
    }
}

// ---------------- depthwise conv + channel shuffle ----------------
template<int KSZ>
__global__ void __launch_bounds__(224) dw_kernel(const float* __restrict__ x,
                                                 const float* __restrict__ w,
                                                 const float* __restrict__ bias, int head) {
    const int pad = KSZ / 2;
    __shared__ float wks[KSZ * KSZ];
    int tid = threadIdx.x;
    int j = blockIdx.y, b = blockIdx.z;
    if (tid < KSZ * KSZ) wks[tid] = w[j * KSZ * KSZ + tid];
    __syncthreads();
    int q = blockIdx.x * 224 + tid;
    int h = q / 28;
    int wg = q % 28;
    int w0 = wg * 8;
    const float* xin = x + (unsigned)(b * CIN + head * 16 + j) * HWD;
    float bv = bias[j];
    float acc[8];
    #pragma unroll
    for (int o = 0; o < 8; o++) acc[o] = bv;
    const float4 z4 = make_float4(0.f, 0.f, 0.f, 0.f);
    #pragma unroll
    for (int ky = 0; ky < KSZ; ky++) {
        int ih = h + ky - pad;
        if (ih < 0 || ih >= HH) continue;
        const float4* row = (const float4*)(xin + (unsigned)ih * WW);
        int i0 = wg * 2 - 1;
        float4 v0 = (i0 >= 0) ? row[i0] : z4;
        float4 v1 = row[i0 + 1];
        float4 v2 = row[i0 + 2];
        float4 v3 = (i0 + 3 < 56) ? row[i0 + 3] : z4;
        float win[16];
        win[0]=v0.x; win[1]=v0.y; win[2]=v0.z; win[3]=v0.w;
        win[4]=v1.x; win[5]=v1.y; win[6]=v1.z; win[7]=v1.w;
        win[8]=v2.x; win[9]=v2.y; win[10]=v2.z; win[11]=v2.w;
        win[12]=v3.x; win[13]=v3.y; win[14]=v3.z; win[15]=v3.w;
        #pragma unroll
        for (int kx = 0; kx < KSZ; kx++) {
            float wv = wks[ky * KSZ + kx];
            #pragma unroll
            for (int o = 0; o < 8; o++)
                acc[o] += win[o + kx + 4 - pad] * wv;
        }
    }
    float* dst = sc_s + (unsigned)(b * CIN + j * 4 + head) * HWD + (unsigned)h * WW + w0;
    *(float4*)dst       = make_float4(acc[0], acc[1], acc[2], acc[3]);
    *(float4*)(dst + 4) = make_float4(acc[4], acc[5], acc[6], acc[7]);
}

// ---------------- precompute ----------------
__global__ void precompute_kernel(const float* g, const float* be, const float* mn,
                                  const float* vr, const float* proj_w,
                                  const float* qkv_b, const float* proj_b) {
    int c = threadIdx.x;
    float sc = g[c] * rsqrtf(vr[c] + 1e-5f);
    sc_bnscale[c] = sc;
    sc_bnshift[c] = be[c] - mn[c] * sc;
    float acc = proj_b[c];
    for (int k = 0; k < CO; k++) acc += proj_w[c * CO + k] * qkv_b[256 + k];
    sc_beff[c] = acc;
}

// ---------------- pack weights ----------------
__global__ void packW_pair(const float* __restrict__ W, int n,
                           __half* __restrict__ Hd, __half* __restrict__ Ld) {
    int i = blockIdx.x * 256 + threadIdx.x;
    if (i >= n) return;
    __half h, l; split_h(W[i], h, l);
    Hd[i] = h; Ld[i] = l;
}
__global__ void packW_hi(const float* __restrict__ W, int n, __half* __restrict__ Hd) {
    int i = blockIdx.x * 256 + threadIdx.x;
    if (i >= n) return;
    Hd[i] = __float2half_rn(W[i]);
}

// ---------------- csc GEMM with fused B transpose-split and TB-hi epilogue ----------------
__global__ void __launch_bounds__(256) gemm_csc(const float* __restrict__ bias) {
    extern __shared__ __align__(16) char smem[];
    int tid = threadIdx.x, lane = tid & 31, w = tid >> 5;
    int nt = blockIdx.x, b = blockIdx.z;
    int hw0 = nt * 128;
    uint32_t sb = smem_u32(smem);
    int mr0 = (w & 3) * 32, n0 = (w >> 2) * 64;

    copy_chunk(smem, 0, sc_cAh, sc_cAl, 64, tid);
    // B: transpose-split sc_s fp32 [c][hw] -> smem [hw][64c] swizzled (pair)
    {
        int r = tid & 31;          // channel pair
        int seg = tid >> 5;
        int c0 = 2 * r;
        int cc = c0 >> 3, cbw = (c0 & 7) * 2;
        const float* src0 = sc_s + (unsigned)(b * CIN + c0) * HWD + hw0 + seg * 16;
        const float* src1 = src0 + HWD;
        #pragma unroll
        for (int jj = 0; jj < 4; jj++) {
            float4 a4 = *(const float4*)(src0 + jj * 4);
            float4 b4 = *(const float4*)(src1 + jj * 4);
            float va[4] = {a4.x, a4.y, a4.z, a4.w};
            float vb[4] = {b4.x, b4.y, b4.z, b4.w};
            #pragma unroll
            for (int e = 0; e < 4; e++) {
                int hwl = seg * 16 + jj * 4 + e;
                __half h0, l0, h1, l1;
                split_h(va[e], h0, l0); split_h(vb[e], h1, l1);
                uint32_t off = (uint32_t)(hwl * 128 + ((cc ^ (hwl & 7)) << 4) + cbw);
                *(uint32_t*)(smem + 32768 + off) = pack2h(h0, h1);
                *(uint32_t*)(smem + 49152 + off) = pack2h(l0, l1);
            }
        }
    }
    __syncthreads();

    float c[2][8][4];
    #pragma unroll
    for (int i = 0; i < 2; i++)
        #pragma unroll
        for (int j = 0; j < 8; j++)
            { c[i][j][0]=0.f; c[i][j][1]=0.f; c[i][j][2]=0.f; c[i][j][3]=0.f; }
    mma_tile(sb, 0, 32768, 1, mr0, n0, lane, c);

    int g = lane >> 2, tg = lane & 3;
    // epilogue (a): y fp16
    #pragma unroll
    for (int mi = 0; mi < 2; mi++) {
        int r0 = mr0 + mi * 16 + g;
        float bv0 = bias[r0], bv1 = bias[r0 + 8];
        #pragma unroll
        for (int ni = 0; ni < 8; ni++) {
            int col = n0 + ni * 8 + tg * 2;
            __half2 v0 = __floats2half2_rn(c[mi][ni][0] + bv0, c[mi][ni][1] + bv0);
            __half2 v1 = __floats2half2_rn(c[mi][ni][2] + bv1, c[mi][ni][3] + bv1);
            *(__half2*)(sc_y + (unsigned)(b * CO + r0) * HWD + hw0 + col) = v0;
            *(__half2*)(sc_y + (unsigned)(b * CO + r0 + 8) * HWD + hw0 + col) = v1;
        }
    }
    __syncthreads();
    // epilogue (b): stage hi-only transposed [hw][128c], row stride TSTR u16 (272B, int4-aligned)
    {
        uint16_t* sh = (uint16_t*)smem;
        #pragma unroll
        for (int mi = 0; mi < 2; mi++) {
            int r0 = mr0 + mi * 16 + g;
            float bv0 = bias[r0], bv1 = bias[r0 + 8];
            #pragma unroll
            for (int ni = 0; ni < 8; ni++) {
                int col = n0 + ni * 8 + tg * 2;
                float vals[4] = {c[mi][ni][0] + bv0, c[mi][ni][1] + bv0,
                                 c[mi][ni][2] + bv1, c[mi][ni][3] + bv1};
                int rows[4] = {r0, r0, r0 + 8, r0 + 8};
                int cols[4] = {col, col + 1, col, col + 1};
                #pragma unroll
                for (int e = 0; e < 4; e++)
                    sh[cols[e] * TSTR + rows[e]] = __half_as_ushort(__float2half_rn(vals[e]));
            }
        }
    }
    __syncthreads();
    // write out to TB planes 1..4 (hi only)
    {
        int qq = tid & 1, hb = tid >> 1;   // hb = hwl 0..127
        int hw = hw0 + hb;
        int h = hw / WW, wv = hw % WW;
        int p = 1 + ((h & 1) << 1) + (wv & 1);
        int l = (h >> 1) * WO + (wv >> 1);
        int4* dst = (int4*)(sc_TBh + (unsigned)((b * 5 + p) * LL + l) * 128 + qq * 64);
        const int4* src = (const int4*)((char*)smem + hb * (TSTR * 2) + qq * 128);
        #pragma unroll
        for (int jj = 0; jj < 8; jj++) dst[jj] = src[jj];
    }
}

// ---------------- fused BN + GELU + dwconv7 stride2 (fp16 y in) ----------------
__global__ void __launch_bounds__(256) actggm_kernel(const float* __restrict__ w,
                                                     const float* __restrict__ bias) {
    __shared__ float a[38 * 38];
    __shared__ float wk[49];
    int t = blockIdx.x, c = blockIdx.y, b = blockIdx.z;
    int ty = t / 7, tx = t % 7;
    int ho0 = ty * 16, wo0 = tx * 16;
    if (threadIdx.x < 49) wk[threadIdx.x] = w[c * 49 + threadIdx.x];
    const __half* y = sc_y + (unsigned)(b * CO + c) * HWD;
    float bs = sc_bnscale[c], bh = sc_bnshift[c];
    for (int ii = threadIdx.x; ii < 38 * 38; ii += 256) {
        int r = ii / 38, col = ii % 38;
        int ih = 2 * ho0 - 3 + r, iw = 2 * wo0 - 3 + col;
        float v = 0.f;
        if (ih >= 0 && ih < HH && iw >= 0 && iw < WW) {
            v = __half2float(y[(unsigned)ih * WW + iw]) * bs + bh;
            v = 0.5f * v * (1.f + erff(v * 0.7071067811865476f));
        }
        a[ii] = v;
    }
    __syncthreads();
    int oy = threadIdx.x / 16, ox = threadIdx.x % 16;
    float acc = bias[c];
    #pragma unroll
    for (int i = 0; i < 7; i++)
        #pragma unroll
        for (int j = 0; j < 7; j++)
            acc += a[(2 * oy + i) * 38 + (2 * ox + j)] * wk[i * 7 + j];
    sc_g[(unsigned)(b * CO + c) * LL + (unsigned)(ho0 + oy) * WO + wo0 + ox] = acc;
}

// ---------------- g -> TB plane 0 (hi only) ----------------
__global__ void __launch_bounds__(256) buildT0_kernel() {
    extern __shared__ __align__(16) char smem[];   // 128 * 272 = 34816
    int lt = blockIdx.x, b = blockIdx.y;
    int tid = threadIdx.x;
    uint16_t* sh = (uint16_t*)smem;
    {
        int c = tid >> 1, seg = tid & 1;
        const float* gsrc = sc_g + (unsigned)(b * CO + c) * LL + lt * 128 + seg * 64;
        #pragma unroll 8
        for (int j = 0; j < 64; j++) {
            int l = seg * 64 + j;
            sh[l * TSTR + c] = __half_as_ushort(__float2half_rn(gsrc[j]));
        }
    }
    __syncthreads();
    int qq = tid & 1, hb2 = tid >> 1;
    int l = lt * 128 + hb2;
    int4* dst = (int4*)(sc_TBh + (unsigned)((b * 5 + 0) * LL + l) * 128 + qq * 64);
    const int4* src = (const int4*)((char*)smem + hb2 * (TSTR * 2) + qq * 128);
    #pragma unroll
    for (int jj = 0; jj < 8; jj++) dst[jj] = src[jj];
}

// ---------------- fused score kernel (hi-only, q0 in regs, double-buffered) ----------------
// smem: W 0..32K, B buf0 32K..64K, buf1 64K..96K, red at 98304. total 99328.
__global__ void __launch_bounds__(256) score_kernel(const float* __restrict__ qkv_b) {
    extern __shared__ __align__(16) char smem[];
    int tid = threadIdx.x, lane = tid & 31, w = tid >> 5;
    int nt = blockIdx.x, b = blockIdx.z;
    int l0 = nt * 128;
    uint32_t sb = smem_u32(smem);
    int mr0 = (w & 3) * 32, n0 = (w >> 2) * 64;
    int g = lane >> 2, tg = lane & 3;
    float* red = (float*)(smem + 98304);

    for (int ch = 0; ch < 2; ch++)
        copy_chunk_h(smem, ch * 16384, sc_qA + ch * 64, 128, tid);
    for (int ch = 0; ch < 2; ch++)
        copy_chunk_h_async(sb, 32768 + ch * 16384,
                           sc_TBh + (unsigned)((b * 5 + 0) * LL + l0) * 128 + ch * 64, 128, tid);
    CPA_COMMIT();
    for (int ch = 0; ch < 2; ch++)
        copy_chunk_h_async(sb, 65536 + ch * 16384,
                           sc_TBh + (unsigned)((b * 5 + 1) * LL + l0) * 128 + ch * 64, 128, tid);
    CPA_COMMIT();
    CPA_WAIT1();
    __syncthreads();

    float c[2][8][4];
    #pragma unroll
    for (int i = 0; i < 2; i++)
        #pragma unroll
        for (int j = 0; j < 8; j++)
            { c[i][j][0]=0.f; c[i][j][1]=0.f; c[i][j][2]=0.f; c[i][j][3]=0.f; }
    mma_tile_h(sb, 0, 32768, 2, mr0, n0, lane, c);

    float qreg[2][8][4];
    #pragma unroll
    for (int mi = 0; mi < 2; mi++) {
        int r0 = mr0 + mi * 16 + g;
        float bq0 = qkv_b[r0], bq1 = qkv_b[r0 + 8];
        #pragma unroll
        for (int ni = 0; ni < 8; ni++) {
            qreg[mi][ni][0] = c[mi][ni][0] + bq0;
            qreg[mi][ni][1] = c[mi][ni][1] + bq0;
            qreg[mi][ni][2] = c[mi][ni][2] + bq1;
            qreg[mi][ni][3] = c[mi][ni][3] + bq1;
        }
    }
    __syncthreads();
    for (int ch = 0; ch < 2; ch++)
        copy_chunk_h(smem, ch * 16384, sc_kA + ch * 64, 128, tid);
    __syncthreads();

    for (int p = 0; p < 5; p++) {
        int buf = p & 1;
        uint32_t bOff = 32768 + (uint32_t)buf * 32768;
        if (p >= 1) { CPA_WAIT1(); __syncthreads(); }
        #pragma unroll
        for (int i = 0; i < 2; i++)
            #pragma unroll
            for (int j = 0; j < 8; j++)
                { c[i][j][0]=0.f; c[i][j][1]=0.f; c[i][j][2]=0.f; c[i][j][3]=0.f; }
        mma_tile_h(sb, 0, bOff, 2, mr0, n0, lane, c);

        float part[4] = {0.f, 0.f, 0.f, 0.f};
        #pragma unroll
        for (int mi = 0; mi < 2; mi++) {
            int r0 = mr0 + mi * 16 + g;
            float bk0 = qkv_b[128 + r0], bk1 = qkv_b[128 + r0 + 8];
            #pragma unroll
            for (int ni = 0; ni < 8; ni++) {
                part[mi*2]   += (c[mi][ni][0] + bk0) * qreg[mi][ni][0]
                              + (c[mi][ni][1] + bk0) * qreg[mi][ni][1];
                part[mi*2+1] += (c[mi][ni][2] + bk1) * qreg[mi][ni][2]
                              + (c[mi][ni][3] + bk1) * qreg[mi][ni][3];
            }
        }
        #pragma unroll
        for (int e = 0; e < 4; e++) {
            part[e] += __shfl_xor_sync(0xffffffffu, part[e], 1);
            part[e] += __shfl_xor_sync(0xffffffffu, part[e], 2);
        }
        if (tg == 0) {
            red[w * 32 + 0 * 16 + g]     = part[0];
            red[w * 32 + 0 * 16 + g + 8] = part[1];
            red[w * 32 + 1 * 16 + g]     = part[2];
            red[w * 32 + 1 * 16 + g + 8] = part[3];
        }
        __syncthreads();
        if (tid < 128) {
            int cch = tid, wa = cch >> 5, loc = cch & 31;
            sc_Spart[((b * 5 + p) * NT_L + nt) * 128 + cch] =
                red[wa * 32 + loc] + red[(wa + 4) * 32 + loc];
        }
        if (p + 2 <= 4) {
            for (int ch = 0; ch < 2; ch++)
                copy_chunk_h_async(sb, bOff + ch * 16384,
                                   sc_TBh + (unsigned)((b * 5 + p + 2) * LL + l0) * 128 + ch * 64, 128, tid);
            CPA_COMMIT();
        }
    }
}

// ---------------- softmax over 5 tokens ----------------
__global__ void softmax_kernel() {
    int b = blockIdx.x, cc = threadIdx.x;
    float S[5];
    const float scale = 0.08838834764831845f;
    #pragma unroll
    for (int p = 0; p < 5; p++) {
        float s = 0.f;
        const float* sp = sc_Spart + ((b * 5 + p) * NT_L) * 128 + cc;
        for (int blk = 0; blk < NT_L; blk++) s += sp[blk * 128];
        S[p] = s * scale;
    }
    float m = -1e30f;
    #pragma unroll
    for (int p = 0; p < 5; p++) m = fmaxf(m, S[p]);
    float e[5], sum = 0.f;
    #pragma unroll
    for (int p = 0; p < 5; p++) { e[p] = expf(S[p] - m); sum += e[p]; }
    float inv = 1.f / sum;
    #pragma unroll
    for (int p = 0; p < 5; p++) sc_attn[(b * 5 + p) * 128 + cc] = e[p] * inv;
}

// ---------------- effective folded weight ----------------
__global__ void feff_kernel(const float* __restrict__ proj_w, const float* __restrict__ qkv_w) {
    int idx = blockIdx.x * 256 + threadIdx.x;
    int j = idx % 640;
    int o = (idx / 640) % CO;
    int b = idx / (640 * CO);
    int pp = j >> 7, cpx = j & 127;
    float acc = 0.f;
    for (int cc = 0; cc < CO; cc++)
        acc += proj_w[o * CO + cc] * sc_attn[(b * 5 + pp) * 128 + cc] * qkv_w[(256 + cc) * CO + cpx];
    __half h, l; split_h(acc, h, l);
    sc_fAh[idx] = h; sc_fAl[idx] = l;
}

// ---------------- final GEMM: out = Feff_b @ T_b + beff (2-term, double-buffered) ----------------
// smem: buf{0,1} x (A pair 32KB | B hi 16KB) = 98304
__global__ void __launch_bounds__(256) gemm_fin(float* __restrict__ out) {
    extern __shared__ __align__(16) char smem[];
    int tid = threadIdx.x, lane = tid & 31, w = tid >> 5;
    int nt = blockIdx.x, b = blockIdx.z;
    int l0 = nt * 128;
    uint32_t sb = smem_u32(smem);
    int mr0 = (w & 3) * 32, n0 = (w >> 2) * 64;

    const __half* Ah = sc_fAh + (unsigned)b * 128 * 640;
    const __half* Al = sc_fAl + (unsigned)b * 128 * 640;

    auto issue = [&](int kc, int buf) {
        int plane = kc >> 1, half = kc & 1;
        uint32_t base = (uint32_t)buf * 49152;
        copy_chunk_async(sb, base, Ah + kc * 64, Al + kc * 64, 640, tid);
        copy_chunk_h_async(sb, base + 32768,
                           sc_TBh + (unsigned)((b * 5 + plane) * LL + l0) * 128 + half * 64, 128, tid);
        CPA_COMMIT();
    };
    issue(0, 0);
    issue(1, 1);

    float c[2][8][4];
    #pragma unroll
    for (int i = 0; i < 2; i++)
        #pragma unroll
        for (int j = 0; j < 8; j++)
            { c[i][j][0]=0.f; c[i][j][1]=0.f; c[i][j][2]=0.f; c[i][j][3]=0.f; }

    for (int kc = 0; kc < 10; kc++) {
        int buf = kc & 1;
        CPA_WAIT1();
        __syncthreads();
        mma_tile_fin(sb, (uint32_t)buf * 49152, (uint32_t)buf * 49152 + 32768, mr0, n0, lane, c);
        __syncthreads();
        if (kc + 2 < 10) issue(kc + 2, buf);
    }
    int g = lane >> 2, tg = lane & 3;
    #pragma unroll
    for (int mi = 0; mi < 2; mi++) {
        int r0 = mr0 + mi * 16 + g;
        float bv0 = sc_beff[r0], bv1 = sc_beff[r0 + 8];
        #pragma unroll
        for (int ni = 0; ni < 8; ni++) {
            int col = n0 + ni * 8 + tg * 2;
            float2 v0 = make_float2(c[mi][ni][0] + bv0, c[mi][ni][1] + bv0);
            float2 v1 = make_float2(c[mi][ni][2] + bv1, c[mi][ni][3] + bv1);
            *(float2*)(out + (unsigned)(b * CO + r0) * LL + l0 + col) = v0;
            *(float2*)(out + (unsigned)(b * CO + r0 + 8) * LL + l0 + col) = v1;
        }
    }
}

// ---------------- launch ----------------
extern "C" void kernel_launch(void* const* d_in, const int* in_sizes, int n_in,
                              void* d_out, int out_size) {
    const float* x      = (const float*)d_in[0];
    const float* dww[4] = {(const float*)d_in[1], (const float*)d_in[3],
                           (const float*)d_in[5], (const float*)d_in[7]};
    const float* dwb[4] = {(const float*)d_in[2], (const float*)d_in[4],
                           (const float*)d_in[6], (const float*)d_in[8]};
    const float* csc_w  = (const float*)d_in[9];
    const float* csc_b  = (const float*)d_in[10];
    const float* bn_g   = (const float*)d_in[11];
    const float* bn_b   = (const float*)d_in[12];
    const float* bn_m   = (const float*)d_in[13];
    const float* bn_v   = (const float*)d_in[14];
    const float* ggm_w  = (const float*)d_in[15];
    const float* ggm_b  = (const float*)d_in[16];
    const float* qkv_w  = (const float*)d_in[17];
    const float* qkv_b  = (const float*)d_in[18];
    const float* proj_w = (const float*)d_in[19];
    const float* proj_b = (const float*)d_in[20];
    float* out = (float*)d_out;

    __half *p_cAh, *p_cAl, *p_qA, *p_kA;
    cudaGetSymbolAddress((void**)&p_cAh, sc_cAh);
    cudaGetSymbolAddress((void**)&p_cAl, sc_cAl);
    cudaGetSymbolAddress((void**)&p_qA,  sc_qA);
    cudaGetSymbolAddress((void**)&p_kA,  sc_kA);

    cudaFuncSetAttribute(gemm_csc, cudaFuncAttributeMaxDynamicSharedMemorySize, 67584);
    cudaFuncSetAttribute(buildT0_kernel, cudaFuncAttributeMaxDynamicSharedMemorySize, 35840);
    cudaFuncSetAttribute(score_kernel, cudaFuncAttributeMaxDynamicSharedMemorySize, 99328);
    cudaFuncSetAttribute(gemm_fin, cudaFuncAttributeMaxDynamicSharedMemorySize, 98304);

    precompute_kernel<<<1, 128>>>(bn_g, bn_b, bn_m, bn_v, proj_w, qkv_b, proj_b);

    dim3 gdw(28, 16, BB);
    dw_kernel<3><<<gdw, 224>>>(x, dww[0], dwb[0], 0);
    dw_kernel<5><<<gdw, 224>>>(x, dww[1], dwb[1], 1);
    dw_kernel<7><<<gdw, 224>>>(x, dww[2], dwb[2], 2);
    dw_kernel<9><<<gdw, 224>>>(x, dww[3], dwb[3], 3);

    packW_pair<<<(128*64 + 255)/256, 256>>>(csc_w, 128*64, p_cAh, p_cAl);
    packW_hi<<<(128*128 + 255)/256, 256>>>(qkv_w, 128*128, p_qA);
    packW_hi<<<(128*128 + 255)/256, 256>>>(qkv_w + 128*128, 128*128, p_kA);

    gemm_csc<<<dim3(NT_S, 1, BB), 256, 67584>>>(csc_b);

    actggm_kernel<<<dim3(49, CO, BB), 256>>>(ggm_w, ggm_b);

    buildT0_kernel<<<dim3(NT_L, BB), 256, 35840>>>();

    score_kernel<<<dim3(NT_L, 1, BB), 256, 99328>>>(qkv_b);

    softmax_kernel<<<BB, 128>>>();

    feff_kernel<<<(BB * CO * 640) / 256, 256>>>(proj_w, qkv_w);

    gemm_fin<<<dim3(NT_L, 1, BB), 256, 98304>>>(out);
}

// round 12
// speedup vs baseline: 3.1186x; 1.0600x over previous
#include <cuda_runtime.h>
#include <cuda_fp16.h>
#include <stdint.h>
#include <math.h>

#define BB  8
#define CIN 64
#define CO  128
#define HH  224
#define WW  224
#define HO  112
#define WO  112
#define LL  (HO*WO)     // 12544
#define HWD (HH*WW)     // 50176
#define NT_S (HWD/128)  // 392
#define NT_L (LL/128)   // 98

// ---------------- static device scratch ----------------
__device__ __align__(16) __half sc_sh[(size_t)BB*CIN*HWD];   // dw output fp16 [b][c][hw]
__device__ __align__(16) __half sc_y[(size_t)BB*CO*HWD];     // csc output fp16 (guide path)
__device__ __align__(16) float sc_g[(size_t)BB*CO*LL];       // guide tokens [b][c][l]
__device__ __align__(16) float sc_Spart[BB*5*NT_L*128];
__device__ float sc_attn[BB*5*128];
__device__ float sc_beff[CO], sc_bnscale[CO], sc_bnshift[CO];
// token planes [b][p][l][c], fp16 HI ONLY
__device__ __align__(16) __half sc_TBh[(size_t)BB*5*LL*128];
__device__ __align__(16) __half sc_cAh[128*64],  sc_cAl[128*64];
__device__ __align__(16) __half sc_qA[128*128];   // Wq hi only
__device__ __align__(16) __half sc_kA[128*128];   // Wk hi only
__device__ __align__(16) __half sc_fAh[(size_t)BB*128*640], sc_fAl[(size_t)BB*128*640];

// staging row stride for transposed epilogue: 136 u16 = 272 bytes = 17*16 (int4-aligned)
#define TSTR 136

// ---------------- helpers ----------------
__device__ __forceinline__ uint32_t smem_u32(const void* p) {
    uint32_t a;
    asm("{ .reg .u64 t; cvta.to.shared.u64 t, %1; cvt.u32.u64 %0, t; }" : "=r"(a) : "l"(p));
    return a;
}
__device__ __forceinline__ void split_h(float v, __half& h, __half& l) {
    h = __float2half_rn(v);
    l = __float2half_rn(v - __half2float(h));
}

#define LDSM4(r, a)                                                           \
    asm volatile("ldmatrix.sync.aligned.m8n8.x4.shared.b16 {%0,%1,%2,%3}, [%4];" \
        : "=r"((r)[0]), "=r"((r)[1]), "=r"((r)[2]), "=r"((r)[3]) : "r"(a))

__device__ __forceinline__ void mma16816(float* c, const uint32_t* a, uint32_t b0, uint32_t b1) {
    asm volatile(
        "mma.sync.aligned.m16n8k16.row.col.f32.f16.f16.f32 "
        "{%0,%1,%2,%3}, {%4,%5,%6,%7}, {%8,%9}, {%0,%1,%2,%3};"
        : "+f"(c[0]), "+f"(c[1]), "+f"(c[2]), "+f"(c[3])
        : "r"(a[0]), "r"(a[1]), "r"(a[2]), "r"(a[3]), "r"(b0), "r"(b1));
}

__device__ __forceinline__ void cpa16(uint32_t saddr, const void* g) {
    asm volatile("cp.async.cg.shared.global [%0], [%1], 16;" :: "r"(saddr), "l"(g));
}
#define CPA_COMMIT() asm volatile("cp.async.commit_group;" ::: "memory")
#define CPA_WAIT1()  asm volatile("cp.async.wait_group 1;" ::: "memory")
#define CPA_WAIT0()  asm volatile("cp.async.wait_group 0;" ::: "memory")

// pair chunk: hi at off, lo at off+16384 (32KB)
__device__ __forceinline__ void copy_chunk(char* smem, uint32_t off,
                                           const __half* gh, const __half* gl,
                                           int ld, int tid) {
    for (int i = tid; i < 1024; i += 256) {
        int r = i >> 3, cc = i & 7;
        uint32_t d = (uint32_t)(r * 128 + ((cc ^ (r & 7)) << 4));
        *(int4*)(smem + off + d)         = *(const int4*)(gh + r * ld + cc * 8);
        *(int4*)(smem + off + 16384 + d) = *(const int4*)(gl + r * ld + cc * 8);
    }
}
__device__ __forceinline__ void copy_chunk_async(uint32_t sb, uint32_t off,
                                                 const __half* gh, const __half* gl,
                                                 int ld, int tid) {
    for (int i = tid; i < 1024; i += 256) {
        int r = i >> 3, cc = i & 7;
        uint32_t d = (uint32_t)(r * 128 + ((cc ^ (r & 7)) << 4));
        cpa16(sb + off + d,         gh + r * ld + cc * 8);
        cpa16(sb + off + 16384 + d, gl + r * ld + cc * 8);
    }
}
// hi-only chunk (16KB)
__device__ __forceinline__ void copy_chunk_h(char* smem, uint32_t off,
                                             const __half* gh, int ld, int tid) {
    for (int i = tid; i < 1024; i += 256) {
        int r = i >> 3, cc = i & 7;
        uint32_t d = (uint32_t)(r * 128 + ((cc ^ (r & 7)) << 4));
        *(int4*)(smem + off + d) = *(const int4*)(gh + r * ld + cc * 8);
    }
}
__device__ __forceinline__ void copy_chunk_h_async(uint32_t sb, uint32_t off,
                                                   const __half* gh, int ld, int tid) {
    for (int i = tid; i < 1024; i += 256) {
        int r = i >> 3, cc = i & 7;
        uint32_t d = (uint32_t)(r * 128 + ((cc ^ (r & 7)) << 4));
        cpa16(sb + off + d, gh + r * ld + cc * 8);
    }
}

// 1-term hi-only gemm (score path), 16KB chunks
__device__ __forceinline__ void mma_tile_h(uint32_t sb, uint32_t aOff, uint32_t bOff, int nch,
                                           int mr0, int n0, int lane, float c[2][8][4]) {
    int ar = lane & 15, ac = lane >> 4;
    int br = (lane & 7) + ((lane >> 4) << 3), bc = (lane >> 3) & 1;
    for (int ch = 0; ch < nch; ch++) {
        #pragma unroll
        for (int kk = 0; kk < 4; kk++) {
            uint32_t aH[2][4], bH[4][4];
            #pragma unroll
            for (int mi = 0; mi < 2; mi++) {
                int r = mr0 + mi * 16 + ar;
                uint32_t addr = sb + aOff + ch * 16384 + r * 128 + (((kk * 2 + ac) ^ (r & 7)) << 4);
                LDSM4(aH[mi], addr);
            }
            #pragma unroll
            for (int np = 0; np < 4; np++) {
                int r = n0 + np * 16 + br;
                uint32_t addr = sb + bOff + ch * 16384 + r * 128 + (((kk * 2 + bc) ^ (r & 7)) << 4);
                LDSM4(bH[np], addr);
            }
            #pragma unroll
            for (int mi = 0; mi < 2; mi++)
                #pragma unroll
                for (int np = 0; np < 4; np++) {
                    mma16816(c[mi][np*2],     aH[mi], bH[np][0], bH[np][1]);
                    mma16816(c[mi][np*2 + 1], aH[mi], bH[np][2], bH[np][3]);
                }
        }
    }
}

// 2-term gemm: A pair (hi at aOff, lo at +16384), B hi-only at bOff (csc + fin paths)
__device__ __forceinline__ void mma_tile_fin(uint32_t sb, uint32_t aOff, uint32_t bOff,
                                             int mr0, int n0, int lane, float c[2][8][4]) {
    int ar = lane & 15, ac = lane >> 4;
    int br = (lane & 7) + ((lane >> 4) << 3), bc = (lane >> 3) & 1;
    #pragma unroll
    for (int kk = 0; kk < 4; kk++) {
        uint32_t aH[2][4], aL[2][4], bH[4][4];
        #pragma unroll
        for (int mi = 0; mi < 2; mi++) {
            int r = mr0 + mi * 16 + ar;
            uint32_t addr = sb + aOff + r * 128 + (((kk * 2 + ac) ^ (r & 7)) << 4);
            LDSM4(aH[mi], addr);
            LDSM4(aL[mi], addr + 16384);
        }
        #pragma unroll
        for (int np = 0; np < 4; np++) {
            int r = n0 + np * 16 + br;
            uint32_t addr = sb + bOff + r * 128 + (((kk * 2 + bc) ^ (r & 7)) << 4);
            LDSM4(bH[np], addr);
        }
        #pragma unroll
        for (int mi = 0; mi < 2; mi++)
            #pragma unroll
            for (int np = 0; np < 4; np++) {
                mma16816(c[mi][np*2],     aH[mi], bH[np][0], bH[np][1]);
                mma16816(c[mi][np*2],     aL[mi], bH[np][0], bH[np][1]);
                mma16816(c[mi][np*2 + 1], aH[mi], bH[np][2], bH[np][3]);
                mma16816(c[mi][np*2 + 1], aL[mi], bH[np][2], bH[np][3]);
            }
    }
}

// ---------------- depthwise conv + channel shuffle: 2x8 outputs/thread, fp16 out ----------------
template<int KSZ>
__global__ void __launch_bounds__(224) dw_kernel(const float* __restrict__ x,
                                                 const float* __restrict__ w,
                                                 const float* __restrict__ bias, int head) {
    const int pad = KSZ / 2;
    __shared__ float wks[KSZ * KSZ];
    int tid = threadIdx.x;
    int j = blockIdx.y, b = blockIdx.z;
    if (tid < KSZ * KSZ) wks[tid] = w[j * KSZ * KSZ + tid];
    __syncthreads();
    int q = blockIdx.x * 224 + tid;     // 3136 (row-pair, col-group) positions
    int h2 = q / 28, wg = q % 28;
    int h0 = 2 * h2;
    int w0 = wg * 8;
    const float* xin = x + (unsigned)(b * CIN + head * 16 + j) * HWD;
    float bv = bias[j];
    float a0[8], a1[8];
    #pragma unroll
    for (int o = 0; o < 8; o++) { a0[o] = bv; a1[o] = bv; }
    const float4 z4 = make_float4(0.f, 0.f, 0.f, 0.f);
    #pragma unroll
    for (int t = 0; t <= KSZ; t++) {     // KSZ+1 input rows shared across 2 output rows
        int ih = h0 - pad + t;
        if (ih < 0 || ih >= HH) continue;
        const float4* row = (const float4*)(xin + (unsigned)ih * WW);
        int i0 = wg * 2 - 1;
        float4 v0 = (i0 >= 0) ? row[i0] : z4;
        float4 v1 = row[i0 + 1];
        float4 v2 = row[i0 + 2];
        float4 v3 = (i0 + 3 < 56) ? row[i0 + 3] : z4;
        float win[16];
        win[0]=v0.x; win[1]=v0.y; win[2]=v0.z; win[3]=v0.w;
        win[4]=v1.x; win[5]=v1.y; win[6]=v1.z; win[7]=v1.w;
        win[8]=v2.x; win[9]=v2.y; win[10]=v2.z; win[11]=v2.w;
        win[12]=v3.x; win[13]=v3.y; win[14]=v3.z; win[15]=v3.w;
        if (t < KSZ) {
            #pragma unroll
            for (int kx = 0; kx < KSZ; kx++) {
                float wv = wks[t * KSZ + kx];
                #pragma unroll
                for (int o = 0; o < 8; o++)
                    a0[o] += win[o + kx + 4 - pad] * wv;
            }
        }
        if (t >= 1) {
            #pragma unroll
            for (int kx = 0; kx < KSZ; kx++) {
                float wv = wks[(t - 1) * KSZ + kx];
                #pragma unroll
                for (int o = 0; o < 8; o++)
                    a1[o] += win[o + kx + 4 - pad] * wv;
            }
        }
    }
    __half* dst = sc_sh + (unsigned)(b * CIN + j * 4 + head) * HWD + (unsigned)h0 * WW + w0;
    __half hb[8];
    #pragma unroll
    for (int o = 0; o < 8; o++) hb[o] = __float2half_rn(a0[o]);
    *(int4*)dst = *(int4*)hb;
    #pragma unroll
    for (int o = 0; o < 8; o++) hb[o] = __float2half_rn(a1[o]);
    *(int4*)(dst + WW) = *(int4*)hb;
}

// ---------------- precompute ----------------
__global__ void precompute_kernel(const float* g, const float* be, const float* mn,
                                  const float* vr, const float* proj_w,
                                  const float* qkv_b, const float* proj_b) {
    int c = threadIdx.x;
    float sc = g[c] * rsqrtf(vr[c] + 1e-5f);
    sc_bnscale[c] = sc;
    sc_bnshift[c] = be[c] - mn[c] * sc;
    float acc = proj_b[c];
    for (int k = 0; k < CO; k++) acc += proj_w[c * CO + k] * qkv_b[256 + k];
    sc_beff[c] = acc;
}

// ---------------- pack weights ----------------
__global__ void packW_pair(const float* __restrict__ W, int n,
                           __half* __restrict__ Hd, __half* __restrict__ Ld) {
    int i = blockIdx.x * 256 + threadIdx.x;
    if (i >= n) return;
    __half h, l; split_h(W[i], h, l);
    Hd[i] = h; Ld[i] = l;
}
__global__ void packW_hi(const float* __restrict__ W, int n, __half* __restrict__ Hd) {
    int i = blockIdx.x * 256 + threadIdx.x;
    if (i >= n) return;
    Hd[i] = __float2half_rn(W[i]);
}

// ---------------- csc GEMM: A pair x B(s fp16, exact) 2-term + TB-hi epilogue ----------------
// smem: A pair 0..32K, B hi 32K..48K. epilogue staging reuses base. dyn smem 49152.
__global__ void __launch_bounds__(256) gemm_csc(const float* __restrict__ bias) {
    extern __shared__ __align__(16) char smem[];
    int tid = threadIdx.x, lane = tid & 31, w = tid >> 5;
    int nt = blockIdx.x, b = blockIdx.z;
    int hw0 = nt * 128;
    uint32_t sb = smem_u32(smem);
    int mr0 = (w & 3) * 32, n0 = (w >> 2) * 64;

    copy_chunk(smem, 0, sc_cAh, sc_cAl, 64, tid);
    // B: repack s fp16 [c][hw] -> smem [hw][64c] swizzled (hi plane only; exact)
    {
        int r = tid & 31;          // channel pair
        int seg = tid >> 5;
        int c0 = 2 * r;
        int cc = c0 >> 3, cbw = (c0 & 7) * 2;
        const __half* src0 = sc_sh + (unsigned)(b * CIN + c0) * HWD + hw0 + seg * 16;
        const __half* src1 = src0 + HWD;
        union { int4 v; uint16_t u[8]; } A0, A1, B0, B1;
        A0.v = *(const int4*)src0; A1.v = *(const int4*)(src0 + 8);
        B0.v = *(const int4*)src1; B1.v = *(const int4*)(src1 + 8);
        #pragma unroll
        for (int jj = 0; jj < 16; jj++) {
            int hwl = seg * 16 + jj;
            uint16_t va = (jj < 8) ? A0.u[jj] : A1.u[jj - 8];
            uint16_t vb = (jj < 8) ? B0.u[jj] : B1.u[jj - 8];
            uint32_t off = (uint32_t)(hwl * 128 + ((cc ^ (hwl & 7)) << 4) + cbw);
            *(uint32_t*)(smem + 32768 + off) = (uint32_t)va | ((uint32_t)vb << 16);
        }
    }
    __syncthreads();

    float c[2][8][4];
    #pragma unroll
    for (int i = 0; i < 2; i++)
        #pragma unroll
        for (int j = 0; j < 8; j++)
            { c[i][j][0]=0.f; c[i][j][1]=0.f; c[i][j][2]=0.f; c[i][j][3]=0.f; }
    mma_tile_fin(sb, 0, 32768, mr0, n0, lane, c);

    int g = lane >> 2, tg = lane & 3;
    // epilogue (a): y fp16
    #pragma unroll
    for (int mi = 0; mi < 2; mi++) {
        int r0 = mr0 + mi * 16 + g;
        float bv0 = bias[r0], bv1 = bias[r0 + 8];
        #pragma unroll
        for (int ni = 0; ni < 8; ni++) {
            int col = n0 + ni * 8 + tg * 2;
            __half2 v0 = __floats2half2_rn(c[mi][ni][0] + bv0, c[mi][ni][1] + bv0);
            __half2 v1 = __floats2half2_rn(c[mi][ni][2] + bv1, c[mi][ni][3] + bv1);
            *(__half2*)(sc_y + (unsigned)(b * CO + r0) * HWD + hw0 + col) = v0;
            *(__half2*)(sc_y + (unsigned)(b * CO + r0 + 8) * HWD + hw0 + col) = v1;
        }
    }
    __syncthreads();
    // epilogue (b): stage hi-only transposed [hw][128c], row stride TSTR u16 (272B aligned)
    {
        uint16_t* sh = (uint16_t*)smem;
        #pragma unroll
        for (int mi = 0; mi < 2; mi++) {
            int r0 = mr0 + mi * 16 + g;
            float bv0 = bias[r0], bv1 = bias[r0 + 8];
            #pragma unroll
            for (int ni = 0; ni < 8; ni++) {
                int col = n0 + ni * 8 + tg * 2;
                float vals[4] = {c[mi][ni][0] + bv0, c[mi][ni][1] + bv0,
                                 c[mi][ni][2] + bv1, c[mi][ni][3] + bv1};
                int rows[4] = {r0, r0, r0 + 8, r0 + 8};
                int cols[4] = {col, col + 1, col, col + 1};
                #pragma unroll
                for (int e = 0; e < 4; e++)
                    sh[cols[e] * TSTR + rows[e]] = __half_as_ushort(__float2half_rn(vals[e]));
            }
        }
    }
    __syncthreads();
    // write out to TB planes 1..4 (hi only)
    {
        int qq = tid & 1, hb = tid >> 1;   // hb = hwl 0..127
        int hw = hw0 + hb;
        int h = hw / WW, wv = hw % WW;
        int p = 1 + ((h & 1) << 1) + (wv & 1);
        int l = (h >> 1) * WO + (wv >> 1);
        int4* dst = (int4*)(sc_TBh + (unsigned)((b * 5 + p) * LL + l) * 128 + qq * 64);
        const int4* src = (const int4*)((char*)smem + hb * (TSTR * 2) + qq * 128);
        #pragma unroll
        for (int jj = 0; jj < 8; jj++) dst[jj] = src[jj];
    }
}

// ---------------- fused BN + GELU + dwconv7 stride2 (fp16 y in) ----------------
__global__ void __launch_bounds__(256) actggm_kernel(const float* __restrict__ w,
                                                     const float* __restrict__ bias) {
    __shared__ float a[38 * 38];
    __shared__ float wk[49];
    int t = blockIdx.x, c = blockIdx.y, b = blockIdx.z;
    int ty = t / 7, tx = t % 7;
    int ho0 = ty * 16, wo0 = tx * 16;
    if (threadIdx.x < 49) wk[threadIdx.x] = w[c * 49 + threadIdx.x];
    const __half* y = sc_y + (unsigned)(b * CO + c) * HWD;
    float bs = sc_bnscale[c], bh = sc_bnshift[c];
    for (int ii = threadIdx.x; ii < 38 * 38; ii += 256) {
        int r = ii / 38, col = ii % 38;
        int ih = 2 * ho0 - 3 + r, iw = 2 * wo0 - 3 + col;
        float v = 0.f;
        if (ih >= 0 && ih < HH && iw >= 0 && iw < WW) {
            v = __half2float(y[(unsigned)ih * WW + iw]) * bs + bh;
            v = 0.5f * v * (1.f + erff(v * 0.7071067811865476f));
        }
        a[ii] = v;
    }
    __syncthreads();
    int oy = threadIdx.x / 16, ox = threadIdx.x % 16;
    float acc = bias[c];
    #pragma unroll
    for (int i = 0; i < 7; i++)
        #pragma unroll
        for (int j = 0; j < 7; j++)
            acc += a[(2 * oy + i) * 38 + (2 * ox + j)] * wk[i * 7 + j];
    sc_g[(unsigned)(b * CO + c) * LL + (unsigned)(ho0 + oy) * WO + wo0 + ox] = acc;
}

// ---------------- g -> TB plane 0 (hi only) ----------------
__global__ void __launch_bounds__(256) buildT0_kernel() {
    extern __shared__ __align__(16) char smem[];   // 128 * 272 = 34816
    int lt = blockIdx.x, b = blockIdx.y;
    int tid = threadIdx.x;
    uint16_t* sh = (uint16_t*)smem;
    {
        int c = tid >> 1, seg = tid & 1;
        const float* gsrc = sc_g + (unsigned)(b * CO + c) * LL + lt * 128 + seg * 64;
        #pragma unroll 8
        for (int j = 0; j < 64; j++) {
            int l = seg * 64 + j;
            sh[l * TSTR + c] = __half_as_ushort(__float2half_rn(gsrc[j]));
        }
    }
    __syncthreads();
    int qq = tid & 1, hb2 = tid >> 1;
    int l = lt * 128 + hb2;
    int4* dst = (int4*)(sc_TBh + (unsigned)((b * 5 + 0) * LL + l) * 128 + qq * 64);
    const int4* src = (const int4*)((char*)smem + hb2 * (TSTR * 2) + qq * 128);
    #pragma unroll
    for (int jj = 0; jj < 8; jj++) dst[jj] = src[jj];
}

// ---------------- fused score kernel (hi-only, q0 in regs, double-buffered) ----------------
// smem: W 0..32K, B buf0 32K..64K, buf1 64K..96K, red at 98304. total 99328.
__global__ void __launch_bounds__(256) score_kernel(const float* __restrict__ qkv_b) {
    extern __shared__ __align__(16) char smem[];
    int tid = threadIdx.x, lane = tid & 31, w = tid >> 5;
    int nt = blockIdx.x, b = blockIdx.z;
    int l0 = nt * 128;
    uint32_t sb = smem_u32(smem);
    int mr0 = (w & 3) * 32, n0 = (w >> 2) * 64;
    int g = lane >> 2, tg = lane & 3;
    float* red = (float*)(smem + 98304);

    for (int ch = 0; ch < 2; ch++)
        copy_chunk_h(smem, ch * 16384, sc_qA + ch * 64, 128, tid);
    for (int ch = 0; ch < 2; ch++)
        copy_chunk_h_async(sb, 32768 + ch * 16384,
                           sc_TBh + (unsigned)((b * 5 + 0) * LL + l0) * 128 + ch * 64, 128, tid);
    CPA_COMMIT();
    for (int ch = 0; ch < 2; ch++)
        copy_chunk_h_async(sb, 65536 + ch * 16384,
                           sc_TBh + (unsigned)((b * 5 + 1) * LL + l0) * 128 + ch * 64, 128, tid);
    CPA_COMMIT();
    CPA_WAIT1();
    __syncthreads();

    float c[2][8][4];
    #pragma unroll
    for (int i = 0; i < 2; i++)
        #pragma unroll
        for (int j = 0; j < 8; j++)
            { c[i][j][0]=0.f; c[i][j][1]=0.f; c[i][j][2]=0.f; c[i][j][3]=0.f; }
    mma_tile_h(sb, 0, 32768, 2, mr0, n0, lane, c);

    float qreg[2][8][4];
    #pragma unroll
    for (int mi = 0; mi < 2; mi++) {
        int r0 = mr0 + mi * 16 + g;
        float bq0 = qkv_b[r0], bq1 = qkv_b[r0 + 8];
        #pragma unroll
        for (int ni = 0; ni < 8; ni++) {
            qreg[mi][ni][0] = c[mi][ni][0] + bq0;
            qreg[mi][ni][1] = c[mi][ni][1] + bq0;
            qreg[mi][ni][2] = c[mi][ni][2] + bq1;
            qreg[mi][ni][3] = c[mi][ni][3] + bq1;
        }
    }
    __syncthreads();
    for (int ch = 0; ch < 2; ch++)
        copy_chunk_h(smem, ch * 16384, sc_kA + ch * 64, 128, tid);
    __syncthreads();

    for (int p = 0; p < 5; p++) {
        int buf = p & 1;
        uint32_t bOff = 32768 + (uint32_t)buf * 32768;
        if (p >= 1) {
            // Last iteration: the plane-4 group is the ONLY pending group, so
            // wait_group 1 would NOT wait for it (race found in R11 post-mortem).
            if (p == 4) CPA_WAIT0(); else CPA_WAIT1();
            __syncthreads();
        }
        #pragma unroll
        for (int i = 0; i < 2; i++)
            #pragma unroll
            for (int j = 0; j < 8; j++)
                { c[i][j][0]=0.f; c[i][j][1]=0.f; c[i][j][2]=0.f; c[i][j][3]=0.f; }
        mma_tile_h(sb, 0, bOff, 2, mr0, n0, lane, c);

        float part[4] = {0.f, 0.f, 0.f, 0.f};
        #pragma unroll
        for (int mi = 0; mi < 2; mi++) {
            int r0 = mr0 + mi * 16 + g;
            float bk0 = qkv_b[128 + r0], bk1 = qkv_b[128 + r0 + 8];
            #pragma unroll
            for (int ni = 0; ni < 8; ni++) {
                part[mi*2]   += (c[mi][ni][0] + bk0) * qreg[mi][ni][0]
                              + (c[mi][ni][1] + bk0) * qreg[mi][ni][1];
                part[mi*2+1] += (c[mi][ni][2] + bk1) * qreg[mi][ni][2]
                              + (c[mi][ni][3] + bk1) * qreg[mi][ni][3];
            }
        }
        #pragma unroll
        for (int e = 0; e < 4; e++) {
            part[e] += __shfl_xor_sync(0xffffffffu, part[e], 1);
            part[e] += __shfl_xor_sync(0xffffffffu, part[e], 2);
        }
        if (tg == 0) {
            red[w * 32 + 0 * 16 + g]     = part[0];
            red[w * 32 + 0 * 16 + g + 8] = part[1];
            red[w * 32 + 1 * 16 + g]     = part[2];
            red[w * 32 + 1 * 16 + g + 8] = part[3];
        }
        __syncthreads();
        if (tid < 128) {
            int cch = tid, wa = cch >> 5, loc = cch & 31;
            sc_Spart[((b * 5 + p) * NT_L + nt) * 128 + cch] =
                red[wa * 32 + loc] + red[(wa + 4) * 32 + loc];
        }
        if (p + 2 <= 4) {
            for (int ch = 0; ch < 2; ch++)
                copy_chunk_h_async(sb, bOff + ch * 16384,
                                   sc_TBh + (unsigned)((b * 5 + p + 2) * LL + l0) * 128 + ch * 64, 128, tid);
            CPA_COMMIT();
        }
    }
}

// ---------------- softmax over 5 tokens ----------------
__global__ void softmax_kernel() {
    int b = blockIdx.x, cc = threadIdx.x;
    float S[5];
    const float scale = 0.08838834764831845f;
    #pragma unroll
    for (int p = 0; p < 5; p++) {
        float s = 0.f;
        const float* sp = sc_Spart + ((b * 5 + p) * NT_L) * 128 + cc;
        for (int blk = 0; blk < NT_L; blk++) s += sp[blk * 128];
        S[p] = s * scale;
    }
    float m = -1e30f;
    #pragma unroll
    for (int p = 0; p < 5; p++) m = fmaxf(m, S[p]);
    float e[5], sum = 0.f;
    #pragma unroll
    for (int p = 0; p < 5; p++) { e[p] = expf(S[p] - m); sum += e[p]; }
    float inv = 1.f / sum;
    #pragma unroll
    for (int p = 0; p < 5; p++) sc_attn[(b * 5 + p) * 128 + cc] = e[p] * inv;
}

// ---------------- effective folded weight ----------------
__global__ void feff_kernel(const float* __restrict__ proj_w, const float* __restrict__ qkv_w) {
    int idx = blockIdx.x * 256 + threadIdx.x;
    int j = idx % 640;
    int o = (idx / 640) % CO;
    int b = idx / (640 * CO);
    int pp = j >> 7, cpx = j & 127;
    float acc = 0.f;
    for (int cc = 0; cc < CO; cc++)
        acc += proj_w[o * CO + cc] * sc_attn[(b * 5 + pp) * 128 + cc] * qkv_w[(256 + cc) * CO + cpx];
    __half h, l; split_h(acc, h, l);
    sc_fAh[idx] = h; sc_fAl[idx] = l;
}

// ---------------- final GEMM: out = Feff_b @ T_b + beff (2-term, double-buffered) ----------------
// smem: buf{0,1} x (A pair 32KB | B hi 16KB) = 98304
__global__ void __launch_bounds__(256) gemm_fin(float* __restrict__ out) {
    extern __shared__ __align__(16) char smem[];
    int tid = threadIdx.x, lane = tid & 31, w = tid >> 5;
    int nt = blockIdx.x, b = blockIdx.z;
    int l0 = nt * 128;
    uint32_t sb = smem_u32(smem);
    int mr0 = (w & 3) * 32, n0 = (w >> 2) * 64;

    const __half* Ah = sc_fAh + (unsigned)b * 128 * 640;
    const __half* Al = sc_fAl + (unsigned)b * 128 * 640;

    auto issue = [&](int kc, int buf) {
        int plane = kc >> 1, half = kc & 1;
        uint32_t base = (uint32_t)buf * 49152;
        copy_chunk_async(sb, base, Ah + kc * 64, Al + kc * 64, 640, tid);
        copy_chunk_h_async(sb, base + 32768,
                           sc_TBh + (unsigned)((b * 5 + plane) * LL + l0) * 128 + half * 64, 128, tid);
        CPA_COMMIT();
    };
    issue(0, 0);
    issue(1, 1);

    float c[2][8][4];
    #pragma unroll
    for (int i = 0; i < 2; i++)
        #pragma unroll
        for (int j = 0; j < 8; j++)
            { c[i][j][0]=0.f; c[i][j][1]=0.f; c[i][j][2]=0.f; c[i][j][3]=0.f; }

    for (int kc = 0; kc < 10; kc++) {
        int buf = kc & 1;
        // Last iteration: its group is the only one pending -> must wait_group 0
        // (same under-synchronization race as score_kernel; fixed in R12).
        if (kc == 9) CPA_WAIT0(); else CPA_WAIT1();
        __syncthreads();
        mma_tile_fin(sb, (uint32_t)buf * 49152, (uint32_t)buf * 49152 + 32768, mr0, n0, lane, c);
        __syncthreads();
        if (kc + 2 < 10) issue(kc + 2, buf);
    }
    int g = lane >> 2, tg = lane & 3;
    #pragma unroll
    for (int mi = 0; mi < 2; mi++) {
        int r0 = mr0 + mi * 16 + g;
        float bv0 = sc_beff[r0], bv1 = sc_beff[r0 + 8];
        #pragma unroll
        for (int ni = 0; ni < 8; ni++) {
            int col = n0 + ni * 8 + tg * 2;
            float2 v0 = make_float2(c[mi][ni][0] + bv0, c[mi][ni][1] + bv0);
            float2 v1 = make_float2(c[mi][ni][2] + bv1, c[mi][ni][3] + bv1);
            *(float2*)(out + (unsigned)(b * CO + r0) * LL + l0 + col) = v0;
            *(float2*)(out + (unsigned)(b * CO + r0 + 8) * LL + l0 + col) = v1;
        }
    }
}

// ---------------- launch ----------------
extern "C" void kernel_launch(void* const* d_in, const int* in_sizes, int n_in,
                              void* d_out, int out_size) {
    const float* x      = (const float*)d_in[0];
    const float* dww[4] = {(const float*)d_in[1], (const float*)d_in[3],
                           (const float*)d_in[5], (const float*)d_in[7]};
    const float* dwb[4] = {(const float*)d_in[2], (const float*)d_in[4],
                           (const float*)d_in[6], (const float*)d_in[8]};
    const float* csc_w  = (const float*)d_in[9];
    const float* csc_b  = (const float*)d_in[10];
    const float* bn_g   = (const float*)d_in[11];
    const float* bn_b   = (const float*)d_in[12];
    const float* bn_m   = (const float*)d_in[13];
    const float* bn_v   = (const float*)d_in[14];
    const float* ggm_w  = (const float*)d_in[15];
    const float* ggm_b  = (const float*)d_in[16];
    const float* qkv_w  = (const float*)d_in[17];
    const float* qkv_b  = (const float*)d_in[18];
    const float* proj_w = (const float*)d_in[19];
    const float* proj_b = (const float*)d_in[20];
    float* out = (float*)d_out;

    __half *p_cAh, *p_cAl, *p_qA, *p_kA;
    cudaGetSymbolAddress((void**)&p_cAh, sc_cAh);
    cudaGetSymbolAddress((void**)&p_cAl, sc_cAl);
    cudaGetSymbolAddress((void**)&p_qA,  sc_qA);
    cudaGetSymbolAddress((void**)&p_kA,  sc_kA);

    cudaFuncSetAttribute(gemm_csc, cudaFuncAttributeMaxDynamicSharedMemorySize, 49152);
    cudaFuncSetAttribute(buildT0_kernel, cudaFuncAttributeMaxDynamicSharedMemorySize, 35840);
    cudaFuncSetAttribute(score_kernel, cudaFuncAttributeMaxDynamicSharedMemorySize, 99328);
    cudaFuncSetAttribute(gemm_fin, cudaFuncAttributeMaxDynamicSharedMemorySize, 98304);

    precompute_kernel<<<1, 128>>>(bn_g, bn_b, bn_m, bn_v, proj_w, qkv_b, proj_b);

    dim3 gdw(14, 16, BB);     // 3136 (row-pair, col-group) positions / 224 threads
    dw_kernel<3><<<gdw, 224>>>(x, dww[0], dwb[0], 0);
    dw_kernel<5><<<gdw, 224>>>(x, dww[1], dwb[1], 1);
    dw_kernel<7><<<gdw, 224>>>(x, dww[2], dwb[2], 2);
    dw_kernel<9><<<gdw, 224>>>(x, dww[3], dwb[3], 3);

    packW_pair<<<(128*64 + 255)/256, 256>>>(csc_w, 128*64, p_cAh, p_cAl);
    packW_hi<<<(128*128 + 255)/256, 256>>>(qkv_w, 128*128, p_qA);
    packW_hi<<<(128*128 + 255)/256, 256>>>(qkv_w + 128*128, 128*128, p_kA);

    gemm_csc<<<dim3(NT_S, 1, BB), 256, 49152>>>(csc_b);

    actggm_kernel<<<dim3(49, CO, BB), 256>>>(ggm_w, ggm_b);

    buildT0_kernel<<<dim3(NT_L, BB), 256, 35840>>>();

    score_kernel<<<dim3(NT_L, 1, BB), 256, 99328>>>(qkv_b);

    softmax_kernel<<<BB, 128>>>();

    feff_kernel<<<(BB * CO * 640) / 256, 256>>>(proj_w, qkv_w);

    gemm_fin<<<dim3(NT_L, 1, BB), 256, 98304>>>(out);
}

// round 14
// speedup vs baseline: 3.3437x; 1.0722x over previous
#include <cuda_runtime.h>
#include <cuda_fp16.h>
#include <stdint.h>
#include <math.h>

#define BB  8
#define CIN 64
#define CO  128
#define HH  224
#define WW  224
#define HO  112
#define WO  112
#define LL  (HO*WO)     // 12544
#define HWD (HH*WW)     // 50176
#define NT_S (HWD/128)  // 392
#define NT_L (LL/128)   // 98

// ---------------- static device scratch ----------------
__device__ __align__(16) __half sc_sh[(size_t)BB*CIN*HWD];   // dw output fp16 [b][c][hw]
__device__ __align__(16) __half sc_y[(size_t)BB*CO*HWD];     // csc output fp16 (guide path)
__device__ __align__(16) __half sc_g[(size_t)BB*CO*LL];      // guide tokens fp16 [b][c][l]
__device__ __align__(16) float sc_Spart[BB*5*NT_L*128];
__device__ float sc_attn[BB*5*128];
__device__ float sc_beff[CO], sc_bnscale[CO], sc_bnshift[CO];
// token planes [b][p][l][c], fp16 HI ONLY
__device__ __align__(16) __half sc_TBh[(size_t)BB*5*LL*128];
__device__ __align__(16) __half sc_cAh[128*64],  sc_cAl[128*64];
__device__ __align__(16) __half sc_qA[128*128];   // Wq hi only
__device__ __align__(16) __half sc_kA[128*128];   // Wk hi only
__device__ __align__(16) __half sc_fAh[(size_t)BB*128*640];   // Feff hi only (R13)

// staging row stride for transposed epilogue: 136 u16 = 272 bytes = 17*16 (int4-aligned)
#define TSTR 136

// ---------------- helpers ----------------
__device__ __forceinline__ uint32_t smem_u32(const void* p) {
    uint32_t a;
    asm("{ .reg .u64 t; cvta.to.shared.u64 t, %1; cvt.u32.u64 %0, t; }" : "=r"(a) : "l"(p));
    return a;
}
__device__ __forceinline__ void split_h(float v, __half& h, __half& l) {
    h = __float2half_rn(v);
    l = __float2half_rn(v - __half2float(h));
}

#define LDSM4(r, a)                                                           \
    asm volatile("ldmatrix.sync.aligned.m8n8.x4.shared.b16 {%0,%1,%2,%3}, [%4];" \
        : "=r"((r)[0]), "=r"((r)[1]), "=r"((r)[2]), "=r"((r)[3]) : "r"(a))

__device__ __forceinline__ void mma16816(float* c, const uint32_t* a, uint32_t b0, uint32_t b1) {
    asm volatile(
        "mma.sync.aligned.m16n8k16.row.col.f32.f16.f16.f32 "
        "{%0,%1,%2,%3}, {%4,%5,%6,%7}, {%8,%9}, {%0,%1,%2,%3};"
        : "+f"(c[0]), "+f"(c[1]), "+f"(c[2]), "+f"(c[3])
        : "r"(a[0]), "r"(a[1]), "r"(a[2]), "r"(a[3]), "r"(b0), "r"(b1));
}

__device__ __forceinline__ void cpa16(uint32_t saddr, const void* g) {
    asm volatile("cp.async.cg.shared.global [%0], [%1], 16;" :: "r"(saddr), "l"(g));
}
#define CPA_COMMIT() asm volatile("cp.async.commit_group;" ::: "memory")
#define CPA_WAIT1()  asm volatile("cp.async.wait_group 1;" ::: "memory")
#define CPA_WAIT0()  asm volatile("cp.async.wait_group 0;" ::: "memory")

// pair chunk: hi at off, lo at off+16384 (32KB)
__device__ __forceinline__ void copy_chunk_async(uint32_t sb, uint32_t off,
                                                 const __half* gh, const __half* gl,
                                                 int ld, int tid) {
    for (int i = tid; i < 1024; i += 256) {
        int r = i >> 3, cc = i & 7;
        uint32_t d = (uint32_t)(r * 128 + ((cc ^ (r & 7)) << 4));
        cpa16(sb + off + d,         gh + r * ld + cc * 8);
        cpa16(sb + off + 16384 + d, gl + r * ld + cc * 8);
    }
}
// hi-only chunk (16KB)
__device__ __forceinline__ void copy_chunk_h(char* smem, uint32_t off,
                                             const __half* gh, int ld, int tid) {
    for (int i = tid; i < 1024; i += 256) {
        int r = i >> 3, cc = i & 7;
        uint32_t d = (uint32_t)(r * 128 + ((cc ^ (r & 7)) << 4));
        *(int4*)(smem + off + d) = *(const int4*)(gh + r * ld + cc * 8);
    }
}
__device__ __forceinline__ void copy_chunk_h_async(uint32_t sb, uint32_t off,
                                                   const __half* gh, int ld, int tid) {
    for (int i = tid; i < 1024; i += 256) {
        int r = i >> 3, cc = i & 7;
        uint32_t d = (uint32_t)(r * 128 + ((cc ^ (r & 7)) << 4));
        cpa16(sb + off + d, gh + r * ld + cc * 8);
    }
}

// 1-term hi-only gemm, nch 16KB chunks (score + fin paths)
__device__ __forceinline__ void mma_tile_h(uint32_t sb, uint32_t aOff, uint32_t bOff, int nch,
                                           int mr0, int n0, int lane, float c[2][8][4]) {
    int ar = lane & 15, ac = lane >> 4;
    int br = (lane & 7) + ((lane >> 4) << 3), bc = (lane >> 3) & 1;
    for (int ch = 0; ch < nch; ch++) {
        #pragma unroll
        for (int kk = 0; kk < 4; kk++) {
            uint32_t aH[2][4], bH[4][4];
            #pragma unroll
            for (int mi = 0; mi < 2; mi++) {
                int r = mr0 + mi * 16 + ar;
                uint32_t addr = sb + aOff + ch * 16384 + r * 128 + (((kk * 2 + ac) ^ (r & 7)) << 4);
                LDSM4(aH[mi], addr);
            }
            #pragma unroll
            for (int np = 0; np < 4; np++) {
                int r = n0 + np * 16 + br;
                uint32_t addr = sb + bOff + ch * 16384 + r * 128 + (((kk * 2 + bc) ^ (r & 7)) << 4);
                LDSM4(bH[np], addr);
            }
            #pragma unroll
            for (int mi = 0; mi < 2; mi++)
                #pragma unroll
                for (int np = 0; np < 4; np++) {
                    mma16816(c[mi][np*2],     aH[mi], bH[np][0], bH[np][1]);
                    mma16816(c[mi][np*2 + 1], aH[mi], bH[np][2], bH[np][3]);
                }
        }
    }
}

// 2-term gemm: A pair (hi at aOff, lo at +16384), B hi-only at bOff (csc path)
__device__ __forceinline__ void mma_tile_fin(uint32_t sb, uint32_t aOff, uint32_t bOff,
                                             int mr0, int n0, int lane, float c[2][8][4]) {
    int ar = lane & 15, ac = lane >> 4;
    int br = (lane & 7) + ((lane >> 4) << 3), bc = (lane >> 3) & 1;
    #pragma unroll
    for (int kk = 0; kk < 4; kk++) {
        uint32_t aH[2][4], aL[2][4], bH[4][4];
        #pragma unroll
        for (int mi = 0; mi < 2; mi++) {
            int r = mr0 + mi * 16 + ar;
            uint32_t addr = sb + aOff + r * 128 + (((kk * 2 + ac) ^ (r & 7)) << 4);
            LDSM4(aH[mi], addr);
            LDSM4(aL[mi], addr + 16384);
        }
        #pragma unroll
        for (int np = 0; np < 4; np++) {
            int r = n0 + np * 16 + br;
            uint32_t addr = sb + bOff + r * 128 + (((kk * 2 + bc) ^ (r & 7)) << 4);
            LDSM4(bH[np], addr);
        }
        #pragma unroll
        for (int mi = 0; mi < 2; mi++)
            #pragma unroll
            for (int np = 0; np < 4; np++) {
                mma16816(c[mi][np*2],     aH[mi], bH[np][0], bH[np][1]);
                mma16816(c[mi][np*2],     aL[mi], bH[np][0], bH[np][1]);
                mma16816(c[mi][np*2 + 1], aH[mi], bH[np][2], bH[np][3]);
                mma16816(c[mi][np*2 + 1], aL[mi], bH[np][2], bH[np][3]);
            }
    }
}

// ---------------- depthwise conv + channel shuffle: 2x8 outputs/thread, fp16 out ----------------
template<int KSZ>
__global__ void __launch_bounds__(224) dw_kernel(const float* __restrict__ x,
                                                 const float* __restrict__ w,
                                                 const float* __restrict__ bias, int head) {
    const int pad = KSZ / 2;
    __shared__ float wks[KSZ * KSZ];
    int tid = threadIdx.x;
    int j = blockIdx.y, b = blockIdx.z;
    if (tid < KSZ * KSZ) wks[tid] = w[j * KSZ * KSZ + tid];
    __syncthreads();
    int q = blockIdx.x * 224 + tid;
    int h2 = q / 28, wg = q % 28;
    int h0 = 2 * h2;
    int w0 = wg * 8;
    const float* xin = x + (unsigned)(b * CIN + head * 16 + j) * HWD;
    float bv = bias[j];
    float a0[8], a1[8];
    #pragma unroll
    for (int o = 0; o < 8; o++) { a0[o] = bv; a1[o] = bv; }
    const float4 z4 = make_float4(0.f, 0.f, 0.f, 0.f);
    #pragma unroll
    for (int t = 0; t <= KSZ; t++) {
        int ih = h0 - pad + t;
        if (ih < 0 || ih >= HH) continue;
        const float4* row = (const float4*)(xin + (unsigned)ih * WW);
        int i0 = wg * 2 - 1;
        float4 v0 = (i0 >= 0) ? row[i0] : z4;
        float4 v1 = row[i0 + 1];
        float4 v2 = row[i0 + 2];
        float4 v3 = (i0 + 3 < 56) ? row[i0 + 3] : z4;
        float win[16];
        win[0]=v0.x; win[1]=v0.y; win[2]=v0.z; win[3]=v0.w;
        win[4]=v1.x; win[5]=v1.y; win[6]=v1.z; win[7]=v1.w;
        win[8]=v2.x; win[9]=v2.y; win[10]=v2.z; win[11]=v2.w;
        win[12]=v3.x; win[13]=v3.y; win[14]=v3.z; win[15]=v3.w;
        if (t < KSZ) {
            #pragma unroll
            for (int kx = 0; kx < KSZ; kx++) {
                float wv = wks[t * KSZ + kx];
                #pragma unroll
                for (int o = 0; o < 8; o++)
                    a0[o] += win[o + kx + 4 - pad] * wv;
            }
        }
        if (t >= 1) {
            #pragma unroll
            for (int kx = 0; kx < KSZ; kx++) {
                float wv = wks[(t - 1) * KSZ + kx];
                #pragma unroll
                for (int o = 0; o < 8; o++)
                    a1[o] += win[o + kx + 4 - pad] * wv;
            }
        }
    }
    __half* dst = sc_sh + (unsigned)(b * CIN + j * 4 + head) * HWD + (unsigned)h0 * WW + w0;
    __half hb[8];
    #pragma unroll
    for (int o = 0; o < 8; o++) hb[o] = __float2half_rn(a0[o]);
    *(int4*)dst = *(int4*)hb;
    #pragma unroll
    for (int o = 0; o < 8; o++) hb[o] = __float2half_rn(a1[o]);
    *(int4*)(dst + WW) = *(int4*)hb;
}

// ---------------- precompute ----------------
__global__ void precompute_kernel(const float* g, const float* be, const float* mn,
                                  const float* vr, const float* proj_w,
                                  const float* qkv_b, const float* proj_b) {
    int c = threadIdx.x;
    float sc = g[c] * rsqrtf(vr[c] + 1e-5f);
    sc_bnscale[c] = sc;
    sc_bnshift[c] = be[c] - mn[c] * sc;
    float acc = proj_b[c];
    for (int k = 0; k < CO; k++) acc += proj_w[c * CO + k] * qkv_b[256 + k];
    sc_beff[c] = acc;
}

// ---------------- pack weights ----------------
__global__ void packW_pair(const float* __restrict__ W, int n,
                           __half* __restrict__ Hd, __half* __restrict__ Ld) {
    int i = blockIdx.x * 256 + threadIdx.x;
    if (i >= n) return;
    __half h, l; split_h(W[i], h, l);
    Hd[i] = h; Ld[i] = l;
}
__global__ void packW_hi(const float* __restrict__ W, int n, __half* __restrict__ Hd) {
    int i = blockIdx.x * 256 + threadIdx.x;
    if (i >= n) return;
    Hd[i] = __float2half_rn(W[i]);
}

// ---------------- csc GEMM: A pair (async) x B(s fp16, exact) 2-term + TB-hi epilogue ----------------
// smem: A pair 0..32K, B hi 32K..48K. epilogue staging reuses base. dyn smem 49152.
__global__ void __launch_bounds__(256) gemm_csc(const float* __restrict__ bias) {
    extern __shared__ __align__(16) char smem[];
    int tid = threadIdx.x, lane = tid & 31, w = tid >> 5;
    int nt = blockIdx.x, b = blockIdx.z;
    int hw0 = nt * 128;
    uint32_t sb = smem_u32(smem);
    int mr0 = (w & 3) * 32, n0 = (w >> 2) * 64;

    // A async (overlaps with B prep below)
    copy_chunk_async(sb, 0, sc_cAh, sc_cAl, 64, tid);
    CPA_COMMIT();
    // B: repack s fp16 [c][hw] -> smem [hw][64c] swizzled (hi plane only; exact)
    {
        int r = tid & 31;          // channel pair
        int seg = tid >> 5;
        int c0 = 2 * r;
        int cc = c0 >> 3, cbw = (c0 & 7) * 2;
        const __half* src0 = sc_sh + (unsigned)(b * CIN + c0) * HWD + hw0 + seg * 16;
        const __half* src1 = src0 + HWD;
        union { int4 v; uint16_t u[8]; } A0, A1, B0, B1;
        A0.v = *(const int4*)src0; A1.v = *(const int4*)(src0 + 8);
        B0.v = *(const int4*)src1; B1.v = *(const int4*)(src1 + 8);
        #pragma unroll
        for (int jj = 0; jj < 16; jj++) {
            int hwl = seg * 16 + jj;
            uint16_t va = (jj < 8) ? A0.u[jj] : A1.u[jj - 8];
            uint16_t vb = (jj < 8) ? B0.u[jj] : B1.u[jj - 8];
            uint32_t off = (uint32_t)(hwl * 128 + ((cc ^ (hwl & 7)) << 4) + cbw);
            *(uint32_t*)(smem + 32768 + off) = (uint32_t)va | ((uint32_t)vb << 16);
        }
    }
    CPA_WAIT0();
    __syncthreads();

    float c[2][8][4];
    #pragma unroll
    for (int i = 0; i < 2; i++)
        #pragma unroll
        for (int j = 0; j < 8; j++)
            { c[i][j][0]=0.f; c[i][j][1]=0.f; c[i][j][2]=0.f; c[i][j][3]=0.f; }
    mma_tile_fin(sb, 0, 32768, mr0, n0, lane, c);

    int g = lane >> 2, tg = lane & 3;
    // epilogue (a): y fp16
    #pragma unroll
    for (int mi = 0; mi < 2; mi++) {
        int r0 = mr0 + mi * 16 + g;
        float bv0 = bias[r0], bv1 = bias[r0 + 8];
        #pragma unroll
        for (int ni = 0; ni < 8; ni++) {
            int col = n0 + ni * 8 + tg * 2;
            __half2 v0 = __floats2half2_rn(c[mi][ni][0] + bv0, c[mi][ni][1] + bv0);
            __half2 v1 = __floats2half2_rn(c[mi][ni][2] + bv1, c[mi][ni][3] + bv1);
            *(__half2*)(sc_y + (unsigned)(b * CO + r0) * HWD + hw0 + col) = v0;
            *(__half2*)(sc_y + (unsigned)(b * CO + r0 + 8) * HWD + hw0 + col) = v1;
        }
    }
    __syncthreads();
    // epilogue (b): stage hi-only transposed [hw][128c], row stride TSTR u16 (272B aligned)
    {
        uint16_t* sh = (uint16_t*)smem;
        #pragma unroll
        for (int mi = 0; mi < 2; mi++) {
            int r0 = mr0 + mi * 16 + g;
            float bv0 = bias[r0], bv1 = bias[r0 + 8];
            #pragma unroll
            for (int ni = 0; ni < 8; ni++) {
                int col = n0 + ni * 8 + tg * 2;
                float vals[4] = {c[mi][ni][0] + bv0, c[mi][ni][1] + bv0,
                                 c[mi][ni][2] + bv1, c[mi][ni][3] + bv1};
                int rows[4] = {r0, r0, r0 + 8, r0 + 8};
                int cols[4] = {col, col + 1, col, col + 1};
                #pragma unroll
                for (int e = 0; e < 4; e++)
                    sh[cols[e] * TSTR + rows[e]] = __half_as_ushort(__float2half_rn(vals[e]));
            }
        }
    }
    __syncthreads();
    // write out to TB planes 1..4 (hi only)
    {
        int qq = tid & 1, hb = tid >> 1;   // hb = hwl 0..127
        int hw = hw0 + hb;
        int h = hw / WW, wv = hw % WW;
        int p = 1 + ((h & 1) << 1) + (wv & 1);
        int l = (h >> 1) * WO + (wv >> 1);
        int4* dst = (int4*)(sc_TBh + (unsigned)((b * 5 + p) * LL + l) * 128 + qq * 64);
        const int4* src = (const int4*)((char*)smem + hb * (TSTR * 2) + qq * 128);
        #pragma unroll
        for (int jj = 0; jj < 8; jj++) dst[jj] = src[jj];
    }
}

// ---------------- fused BN + GELU + dwconv7 stride2 (fp16 y in, fp16 g out) ----------------
__global__ void __launch_bounds__(256) actggm_kernel(const float* __restrict__ w,
                                                     const float* __restrict__ bias) {
    __shared__ float a[38 * 38];
    __shared__ float wk[49];
    int t = blockIdx.x, c = blockIdx.y, b = blockIdx.z;
    int ty = t / 7, tx = t % 7;
    int ho0 = ty * 16, wo0 = tx * 16;
    if (threadIdx.x < 49) wk[threadIdx.x] = w[c * 49 + threadIdx.x];
    const __half* y = sc_y + (unsigned)(b * CO + c) * HWD;
    float bs = sc_bnscale[c], bh = sc_bnshift[c];
    for (int ii = threadIdx.x; ii < 38 * 38; ii += 256) {
        int r = ii / 38, col = ii % 38;
        int ih = 2 * ho0 - 3 + r, iw = 2 * wo0 - 3 + col;
        float v = 0.f;
        if (ih >= 0 && ih < HH && iw >= 0 && iw < WW) {
            v = __half2float(y[(unsigned)ih * WW + iw]) * bs + bh;
            v = 0.5f * v * (1.f + erff(v * 0.7071067811865476f));
        }
        a[ii] = v;
    }
    __syncthreads();
    int oy = threadIdx.x / 16, ox = threadIdx.x % 16;
    float acc = bias[c];
    #pragma unroll
    for (int i = 0; i < 7; i++)
        #pragma unroll
        for (int j = 0; j < 7; j++)
            acc += a[(2 * oy + i) * 38 + (2 * ox + j)] * wk[i * 7 + j];
    sc_g[(unsigned)(b * CO + c) * LL + (unsigned)(ho0 + oy) * WO + wo0 + ox] = __float2half_rn(acc);
}

// ---------------- g (fp16) -> TB plane 0 (hi only) ----------------
__global__ void __launch_bounds__(256) buildT0_kernel() {
    extern __shared__ __align__(16) char smem[];   // 128 * 272 = 34816
    int lt = blockIdx.x, b = blockIdx.y;
    int tid = threadIdx.x;
    uint16_t* sh = (uint16_t*)smem;
    {
        int c = tid >> 1, seg = tid & 1;
        const __half* gsrc = sc_g + (unsigned)(b * CO + c) * LL + lt * 128 + seg * 64;
        #pragma unroll 8
        for (int j = 0; j < 64; j++) {
            int l = seg * 64 + j;
            sh[l * TSTR + c] = __half_as_ushort(gsrc[j]);
        }
    }
    __syncthreads();
    int qq = tid & 1, hb2 = tid >> 1;
    int l = lt * 128 + hb2;
    int4* dst = (int4*)(sc_TBh + (unsigned)((b * 5 + 0) * LL + l) * 128 + qq * 64);
    const int4* src = (const int4*)((char*)smem + hb2 * (TSTR * 2) + qq * 128);
    #pragma unroll
    for (int jj = 0; jj < 8; jj++) dst[jj] = src[jj];
}

// ---------------- fused score kernel (hi-only, q0 in regs, double-buffered) ----------------
// smem: W 0..32K, B buf0 32K..64K, buf1 64K..96K, red at 98304. total 99328.
__global__ void __launch_bounds__(256) score_kernel(const float* __restrict__ qkv_b) {
    extern __shared__ __align__(16) char smem[];
    int tid = threadIdx.x, lane = tid & 31, w = tid >> 5;
    int nt = blockIdx.x, b = blockIdx.z;
    int l0 = nt * 128;
    uint32_t sb = smem_u32(smem);
    int mr0 = (w & 3) * 32, n0 = (w >> 2) * 64;
    int g = lane >> 2, tg = lane & 3;
    float* red = (float*)(smem + 98304);

    for (int ch = 0; ch < 2; ch++)
        copy_chunk_h(smem, ch * 16384, sc_qA + ch * 64, 128, tid);
    for (int ch = 0; ch < 2; ch++)
        copy_chunk_h_async(sb, 32768 + ch * 16384,
                           sc_TBh + (unsigned)((b * 5 + 0) * LL + l0) * 128 + ch * 64, 128, tid);
    CPA_COMMIT();
    for (int ch = 0; ch < 2; ch++)
        copy_chunk_h_async(sb, 65536 + ch * 16384,
                           sc_TBh + (unsigned)((b * 5 + 1) * LL + l0) * 128 + ch * 64, 128, tid);
    CPA_COMMIT();
    CPA_WAIT1();
    __syncthreads();

    float c[2][8][4];
    #pragma unroll
    for (int i = 0; i < 2; i++)
        #pragma unroll
        for (int j = 0; j < 8; j++)
            { c[i][j][0]=0.f; c[i][j][1]=0.f; c[i][j][2]=0.f; c[i][j][3]=0.f; }
    mma_tile_h(sb, 0, 32768, 2, mr0, n0, lane, c);

    float qreg[2][8][4];
    #pragma unroll
    for (int mi = 0; mi < 2; mi++) {
        int r0 = mr0 + mi * 16 + g;
        float bq0 = qkv_b[r0], bq1 = qkv_b[r0 + 8];
        #pragma unroll
        for (int ni = 0; ni < 8; ni++) {
            qreg[mi][ni][0] = c[mi][ni][0] + bq0;
            qreg[mi][ni][1] = c[mi][ni][1] + bq0;
            qreg[mi][ni][2] = c[mi][ni][2] + bq1;
            qreg[mi][ni][3] = c[mi][ni][3] + bq1;
        }
    }
    __syncthreads();
    for (int ch = 0; ch < 2; ch++)
        copy_chunk_h(smem, ch * 16384, sc_kA + ch * 64, 128, tid);
    __syncthreads();

    for (int p = 0; p < 5; p++) {
        int buf = p & 1;
        uint32_t bOff = 32768 + (uint32_t)buf * 32768;
        if (p >= 1) {
            // p==4: its group is the ONLY pending one -> must wait_group 0 (R12 race fix)
            if (p == 4) CPA_WAIT0(); else CPA_WAIT1();
            __syncthreads();
        }
        #pragma unroll
        for (int i = 0; i < 2; i++)
            #pragma unroll
            for (int j = 0; j < 8; j++)
                { c[i][j][0]=0.f; c[i][j][1]=0.f; c[i][j][2]=0.f; c[i][j][3]=0.f; }
        mma_tile_h(sb, 0, bOff, 2, mr0, n0, lane, c);

        float part[4] = {0.f, 0.f, 0.f, 0.f};
        #pragma unroll
        for (int mi = 0; mi < 2; mi++) {
            int r0 = mr0 + mi * 16 + g;
            float bk0 = qkv_b[128 + r0], bk1 = qkv_b[128 + r0 + 8];
            #pragma unroll
            for (int ni = 0; ni < 8; ni++) {
                part[mi*2]   += (c[mi][ni][0] + bk0) * qreg[mi][ni][0]
                              + (c[mi][ni][1] + bk0) * qreg[mi][ni][1];
                part[mi*2+1] += (c[mi][ni][2] + bk1) * qreg[mi][ni][2]
                              + (c[mi][ni][3] + bk1) * qreg[mi][ni][3];
            }
        }
        #pragma unroll
        for (int e = 0; e < 4; e++) {
            part[e] += __shfl_xor_sync(0xffffffffu, part[e], 1);
            part[e] += __shfl_xor_sync(0xffffffffu, part[e], 2);
        }
        if (tg == 0) {
            red[w * 32 + 0 * 16 + g]     = part[0];
            red[w * 32 + 0 * 16 + g + 8] = part[1];
            red[w * 32 + 1 * 16 + g]     = part[2];
            red[w * 32 + 1 * 16 + g + 8] = part[3];
        }
        __syncthreads();
        if (tid < 128) {
            int cch = tid, wa = cch >> 5, loc = cch & 31;
            sc_Spart[((b * 5 + p) * NT_L + nt) * 128 + cch] =
                red[wa * 32 + loc] + red[(wa + 4) * 32 + loc];
        }
        if (p + 2 <= 4) {
            for (int ch = 0; ch < 2; ch++)
                copy_chunk_h_async(sb, bOff + ch * 16384,
                                   sc_TBh + (unsigned)((b * 5 + p + 2) * LL + l0) * 128 + ch * 64, 128, tid);
            CPA_COMMIT();
        }
    }
}

// ---------------- softmax over 5 tokens ----------------
__global__ void softmax_kernel() {
    int b = blockIdx.x, cc = threadIdx.x;
    float S[5];
    const float scale = 0.08838834764831845f;
    #pragma unroll
    for (int p = 0; p < 5; p++) {
        float s = 0.f;
        const float* sp = sc_Spart + ((b * 5 + p) * NT_L) * 128 + cc;
        for (int blk = 0; blk < NT_L; blk++) s += sp[blk * 128];
        S[p] = s * scale;
    }
    float m = -1e30f;
    #pragma unroll
    for (int p = 0; p < 5; p++) m = fmaxf(m, S[p]);
    float e[5], sum = 0.f;
    #pragma unroll
    for (int p = 0; p < 5; p++) { e[p] = expf(S[p] - m); sum += e[p]; }
    float inv = 1.f / sum;
    #pragma unroll
    for (int p = 0; p < 5; p++) sc_attn[(b * 5 + p) * 128 + cc] = e[p] * inv;
}

// ---------------- effective folded weight (hi only, R13) ----------------
__global__ void feff_kernel(const float* __restrict__ proj_w, const float* __restrict__ qkv_w) {
    int idx = blockIdx.x * 256 + threadIdx.x;
    int j = idx % 640;
    int o = (idx / 640) % CO;
    int b = idx / (640 * CO);
    int pp = j >> 7, cpx = j & 127;
    float acc = 0.f;
    for (int cc = 0; cc < CO; cc++)
        acc += proj_w[o * CO + cc] * sc_attn[(b * 5 + pp) * 128 + cc] * qkv_w[(256 + cc) * CO + cpx];
    sc_fAh[idx] = __float2half_rn(acc);
}

// ---------------- final GEMM: out = Feff_b @ T_b + beff (1-term hi, double-buffered) ----------------
// smem: buf{0,1} x (A hi 16KB | B hi 16KB) = 65536 -> 3 blocks/SM
__global__ void __launch_bounds__(256) gemm_fin(float* __restrict__ out) {
    extern __shared__ __align__(16) char smem[];
    int tid = threadIdx.x, lane = tid & 31, w = tid >> 5;
    int nt = blockIdx.x, b = blockIdx.z;
    int l0 = nt * 128;
    uint32_t sb = smem_u32(smem);
    int mr0 = (w & 3) * 32, n0 = (w >> 2) * 64;

    const __half* Ah = sc_fAh + (unsigned)b * 128 * 640;

    auto issue = [&](int kc, int buf) {
        int plane = kc >> 1, half = kc & 1;
        uint32_t base = (uint32_t)buf * 32768;
        copy_chunk_h_async(sb, base, Ah + kc * 64, 640, tid);
        copy_chunk_h_async(sb, base + 16384,
                           sc_TBh + (unsigned)((b * 5 + plane) * LL + l0) * 128 + half * 64, 128, tid);
        CPA_COMMIT();
    };
    issue(0, 0);
    issue(1, 1);

    float c[2][8][4];
    #pragma unroll
    for (int i = 0; i < 2; i++)
        #pragma unroll
        for (int j = 0; j < 8; j++)
            { c[i][j][0]=0.f; c[i][j][1]=0.f; c[i][j][2]=0.f; c[i][j][3]=0.f; }

    for (int kc = 0; kc < 10; kc++) {
        int buf = kc & 1;
        // kc==9: its group is the only pending one -> wait_group 0 (R12 race fix)
        if (kc == 9) CPA_WAIT0(); else CPA_WAIT1();
        __syncthreads();
        mma_tile_h(sb, (uint32_t)buf * 32768, (uint32_t)buf * 32768 + 16384, 1, mr0, n0, lane, c);
        __syncthreads();
        if (kc + 2 < 10) issue(kc + 2, buf);
    }
    int g = lane >> 2, tg = lane & 3;
    #pragma unroll
    for (int mi = 0; mi < 2; mi++) {
        int r0 = mr0 + mi * 16 + g;
        float bv0 = sc_beff[r0], bv1 = sc_beff[r0 + 8];
        #pragma unroll
        for (int ni = 0; ni < 8; ni++) {
            int col = n0 + ni * 8 + tg * 2;
            float2 v0 = make_float2(c[mi][ni][0] + bv0, c[mi][ni][1] + bv0);
            float2 v1 = make_float2(c[mi][ni][2] + bv1, c[mi][ni][3] + bv1);
            *(float2*)(out + (unsigned)(b * CO + r0) * LL + l0 + col) = v0;
            *(float2*)(out + (unsigned)(b * CO + r0 + 8) * LL + l0 + col) = v1;
        }
    }
}

// ---------------- launch ----------------
extern "C" void kernel_launch(void* const* d_in, const int* in_sizes, int n_in,
                              void* d_out, int out_size) {
    const float* x      = (const float*)d_in[0];
    const float* dww[4] = {(const float*)d_in[1], (const float*)d_in[3],
                           (const float*)d_in[5], (const float*)d_in[7]};
    const float* dwb[4] = {(const float*)d_in[2], (const float*)d_in[4],
                           (const float*)d_in[6], (const float*)d_in[8]};
    const float* csc_w  = (const float*)d_in[9];
    const float* csc_b  = (const float*)d_in[10];
    const float* bn_g   = (const float*)d_in[11];
    const float* bn_b   = (const float*)d_in[12];
    const float* bn_m   = (const float*)d_in[13];
    const float* bn_v   = (const float*)d_in[14];
    const float* ggm_w  = (const float*)d_in[15];
    const float* ggm_b  = (const float*)d_in[16];
    const float* qkv_w  = (const float*)d_in[17];
    const float* qkv_b  = (const float*)d_in[18];
    const float* proj_w = (const float*)d_in[19];
    const float* proj_b = (const float*)d_in[20];
    float* out = (float*)d_out;

    __half *p_cAh, *p_cAl, *p_qA, *p_kA;
    cudaGetSymbolAddress((void**)&p_cAh, sc_cAh);
    cudaGetSymbolAddress((void**)&p_cAl, sc_cAl);
    cudaGetSymbolAddress((void**)&p_qA,  sc_qA);
    cudaGetSymbolAddress((void**)&p_kA,  sc_kA);

    cudaFuncSetAttribute(gemm_csc, cudaFuncAttributeMaxDynamicSharedMemorySize, 49152);
    cudaFuncSetAttribute(buildT0_kernel, cudaFuncAttributeMaxDynamicSharedMemorySize, 35840);
    cudaFuncSetAttribute(score_kernel, cudaFuncAttributeMaxDynamicSharedMemorySize, 99328);
    cudaFuncSetAttribute(gemm_fin, cudaFuncAttributeMaxDynamicSharedMemorySize, 65536);

    precompute_kernel<<<1, 128>>>(bn_g, bn_b, bn_m, bn_v, proj_w, qkv_b, proj_b);

    dim3 gdw(14, 16, BB);
    dw_kernel<3><<<gdw, 224>>>(x, dww[0], dwb[0], 0);
    dw_kernel<5><<<gdw, 224>>>(x, dww[1], dwb[1], 1);
    dw_kernel<7><<<gdw, 224>>>(x, dww[2], dwb[2], 2);
    dw_kernel<9><<<gdw, 224>>>(x, dww[3], dwb[3], 3);

    packW_pair<<<(128*64 + 255)/256, 256>>>(csc_w, 128*64, p_cAh, p_cAl);
    packW_hi<<<(128*128 + 255)/256, 256>>>(qkv_w, 128*128, p_qA);
    packW_hi<<<(128*128 + 255)/256, 256>>>(qkv_w + 128*128, 128*128, p_kA);

    gemm_csc<<<dim3(NT_S, 1, BB), 256, 49152>>>(csc_b);

    actggm_kernel<<<dim3(49, CO, BB), 256>>>(ggm_w, ggm_b);

    buildT0_kernel<<<dim3(NT_L, BB), 256, 35840>>>();

    score_kernel<<<dim3(NT_L, 1, BB), 256, 99328>>>(qkv_b);

    softmax_kernel<<<BB, 128>>>();

    feff_kernel<<<(BB * CO * 640) / 256, 256>>>(proj_w, qkv_w);

    gemm_fin<<<dim3(NT_L, 1, BB), 256, 65536>>>(out);
}

// round 15
// speedup vs baseline: 3.5253x; 1.0543x over previous
#include <cuda_runtime.h>
#include <cuda_fp16.h>
#include <stdint.h>
#include <math.h>

#define BB  8
#define CIN 64
#define CO  128
#define HH  224
#define WW  224
#define HO  112
#define WO  112
#define LL  (HO*WO)     // 12544
#define HWD (HH*WW)     // 50176
#define NT_S (HWD/128)  // 392
#define NT_L (LL/128)   // 98

// ---------------- static device scratch ----------------
__device__ __align__(16) __half sc_sh[(size_t)BB*CIN*HWD];   // dw output fp16 [b][c][hw]
__device__ __align__(16) __half sc_y[(size_t)BB*CO*HWD];     // csc output fp16 (guide path)
__device__ __align__(16) __half sc_g[(size_t)BB*CO*LL];      // guide tokens fp16 [b][c][l]
__device__ __align__(16) float sc_Spart[BB*5*NT_L*128];
__device__ float sc_attn[BB*5*128];
__device__ float sc_beff[CO], sc_bnscale[CO], sc_bnshift[CO];
// token planes [b][p][l][c], fp16 HI ONLY
__device__ __align__(16) __half sc_TBh[(size_t)BB*5*LL*128];
__device__ __align__(16) __half sc_cAh[128*64],  sc_cAl[128*64];
__device__ __align__(16) __half sc_qA[128*128];   // Wq hi only
__device__ __align__(16) __half sc_kA[128*128];   // Wk hi only
__device__ __align__(16) __half sc_fAh[(size_t)BB*128*640];   // Feff hi only

#define TSTR 136   // staging row stride (u16): 272B = 17*16, int4-aligned

// ---------------- helpers ----------------
__device__ __forceinline__ uint32_t smem_u32(const void* p) {
    uint32_t a;
    asm("{ .reg .u64 t; cvta.to.shared.u64 t, %1; cvt.u32.u64 %0, t; }" : "=r"(a) : "l"(p));
    return a;
}
__device__ __forceinline__ void split_h(float v, __half& h, __half& l) {
    h = __float2half_rn(v);
    l = __float2half_rn(v - __half2float(h));
}

#define LDSM4(r, a)                                                           \
    asm volatile("ldmatrix.sync.aligned.m8n8.x4.shared.b16 {%0,%1,%2,%3}, [%4];" \
        : "=r"((r)[0]), "=r"((r)[1]), "=r"((r)[2]), "=r"((r)[3]) : "r"(a))

__device__ __forceinline__ void mma16816(float* c, const uint32_t* a, uint32_t b0, uint32_t b1) {
    asm volatile(
        "mma.sync.aligned.m16n8k16.row.col.f32.f16.f16.f32 "
        "{%0,%1,%2,%3}, {%4,%5,%6,%7}, {%8,%9}, {%0,%1,%2,%3};"
        : "+f"(c[0]), "+f"(c[1]), "+f"(c[2]), "+f"(c[3])
        : "r"(a[0]), "r"(a[1]), "r"(a[2]), "r"(a[3]), "r"(b0), "r"(b1));
}

__device__ __forceinline__ void cpa16(uint32_t saddr, const void* g) {
    asm volatile("cp.async.cg.shared.global [%0], [%1], 16;" :: "r"(saddr), "l"(g));
}
#define CPA_COMMIT() asm volatile("cp.async.commit_group;" ::: "memory")
#define CPA_WAIT1()  asm volatile("cp.async.wait_group 1;" ::: "memory")
#define CPA_WAIT0()  asm volatile("cp.async.wait_group 0;" ::: "memory")

// pair chunk: hi at off, lo at off+16384 (32KB)
__device__ __forceinline__ void copy_chunk_async(uint32_t sb, uint32_t off,
                                                 const __half* gh, const __half* gl,
                                                 int ld, int tid) {
    for (int i = tid; i < 1024; i += 256) {
        int r = i >> 3, cc = i & 7;
        uint32_t d = (uint32_t)(r * 128 + ((cc ^ (r & 7)) << 4));
        cpa16(sb + off + d,         gh + r * ld + cc * 8);
        cpa16(sb + off + 16384 + d, gl + r * ld + cc * 8);
    }
}
// hi-only chunk (16KB)
__device__ __forceinline__ void copy_chunk_h(char* smem, uint32_t off,
                                             const __half* gh, int ld, int tid) {
    for (int i = tid; i < 1024; i += 256) {
        int r = i >> 3, cc = i & 7;
        uint32_t d = (uint32_t)(r * 128 + ((cc ^ (r & 7)) << 4));
        *(int4*)(smem + off + d) = *(const int4*)(gh + r * ld + cc * 8);
    }
}
__device__ __forceinline__ void copy_chunk_h_async(uint32_t sb, uint32_t off,
                                                   const __half* gh, int ld, int tid) {
    for (int i = tid; i < 1024; i += 256) {
        int r = i >> 3, cc = i & 7;
        uint32_t d = (uint32_t)(r * 128 + ((cc ^ (r & 7)) << 4));
        cpa16(sb + off + d, gh + r * ld + cc * 8);
    }
}

// 1-term hi-only gemm, nch 16KB chunks (score + fin paths)
__device__ __forceinline__ void mma_tile_h(uint32_t sb, uint32_t aOff, uint32_t bOff, int nch,
                                           int mr0, int n0, int lane, float c[2][8][4]) {
    int ar = lane & 15, ac = lane >> 4;
    int br = (lane & 7) + ((lane >> 4) << 3), bc = (lane >> 3) & 1;
    for (int ch = 0; ch < nch; ch++) {
        #pragma unroll
        for (int kk = 0; kk < 4; kk++) {
            uint32_t aH[2][4], bH[4][4];
            #pragma unroll
            for (int mi = 0; mi < 2; mi++) {
                int r = mr0 + mi * 16 + ar;
                uint32_t addr = sb + aOff + ch * 16384 + r * 128 + (((kk * 2 + ac) ^ (r & 7)) << 4);
                LDSM4(aH[mi], addr);
            }
            #pragma unroll
            for (int np = 0; np < 4; np++) {
                int r = n0 + np * 16 + br;
                uint32_t addr = sb + bOff + ch * 16384 + r * 128 + (((kk * 2 + bc) ^ (r & 7)) << 4);
                LDSM4(bH[np], addr);
            }
            #pragma unroll
            for (int mi = 0; mi < 2; mi++)
                #pragma unroll
                for (int np = 0; np < 4; np++) {
                    mma16816(c[mi][np*2],     aH[mi], bH[np][0], bH[np][1]);
                    mma16816(c[mi][np*2 + 1], aH[mi], bH[np][2], bH[np][3]);
                }
        }
    }
}

// 2-term gemm: A pair (hi at aOff, lo at +16384), B hi-only at bOff (csc path)
__device__ __forceinline__ void mma_tile_fin(uint32_t sb, uint32_t aOff, uint32_t bOff,
                                             int mr0, int n0, int lane, float c[2][8][4]) {
    int ar = lane & 15, ac = lane >> 4;
    int br = (lane & 7) + ((lane >> 4) << 3), bc = (lane >> 3) & 1;
    #pragma unroll
    for (int kk = 0; kk < 4; kk++) {
        uint32_t aH[2][4], aL[2][4], bH[4][4];
        #pragma unroll
        for (int mi = 0; mi < 2; mi++) {
            int r = mr0 + mi * 16 + ar;
            uint32_t addr = sb + aOff + r * 128 + (((kk * 2 + ac) ^ (r & 7)) << 4);
            LDSM4(aH[mi], addr);
            LDSM4(aL[mi], addr + 16384);
        }
        #pragma unroll
        for (int np = 0; np < 4; np++) {
            int r = n0 + np * 16 + br;
            uint32_t addr = sb + bOff + r * 128 + (((kk * 2 + bc) ^ (r & 7)) << 4);
            LDSM4(bH[np], addr);
        }
        #pragma unroll
        for (int mi = 0; mi < 2; mi++)
            #pragma unroll
            for (int np = 0; np < 4; np++) {
                mma16816(c[mi][np*2],     aH[mi], bH[np][0], bH[np][1]);
                mma16816(c[mi][np*2],     aL[mi], bH[np][0], bH[np][1]);
                mma16816(c[mi][np*2 + 1], aH[mi], bH[np][2], bH[np][3]);
                mma16816(c[mi][np*2 + 1], aL[mi], bH[np][2], bH[np][3]);
            }
    }
}

// ---------------- depthwise conv body: 2x8 outputs/thread, fp16 out ----------------
template<int KSZ>
__device__ __forceinline__ void dw_body(const float* __restrict__ x,
                                        const float* __restrict__ w,
                                        const float* __restrict__ bias,
                                        int head, int b, float* wks) {
    const int pad = KSZ / 2;
    int tid = threadIdx.x;
    int j = blockIdx.y;
    if (tid < KSZ * KSZ) wks[tid] = w[j * KSZ * KSZ + tid];
    __syncthreads();
    int q = blockIdx.x * 224 + tid;
    int h2 = q / 28, wg = q % 28;
    int h0 = 2 * h2;
    int w0 = wg * 8;
    const float* xin = x + (unsigned)(b * CIN + head * 16 + j) * HWD;
    float bv = bias[j];
    float a0[8], a1[8];
    #pragma unroll
    for (int o = 0; o < 8; o++) { a0[o] = bv; a1[o] = bv; }
    const float4 z4 = make_float4(0.f, 0.f, 0.f, 0.f);
    #pragma unroll
    for (int t = 0; t <= KSZ; t++) {
        int ih = h0 - pad + t;
        if (ih < 0 || ih >= HH) continue;
        const float4* row = (const float4*)(xin + (unsigned)ih * WW);
        int i0 = wg * 2 - 1;
        float4 v0 = (i0 >= 0) ? row[i0] : z4;
        float4 v1 = row[i0 + 1];
        float4 v2 = row[i0 + 2];
        float4 v3 = (i0 + 3 < 56) ? row[i0 + 3] : z4;
        float win[16];
        win[0]=v0.x; win[1]=v0.y; win[2]=v0.z; win[3]=v0.w;
        win[4]=v1.x; win[5]=v1.y; win[6]=v1.z; win[7]=v1.w;
        win[8]=v2.x; win[9]=v2.y; win[10]=v2.z; win[11]=v2.w;
        win[12]=v3.x; win[13]=v3.y; win[14]=v3.z; win[15]=v3.w;
        if (t < KSZ) {
            #pragma unroll
            for (int kx = 0; kx < KSZ; kx++) {
                float wv = wks[t * KSZ + kx];
                #pragma unroll
                for (int o = 0; o < 8; o++)
                    a0[o] += win[o + kx + 4 - pad] * wv;
            }
        }
        if (t >= 1) {
            #pragma unroll
            for (int kx = 0; kx < KSZ; kx++) {
                float wv = wks[(t - 1) * KSZ + kx];
                #pragma unroll
                for (int o = 0; o < 8; o++)
                    a1[o] += win[o + kx + 4 - pad] * wv;
            }
        }
    }
    __half* dst = sc_sh + (unsigned)(b * CIN + j * 4 + head) * HWD + (unsigned)h0 * WW + w0;
    __half hb[8];
    #pragma unroll
    for (int o = 0; o < 8; o++) hb[o] = __float2half_rn(a0[o]);
    *(int4*)dst = *(int4*)hb;
    #pragma unroll
    for (int o = 0; o < 8; o++) hb[o] = __float2half_rn(a1[o]);
    *(int4*)(dst + WW) = *(int4*)hb;
}

// merged dw kernel: grid (14, 16, BB*4); z = b*4 + head. All heads co-resident.
__global__ void __launch_bounds__(224) dw_all_kernel(
    const float* __restrict__ x,
    const float* __restrict__ w3, const float* __restrict__ b3,
    const float* __restrict__ w5, const float* __restrict__ b5,
    const float* __restrict__ w7, const float* __restrict__ b7,
    const float* __restrict__ w9, const float* __restrict__ b9) {
    __shared__ float wks[81];
    int z = blockIdx.z;
    int head = z & 3, b = z >> 2;
    switch (head) {
        case 0: dw_body<3>(x, w3, b3, 0, b, wks); break;
        case 1: dw_body<5>(x, w5, b5, 1, b, wks); break;
        case 2: dw_body<7>(x, w7, b7, 2, b, wks); break;
        default: dw_body<9>(x, w9, b9, 3, b, wks); break;
    }
}

// ---------------- precompute ----------------
__global__ void precompute_kernel(const float* g, const float* be, const float* mn,
                                  const float* vr, const float* proj_w,
                                  const float* qkv_b, const float* proj_b) {
    int c = threadIdx.x;
    float sc = g[c] * rsqrtf(vr[c] + 1e-5f);
    sc_bnscale[c] = sc;
    sc_bnshift[c] = be[c] - mn[c] * sc;
    float acc = proj_b[c];
    for (int k = 0; k < CO; k++) acc += proj_w[c * CO + k] * qkv_b[256 + k];
    sc_beff[c] = acc;
}

// ---------------- pack all weights in one launch ----------------
__global__ void packAll_kernel(const float* __restrict__ csc_w,
                               const float* __restrict__ qkv_w) {
    int i = blockIdx.x * 256 + threadIdx.x;
    if (i < 8192) {                       // csc pair
        __half h, l; split_h(csc_w[i], h, l);
        sc_cAh[i] = h; sc_cAl[i] = l;
    } else if (i < 8192 + 16384) {        // Wq hi
        int k = i - 8192;
        sc_qA[k] = __float2half_rn(qkv_w[k]);
    } else if (i < 8192 + 32768) {        // Wk hi
        int k = i - 8192 - 16384;
        sc_kA[k] = __float2half_rn(qkv_w[16384 + k]);
    }
}

// ---------------- csc GEMM: A pair (async) x B(s fp16, exact) 2-term + TB-hi epilogue ----------------
__global__ void __launch_bounds__(256) gemm_csc(const float* __restrict__ bias) {
    extern __shared__ __align__(16) char smem[];
    int tid = threadIdx.x, lane = tid & 31, w = tid >> 5;
    int nt = blockIdx.x, b = blockIdx.z;
    int hw0 = nt * 128;
    uint32_t sb = smem_u32(smem);
    int mr0 = (w & 3) * 32, n0 = (w >> 2) * 64;

    copy_chunk_async(sb, 0, sc_cAh, sc_cAl, 64, tid);
    CPA_COMMIT();
    {
        int r = tid & 31;
        int seg = tid >> 5;
        int c0 = 2 * r;
        int cc = c0 >> 3, cbw = (c0 & 7) * 2;
        const __half* src0 = sc_sh + (unsigned)(b * CIN + c0) * HWD + hw0 + seg * 16;
        const __half* src1 = src0 + HWD;
        union { int4 v; uint16_t u[8]; } A0, A1, B0, B1;
        A0.v = *(const int4*)src0; A1.v = *(const int4*)(src0 + 8);
        B0.v = *(const int4*)src1; B1.v = *(const int4*)(src1 + 8);
        #pragma unroll
        for (int jj = 0; jj < 16; jj++) {
            int hwl = seg * 16 + jj;
            uint16_t va = (jj < 8) ? A0.u[jj] : A1.u[jj - 8];
            uint16_t vb = (jj < 8) ? B0.u[jj] : B1.u[jj - 8];
            uint32_t off = (uint32_t)(hwl * 128 + ((cc ^ (hwl & 7)) << 4) + cbw);
            *(uint32_t*)(smem + 32768 + off) = (uint32_t)va | ((uint32_t)vb << 16);
        }
    }
    CPA_WAIT0();
    __syncthreads();

    float c[2][8][4];
    #pragma unroll
    for (int i = 0; i < 2; i++)
        #pragma unroll
        for (int j = 0; j < 8; j++)
            { c[i][j][0]=0.f; c[i][j][1]=0.f; c[i][j][2]=0.f; c[i][j][3]=0.f; }
    mma_tile_fin(sb, 0, 32768, mr0, n0, lane, c);

    int g = lane >> 2, tg = lane & 3;
    // epilogue (a): y fp16
    #pragma unroll
    for (int mi = 0; mi < 2; mi++) {
        int r0 = mr0 + mi * 16 + g;
        float bv0 = bias[r0], bv1 = bias[r0 + 8];
        #pragma unroll
        for (int ni = 0; ni < 8; ni++) {
            int col = n0 + ni * 8 + tg * 2;
            __half2 v0 = __floats2half2_rn(c[mi][ni][0] + bv0, c[mi][ni][1] + bv0);
            __half2 v1 = __floats2half2_rn(c[mi][ni][2] + bv1, c[mi][ni][3] + bv1);
            *(__half2*)(sc_y + (unsigned)(b * CO + r0) * HWD + hw0 + col) = v0;
            *(__half2*)(sc_y + (unsigned)(b * CO + r0 + 8) * HWD + hw0 + col) = v1;
        }
    }
    __syncthreads();
    // epilogue (b): stage hi-only transposed [hw][128c], stride TSTR u16
    {
        uint16_t* sh = (uint16_t*)smem;
        #pragma unroll
        for (int mi = 0; mi < 2; mi++) {
            int r0 = mr0 + mi * 16 + g;
            float bv0 = bias[r0], bv1 = bias[r0 + 8];
            #pragma unroll
            for (int ni = 0; ni < 8; ni++) {
                int col = n0 + ni * 8 + tg * 2;
                float vals[4] = {c[mi][ni][0] + bv0, c[mi][ni][1] + bv0,
                                 c[mi][ni][2] + bv1, c[mi][ni][3] + bv1};
                int rows[4] = {r0, r0, r0 + 8, r0 + 8};
                int cols[4] = {col, col + 1, col, col + 1};
                #pragma unroll
                for (int e = 0; e < 4; e++)
                    sh[cols[e] * TSTR + rows[e]] = __half_as_ushort(__float2half_rn(vals[e]));
            }
        }
    }
    __syncthreads();
    // write out to TB planes 1..4 (hi only)
    {
        int qq = tid & 1, hb = tid >> 1;
        int hw = hw0 + hb;
        int h = hw / WW, wv = hw % WW;
        int p = 1 + ((h & 1) << 1) + (wv & 1);
        int l = (h >> 1) * WO + (wv >> 1);
        int4* dst = (int4*)(sc_TBh + (unsigned)((b * 5 + p) * LL + l) * 128 + qq * 64);
        const int4* src = (const int4*)((char*)smem + hb * (TSTR * 2) + qq * 128);
        #pragma unroll
        for (int jj = 0; jj < 8; jj++) dst[jj] = src[jj];
    }
}

// ---------------- fused BN + GELU + dwconv7 stride2 (fp16 y in, fp16 g out) ----------------
__global__ void __launch_bounds__(256) actggm_kernel(const float* __restrict__ w,
                                                     const float* __restrict__ bias) {
    __shared__ float a[38 * 38];
    __shared__ float wk[49];
    int t = blockIdx.x, c = blockIdx.y, b = blockIdx.z;
    int ty = t / 7, tx = t % 7;
    int ho0 = ty * 16, wo0 = tx * 16;
    if (threadIdx.x < 49) wk[threadIdx.x] = w[c * 49 + threadIdx.x];
    const __half* y = sc_y + (unsigned)(b * CO + c) * HWD;
    float bs = sc_bnscale[c], bh = sc_bnshift[c];
    for (int ii = threadIdx.x; ii < 38 * 38; ii += 256) {
        int r = ii / 38, col = ii % 38;
        int ih = 2 * ho0 - 3 + r, iw = 2 * wo0 - 3 + col;
        float v = 0.f;
        if (ih >= 0 && ih < HH && iw >= 0 && iw < WW) {
            v = __half2float(y[(unsigned)ih * WW + iw]) * bs + bh;
            v = 0.5f * v * (1.f + erff(v * 0.7071067811865476f));
        }
        a[ii] = v;
    }
    __syncthreads();
    int oy = threadIdx.x / 16, ox = threadIdx.x % 16;
    float acc = bias[c];
    #pragma unroll
    for (int i = 0; i < 7; i++)
        #pragma unroll
        for (int j = 0; j < 7; j++)
            acc += a[(2 * oy + i) * 38 + (2 * ox + j)] * wk[i * 7 + j];
    sc_g[(unsigned)(b * CO + c) * LL + (unsigned)(ho0 + oy) * WO + wo0 + ox] = __float2half_rn(acc);
}

// ---------------- g (fp16) -> TB plane 0 (hi only) ----------------
__global__ void __launch_bounds__(256) buildT0_kernel() {
    extern __shared__ __align__(16) char smem[];
    int lt = blockIdx.x, b = blockIdx.y;
    int tid = threadIdx.x;
    uint16_t* sh = (uint16_t*)smem;
    {
        int c = tid >> 1, seg = tid & 1;
        const __half* gsrc = sc_g + (unsigned)(b * CO + c) * LL + lt * 128 + seg * 64;
        #pragma unroll 8
        for (int j = 0; j < 64; j++) {
            int l = seg * 64 + j;
            sh[l * TSTR + c] = __half_as_ushort(gsrc[j]);
        }
    }
    __syncthreads();
    int qq = tid & 1, hb2 = tid >> 1;
    int l = lt * 128 + hb2;
    int4* dst = (int4*)(sc_TBh + (unsigned)((b * 5 + 0) * LL + l) * 128 + qq * 64);
    const int4* src = (const int4*)((char*)smem + hb2 * (TSTR * 2) + qq * 128);
    #pragma unroll
    for (int jj = 0; jj < 8; jj++) dst[jj] = src[jj];
}

// ---------------- fused score kernel (hi-only, q0 in regs, double-buffered) ----------------
// smem: W 0..32K, B buf0 32K..64K, buf1 64K..96K, red at 98304. total 99328.
__global__ void __launch_bounds__(256) score_kernel(const float* __restrict__ qkv_b) {
    extern __shared__ __align__(16) char smem[];
    int tid = threadIdx.x, lane = tid & 31, w = tid >> 5;
    int nt = blockIdx.x, b = blockIdx.z;
    int l0 = nt * 128;
    uint32_t sb = smem_u32(smem);
    int mr0 = (w & 3) * 32, n0 = (w >> 2) * 64;
    int g = lane >> 2, tg = lane & 3;
    float* red = (float*)(smem + 98304);

    // Wq async FIRST (G1), then P0 (G2), P1 (G3) — all overlap
    for (int ch = 0; ch < 2; ch++)
        copy_chunk_h_async(sb, ch * 16384, sc_qA + ch * 64, 128, tid);
    CPA_COMMIT();
    for (int ch = 0; ch < 2; ch++)
        copy_chunk_h_async(sb, 32768 + ch * 16384,
                           sc_TBh + (unsigned)((b * 5 + 0) * LL + l0) * 128 + ch * 64, 128, tid);
    CPA_COMMIT();
    for (int ch = 0; ch < 2; ch++)
        copy_chunk_h_async(sb, 65536 + ch * 16384,
                           sc_TBh + (unsigned)((b * 5 + 1) * LL + l0) * 128 + ch * 64, 128, tid);
    CPA_COMMIT();
    CPA_WAIT1();         // G1 (Wq) + G2 (P0) complete; G3 (P1) may be pending
    __syncthreads();

    float c[2][8][4];
    #pragma unroll
    for (int i = 0; i < 2; i++)
        #pragma unroll
        for (int j = 0; j < 8; j++)
            { c[i][j][0]=0.f; c[i][j][1]=0.f; c[i][j][2]=0.f; c[i][j][3]=0.f; }
    mma_tile_h(sb, 0, 32768, 2, mr0, n0, lane, c);

    float qreg[2][8][4];
    #pragma unroll
    for (int mi = 0; mi < 2; mi++) {
        int r0 = mr0 + mi * 16 + g;
        float bq0 = qkv_b[r0], bq1 = qkv_b[r0 + 8];
        #pragma unroll
        for (int ni = 0; ni < 8; ni++) {
            qreg[mi][ni][0] = c[mi][ni][0] + bq0;
            qreg[mi][ni][1] = c[mi][ni][1] + bq0;
            qreg[mi][ni][2] = c[mi][ni][2] + bq1;
            qreg[mi][ni][3] = c[mi][ni][3] + bq1;
        }
    }
    __syncthreads();
    for (int ch = 0; ch < 2; ch++)
        copy_chunk_h(smem, ch * 16384, sc_kA + ch * 64, 128, tid);
    __syncthreads();

    for (int p = 0; p < 5; p++) {
        int buf = p & 1;
        uint32_t bOff = 32768 + (uint32_t)buf * 32768;
        if (p >= 1) {
            // p==4: its group is the ONLY pending one -> must wait_group 0 (R12 race fix)
            if (p == 4) CPA_WAIT0(); else CPA_WAIT1();
            __syncthreads();
        }
        #pragma unroll
        for (int i = 0; i < 2; i++)
            #pragma unroll
            for (int j = 0; j < 8; j++)
                { c[i][j][0]=0.f; c[i][j][1]=0.f; c[i][j][2]=0.f; c[i][j][3]=0.f; }
        mma_tile_h(sb, 0, bOff, 2, mr0, n0, lane, c);

        float part[4] = {0.f, 0.f, 0.f, 0.f};
        #pragma unroll
        for (int mi = 0; mi < 2; mi++) {
            int r0 = mr0 + mi * 16 + g;
            float bk0 = qkv_b[128 + r0], bk1 = qkv_b[128 + r0 + 8];
            #pragma unroll
            for (int ni = 0; ni < 8; ni++) {
                part[mi*2]   += (c[mi][ni][0] + bk0) * qreg[mi][ni][0]
                              + (c[mi][ni][1] + bk0) * qreg[mi][ni][1];
                part[mi*2+1] += (c[mi][ni][2] + bk1) * qreg[mi][ni][2]
                              + (c[mi][ni][3] + bk1) * qreg[mi][ni][3];
            }
        }
        #pragma unroll
        for (int e = 0; e < 4; e++) {
            part[e] += __shfl_xor_sync(0xffffffffu, part[e], 1);
            part[e] += __shfl_xor_sync(0xffffffffu, part[e], 2);
        }
        if (tg == 0) {
            red[w * 32 + 0 * 16 + g]     = part[0];
            red[w * 32 + 0 * 16 + g + 8] = part[1];
            red[w * 32 + 1 * 16 + g]     = part[2];
            red[w * 32 + 1 * 16 + g + 8] = part[3];
        }
        __syncthreads();
        if (tid < 128) {
            int cch = tid, wa = cch >> 5, loc = cch & 31;
            sc_Spart[((b * 5 + p) * NT_L + nt) * 128 + cch] =
                red[wa * 32 + loc] + red[(wa + 4) * 32 + loc];
        }
        if (p + 2 <= 4) {
            for (int ch = 0; ch < 2; ch++)
                copy_chunk_h_async(sb, bOff + ch * 16384,
                                   sc_TBh + (unsigned)((b * 5 + p + 2) * LL + l0) * 128 + ch * 64, 128, tid);
            CPA_COMMIT();
        }
    }
}

// ---------------- softmax over 5 tokens ----------------
__global__ void softmax_kernel() {
    int b = blockIdx.x, cc = threadIdx.x;
    float S[5];
    const float scale = 0.08838834764831845f;
    #pragma unroll
    for (int p = 0; p < 5; p++) {
        float s = 0.f;
        const float* sp = sc_Spart + ((b * 5 + p) * NT_L) * 128 + cc;
        for (int blk = 0; blk < NT_L; blk++) s += sp[blk * 128];
        S[p] = s * scale;
    }
    float m = -1e30f;
    #pragma unroll
    for (int p = 0; p < 5; p++) m = fmaxf(m, S[p]);
    float e[5], sum = 0.f;
    #pragma unroll
    for (int p = 0; p < 5; p++) { e[p] = expf(S[p] - m); sum += e[p]; }
    float inv = 1.f / sum;
    #pragma unroll
    for (int p = 0; p < 5; p++) sc_attn[(b * 5 + p) * 128 + cc] = e[p] * inv;
}

// ---------------- effective folded weight (hi only) ----------------
__global__ void feff_kernel(const float* __restrict__ proj_w, const float* __restrict__ qkv_w) {
    int idx = blockIdx.x * 256 + threadIdx.x;
    int j = idx % 640;
    int o = (idx / 640) % CO;
    int b = idx / (640 * CO);
    int pp = j >> 7, cpx = j & 127;
    float acc = 0.f;
    for (int cc = 0; cc < CO; cc++)
        acc += proj_w[o * CO + cc] * sc_attn[(b * 5 + pp) * 128 + cc] * qkv_w[(256 + cc) * CO + cpx];
    sc_fAh[idx] = __float2half_rn(acc);
}

// ---------------- final GEMM: out = Feff_b @ T_b + beff (1-term hi, double-buffered) ----------------
// smem: buf{0,1} x (A hi 16KB | B hi 16KB) = 65536 -> 3 blocks/SM
__global__ void __launch_bounds__(256) gemm_fin(float* __restrict__ out) {
    extern __shared__ __align__(16) char smem[];
    int tid = threadIdx.x, lane = tid & 31, w = tid >> 5;
    int nt = blockIdx.x, b = blockIdx.z;
    int l0 = nt * 128;
    uint32_t sb = smem_u32(smem);
    int mr0 = (w & 3) * 32, n0 = (w >> 2) * 64;

    const __half* Ah = sc_fAh + (unsigned)b * 128 * 640;

    auto issue = [&](int kc, int buf) {
        int plane = kc >> 1, half = kc & 1;
        uint32_t base = (uint32_t)buf * 32768;
        copy_chunk_h_async(sb, base, Ah + kc * 64, 640, tid);
        copy_chunk_h_async(sb, base + 16384,
                           sc_TBh + (unsigned)((b * 5 + plane) * LL + l0) * 128 + half * 64, 128, tid);
        CPA_COMMIT();
    };
    issue(0, 0);
    issue(1, 1);

    float c[2][8][4];
    #pragma unroll
    for (int i = 0; i < 2; i++)
        #pragma unroll
        for (int j = 0; j < 8; j++)
            { c[i][j][0]=0.f; c[i][j][1]=0.f; c[i][j][2]=0.f; c[i][j][3]=0.f; }

    for (int kc = 0; kc < 10; kc++) {
        int buf = kc & 1;
        // kc==9: its group is the only pending one -> wait_group 0 (R12 race fix)
        if (kc == 9) CPA_WAIT0(); else CPA_WAIT1();
        __syncthreads();
        mma_tile_h(sb, (uint32_t)buf * 32768, (uint32_t)buf * 32768 + 16384, 1, mr0, n0, lane, c);
        __syncthreads();
        if (kc + 2 < 10) issue(kc + 2, buf);
    }
    int g = lane >> 2, tg = lane & 3;
    #pragma unroll
    for (int mi = 0; mi < 2; mi++) {
        int r0 = mr0 + mi * 16 + g;
        float bv0 = sc_beff[r0], bv1 = sc_beff[r0 + 8];
        #pragma unroll
        for (int ni = 0; ni < 8; ni++) {
            int col = n0 + ni * 8 + tg * 2;
            float2 v0 = make_float2(c[mi][ni][0] + bv0, c[mi][ni][1] + bv0);
            float2 v1 = make_float2(c[mi][ni][2] + bv1, c[mi][ni][3] + bv1);
            *(float2*)(out + (unsigned)(b * CO + r0) * LL + l0 + col) = v0;
            *(float2*)(out + (unsigned)(b * CO + r0 + 8) * LL + l0 + col) = v1;
        }
    }
}

// ---------------- launch ----------------
extern "C" void kernel_launch(void* const* d_in, const int* in_sizes, int n_in,
                              void* d_out, int out_size) {
    const float* x      = (const float*)d_in[0];
    const float* dww[4] = {(const float*)d_in[1], (const float*)d_in[3],
                           (const float*)d_in[5], (const float*)d_in[7]};
    const float* dwb[4] = {(const float*)d_in[2], (const float*)d_in[4],
                           (const float*)d_in[6], (const float*)d_in[8]};
    const float* csc_w  = (const float*)d_in[9];
    const float* csc_b  = (const float*)d_in[10];
    const float* bn_g   = (const float*)d_in[11];
    const float* bn_b   = (const float*)d_in[12];
    const float* bn_m   = (const float*)d_in[13];
    const float* bn_v   = (const float*)d_in[14];
    const float* ggm_w  = (const float*)d_in[15];
    const float* ggm_b  = (const float*)d_in[16];
    const float* qkv_w  = (const float*)d_in[17];
    const float* qkv_b  = (const float*)d_in[18];
    const float* proj_w = (const float*)d_in[19];
    const float* proj_b = (const float*)d_in[20];
    float* out = (float*)d_out;

    cudaFuncSetAttribute(gemm_csc, cudaFuncAttributeMaxDynamicSharedMemorySize, 49152);
    cudaFuncSetAttribute(buildT0_kernel, cudaFuncAttributeMaxDynamicSharedMemorySize, 35840);
    cudaFuncSetAttribute(score_kernel, cudaFuncAttributeMaxDynamicSharedMemorySize, 99328);
    cudaFuncSetAttribute(gemm_fin, cudaFuncAttributeMaxDynamicSharedMemorySize, 65536);

    precompute_kernel<<<1, 128>>>(bn_g, bn_b, bn_m, bn_v, proj_w, qkv_b, proj_b);

    packAll_kernel<<<(8192 + 32768 + 255) / 256, 256>>>(csc_w, qkv_w);

    // merged dw: all 4 heads in one launch
    dw_all_kernel<<<dim3(14, 16, BB * 4), 224>>>(
        x, dww[0], dwb[0], dww[1], dwb[1], dww[2], dwb[2], dww[3], dwb[3]);

    gemm_csc<<<dim3(NT_S, 1, BB), 256, 49152>>>(csc_b);

    actggm_kernel<<<dim3(49, CO, BB), 256>>>(ggm_w, ggm_b);

    buildT0_kernel<<<dim3(NT_L, BB), 256, 35840>>>();

    score_kernel<<<dim3(NT_L, 1, BB), 256, 99328>>>(qkv_b);

    softmax_kernel<<<BB, 128>>>();

    feff_kernel<<<(BB * CO * 640) / 256, 256>>>(proj_w, qkv_w);

    gemm_fin<<<dim3(NT_L, 1, BB), 256, 65536>>>(out);
}